// round 2
// baseline (speedup 1.0000x reference)
#include <cuda_runtime.h>
#include <cuda_bf16.h>
#include <math.h>

#define N_NODES 50000
#define N_EDGES 300000
#define N_GRAPHS 2048
#define HID 256

// ---------------- scratch (static __device__, no allocation) ----------------
__device__ int   g_deg[N_NODES];
__device__ float g_dinv[N_NODES];
__device__ int   g_rowptr[N_NODES + 1];
__device__ int   g_cursor[N_NODES];
__device__ int   g_col[N_EDGES];
__device__ float g_w[N_EDGES];
__device__ float g_t[(size_t)N_NODES * HID];     // GEMM output (pre-aggregation)
__device__ float g_h[(size_t)N_NODES * HID];     // post-aggregation activations
__device__ float g_pool[(size_t)N_GRAPHS * HID];
__device__ float g_fc1[(size_t)N_GRAPHS * 128];

// ---------------- small helpers ----------------
__device__ __forceinline__ float4 f4_zero() { return make_float4(0.f, 0.f, 0.f, 0.f); }
__device__ __forceinline__ void f4_fma(float s, const float4& a, float4& acc) {
    acc.x = fmaf(s, a.x, acc.x); acc.y = fmaf(s, a.y, acc.y);
    acc.z = fmaf(s, a.z, acc.z); acc.w = fmaf(s, a.w, acc.w);
}

// ---------------- graph preprocessing ----------------
__global__ void k_init_deg() {
    int i = blockIdx.x * blockDim.x + threadIdx.x;
    if (i < N_NODES) g_deg[i] = 1;   // self loop
}

__global__ void k_count(const int* __restrict__ dst) {
    int e = blockIdx.x * blockDim.x + threadIdx.x;
    if (e < N_EDGES) atomicAdd(&g_deg[dst[e]], 1);
}

__global__ void k_dinv() {
    int i = blockIdx.x * blockDim.x + threadIdx.x;
    if (i < N_NODES) g_dinv[i] = rsqrtf((float)g_deg[i]);
}

// single-block exclusive scan of (deg-1) -> rowptr, cursor
__global__ void k_scan() {
    __shared__ int sdata[1024];
    __shared__ int s_carry;
    if (threadIdx.x == 0) s_carry = 0;
    __syncthreads();
    for (int base = 0; base < N_NODES; base += 1024) {
        int i = base + (int)threadIdx.x;
        int v = (i < N_NODES) ? (g_deg[i] - 1) : 0;
        sdata[threadIdx.x] = v;
        __syncthreads();
        for (int off = 1; off < 1024; off <<= 1) {
            int t = (threadIdx.x >= (unsigned)off) ? sdata[threadIdx.x - off] : 0;
            __syncthreads();
            sdata[threadIdx.x] += t;
            __syncthreads();
        }
        int incl = sdata[threadIdx.x];
        if (i < N_NODES) {
            int excl = s_carry + incl - v;
            g_rowptr[i] = excl;
            g_cursor[i] = excl;
        }
        __syncthreads();
        if (threadIdx.x == 1023) s_carry += sdata[1023];
        __syncthreads();
    }
    if (threadIdx.x == 0) g_rowptr[N_NODES] = s_carry;
}

__global__ void k_fill(const int* __restrict__ src, const int* __restrict__ dst) {
    int e = blockIdx.x * blockDim.x + threadIdx.x;
    if (e < N_EDGES) {
        int s = src[e], d = dst[e];
        int pos = atomicAdd(&g_cursor[d], 1);
        g_col[pos] = s;
        g_w[pos]   = g_dinv[s] * g_dinv[d];
    }
}

// ---------------- fp32 tiled GEMM: C[M,N] = A[M,K] @ B[K,N] (+bias, relu) ----------------
// BM=128, BN=128, BK=16, 256 threads, 8x8 per thread.
template <bool BIAS, bool RELU>
__global__ void __launch_bounds__(256) gemm_kernel(
    const float* __restrict__ A, const float* __restrict__ B,
    const float* __restrict__ bias, float* __restrict__ C,
    int M, int N, int K)
{
    constexpr int BM = 128, BN = 128, BK = 16, TM = 8, TN = 8;
    __shared__ float As[BK][BM];
    __shared__ float Bs[BK][BN];
    const int tid  = threadIdx.x;
    const int trow = tid >> 4;     // 0..15
    const int tcol = tid & 15;     // 0..15
    const int brow = blockIdx.x, bcol = blockIdx.y;

    float acc[TM][TN];
#pragma unroll
    for (int i = 0; i < TM; i++)
#pragma unroll
        for (int j = 0; j < TN; j++) acc[i][j] = 0.f;

    for (int k0 = 0; k0 < K; k0 += BK) {
        // A tile: BM x BK = 512 float4, 2 per thread; store transposed As[k][row]
#pragma unroll
        for (int it = 0; it < 2; it++) {
            int f4 = tid + it * 256;
            int r  = f4 >> 2;             // row in tile (0..127)
            int kc = (f4 & 3) << 2;       // k offset (0,4,8,12)
            int grow = brow * BM + r;
            float4 v = f4_zero();
            if (grow < M) v = *(const float4*)(A + (size_t)grow * K + k0 + kc);
            As[kc + 0][r] = v.x; As[kc + 1][r] = v.y;
            As[kc + 2][r] = v.z; As[kc + 3][r] = v.w;
        }
        // B tile: BK x BN = 512 float4, 2 per thread
#pragma unroll
        for (int it = 0; it < 2; it++) {
            int f4 = tid + it * 256;
            int kr = f4 >> 5;             // 0..15
            int c4 = (f4 & 31) << 2;      // col (0..124 step 4)
            int gcol = bcol * BN + c4;
            float4 v = f4_zero();
            if (gcol < N) v = *(const float4*)(B + (size_t)(k0 + kr) * N + gcol);
            *(float4*)&Bs[kr][c4] = v;
        }
        __syncthreads();

#pragma unroll
        for (int k = 0; k < BK; k++) {
            float ra[TM], rb[TN];
            *(float4*)&ra[0] = *(const float4*)&As[k][trow * TM];
            *(float4*)&ra[4] = *(const float4*)&As[k][trow * TM + 4];
            *(float4*)&rb[0] = *(const float4*)&Bs[k][tcol * TN];
            *(float4*)&rb[4] = *(const float4*)&Bs[k][tcol * TN + 4];
#pragma unroll
            for (int i = 0; i < TM; i++)
#pragma unroll
                for (int j = 0; j < TN; j++)
                    acc[i][j] = fmaf(ra[i], rb[j], acc[i][j]);
        }
        __syncthreads();
    }

#pragma unroll
    for (int i = 0; i < TM; i++) {
        int grow = brow * BM + trow * TM + i;
        if (grow >= M) continue;
#pragma unroll
        for (int j = 0; j < TN; j++) {
            int gcol = bcol * BN + tcol * TN + j;
            if (gcol >= N) continue;
            float v = acc[i][j];
            if (BIAS) v += bias[gcol];
            if (RELU) v = fmaxf(v, 0.f);
            C[(size_t)grow * N + gcol] = v;
        }
    }
}

// ---------------- aggregation: out[i] = relu(b + dinv[i]^2 * t[i] + sum_e w_e * t[col_e]) ----------------
__global__ void __launch_bounds__(256) agg_relu_kernel(
    const float* __restrict__ t, float* __restrict__ out, const float* __restrict__ bias)
{
    int warp = (blockIdx.x * blockDim.x + threadIdx.x) >> 5;
    int lane = threadIdx.x & 31;
    if (warp >= N_NODES) return;
    const int i = warp;

    const float4* rowi = (const float4*)(t + (size_t)i * HID);
    float di = g_dinv[i];
    float ws = di * di;
    float4 acc0 = f4_zero(), acc1 = f4_zero();
    {
        float4 v0 = rowi[lane], v1 = rowi[lane + 32];
        f4_fma(ws, v0, acc0);
        f4_fma(ws, v1, acc1);
    }
    int e0 = g_rowptr[i], e1 = g_rowptr[i + 1];
    for (int e = e0; e < e1; e++) {
        int   c  = g_col[e];
        float we = g_w[e];
        const float4* rowc = (const float4*)(t + (size_t)c * HID);
        float4 u0 = rowc[lane], u1 = rowc[lane + 32];
        f4_fma(we, u0, acc0);
        f4_fma(we, u1, acc1);
    }
    float4 b0 = ((const float4*)bias)[lane];
    float4 b1 = ((const float4*)bias)[lane + 32];
    acc0.x = fmaxf(acc0.x + b0.x, 0.f); acc0.y = fmaxf(acc0.y + b0.y, 0.f);
    acc0.z = fmaxf(acc0.z + b0.z, 0.f); acc0.w = fmaxf(acc0.w + b0.w, 0.f);
    acc1.x = fmaxf(acc1.x + b1.x, 0.f); acc1.y = fmaxf(acc1.y + b1.y, 0.f);
    acc1.z = fmaxf(acc1.z + b1.z, 0.f); acc1.w = fmaxf(acc1.w + b1.w, 0.f);
    float4* dstp = (float4*)(out + (size_t)i * HID);
    dstp[lane]      = acc0;
    dstp[lane + 32] = acc1;
}

// ---------------- mean pool per graph (batch is sorted, int32) ----------------
__device__ __forceinline__ int lower_bound_i(const int* a, int n, int key) {
    int lo = 0, hi = n;
    while (lo < hi) {
        int mid = (lo + hi) >> 1;
        if (a[mid] < key) lo = mid + 1; else hi = mid;
    }
    return lo;
}

__global__ void __launch_bounds__(256) pool_kernel(
    const float* __restrict__ h, const int* __restrict__ batch)
{
    int g = blockIdx.x;
    int lo = lower_bound_i(batch, N_NODES, g);
    int hi = lower_bound_i(batch, N_NODES, g + 1);
    int cnt = hi - lo;
    int f = threadIdx.x;              // 0..255
    float acc = 0.f;
    for (int i = lo; i < hi; i++)
        acc += h[(size_t)i * HID + f];
    g_pool[(size_t)g * HID + f] = acc / fmaxf((float)cnt, 1.0f);
}

// ---------------- launch ----------------
extern "C" void kernel_launch(void* const* d_in, const int* in_sizes, int n_in,
                              void* d_out, int out_size)
{
    const float* x    = (const float*)d_in[0];
    const int*   ei   = (const int*)d_in[1];     // int32! JAX x64 disabled
    const int*   batc = (const int*)d_in[2];     // int32!
    const float *W1 = (const float*)d_in[3],  *b1 = (const float*)d_in[4];
    const float *W2 = (const float*)d_in[5],  *b2 = (const float*)d_in[6];
    const float *W3 = (const float*)d_in[7],  *b3 = (const float*)d_in[8];
    const float *Wf1 = (const float*)d_in[9], *bf1 = (const float*)d_in[10];
    const float *Wf2 = (const float*)d_in[11], *bf2 = (const float*)d_in[12];
    float* out = (float*)d_out;

    const int* src = ei;               // row 0 of (2, E)
    const int* dst = ei + N_EDGES;     // row 1

    float *t_buf, *h_buf, *pool_buf, *fc1_buf;
    cudaGetSymbolAddress((void**)&t_buf, g_t);
    cudaGetSymbolAddress((void**)&h_buf, g_h);
    cudaGetSymbolAddress((void**)&pool_buf, g_pool);
    cudaGetSymbolAddress((void**)&fc1_buf, g_fc1);

    // --- graph preprocessing ---
    k_init_deg<<<(N_NODES + 255) / 256, 256>>>();
    k_count<<<(N_EDGES + 255) / 256, 256>>>(dst);
    k_dinv<<<(N_NODES + 255) / 256, 256>>>();
    k_scan<<<1, 1024>>>();
    k_fill<<<(N_EDGES + 255) / 256, 256>>>(src, dst);

    const int aggBlocks = (N_NODES * 32 + 255) / 256;

    // --- layer 1: t = x @ W1 ; h = relu(agg(t) + b1) ---
    {
        dim3 grid((N_NODES + 127) / 128, (HID + 127) / 128);
        gemm_kernel<false, false><<<grid, 256>>>(x, W1, nullptr, t_buf, N_NODES, HID, 128);
        agg_relu_kernel<<<aggBlocks, 256>>>(t_buf, h_buf, b1);
    }
    // --- layer 2 ---
    {
        dim3 grid((N_NODES + 127) / 128, (HID + 127) / 128);
        gemm_kernel<false, false><<<grid, 256>>>(h_buf, W2, nullptr, t_buf, N_NODES, HID, HID);
        agg_relu_kernel<<<aggBlocks, 256>>>(t_buf, h_buf, b2);
    }
    // --- layer 3 ---
    {
        dim3 grid((N_NODES + 127) / 128, (HID + 127) / 128);
        gemm_kernel<false, false><<<grid, 256>>>(h_buf, W3, nullptr, t_buf, N_NODES, HID, HID);
        agg_relu_kernel<<<aggBlocks, 256>>>(t_buf, h_buf, b3);
    }

    // --- mean pool ---
    pool_kernel<<<N_GRAPHS, 256>>>(h_buf, batc);

    // --- MLP head ---
    {
        dim3 grid((N_GRAPHS + 127) / 128, 1);
        gemm_kernel<true, true><<<grid, 256>>>(pool_buf, Wf1, bf1, fc1_buf, N_GRAPHS, 128, HID);
        gemm_kernel<true, false><<<grid, 256>>>(fc1_buf, Wf2, bf2, out, N_GRAPHS, 32, 128);
    }
}

// round 3
// speedup vs baseline: 1.5944x; 1.5944x over previous
#include <cuda_runtime.h>
#include <cuda_bf16.h>
#include <math.h>
#include <stdint.h>

#define N_NODES 50000
#define N_EDGES 300000
#define N_GRAPHS 2048
#define HID 256

// ---------------- scratch (static __device__, no allocation) ----------------
__device__ int   g_deg[N_NODES];
__device__ float g_dinv[N_NODES];
__device__ int   g_rowptr[N_NODES + 1];
__device__ int   g_cursor[N_NODES];
__device__ int   g_col[N_EDGES];
__device__ float g_w[N_EDGES];
__device__ float g_t[(size_t)N_NODES * HID];     // GEMM output (pre-aggregation)
__device__ float g_h[(size_t)N_NODES * HID];     // post-aggregation activations
__device__ float g_pool[(size_t)N_GRAPHS * HID];
__device__ float g_fc1[(size_t)N_GRAPHS * 128];

// ---------------- small helpers ----------------
__device__ __forceinline__ float4 f4_zero() { return make_float4(0.f, 0.f, 0.f, 0.f); }
__device__ __forceinline__ void f4_fma(float s, const float4& a, float4& acc) {
    acc.x = fmaf(s, a.x, acc.x); acc.y = fmaf(s, a.y, acc.y);
    acc.z = fmaf(s, a.z, acc.z); acc.w = fmaf(s, a.w, acc.w);
}
__device__ __forceinline__ uint32_t f2tf32(float f) {
    uint32_t r;
    asm("cvt.rna.tf32.f32 %0, %1;" : "=r"(r) : "f"(f));
    return r;
}

// ---------------- graph preprocessing ----------------
__global__ void k_init_deg() {
    int i = blockIdx.x * blockDim.x + threadIdx.x;
    if (i < N_NODES) g_deg[i] = 1;   // self loop
}

__global__ void k_count(const int* __restrict__ dst) {
    int e = blockIdx.x * blockDim.x + threadIdx.x;
    if (e < N_EDGES) atomicAdd(&g_deg[dst[e]], 1);
}

__global__ void k_dinv() {
    int i = blockIdx.x * blockDim.x + threadIdx.x;
    if (i < N_NODES) g_dinv[i] = rsqrtf((float)g_deg[i]);
}

// Fast single-block scan: 1024 threads x 49 contiguous elems each.
// 2 gmem passes, shfl warp scan, 2 barriers.
__global__ void __launch_bounds__(1024) k_scan_fast() {
    const int CH = 49;                       // 1024*49 = 50176 >= 50000
    int t = threadIdx.x;
    int lane = t & 31, warp = t >> 5;
    int base = t * CH;

    int sum = 0;
#pragma unroll 7
    for (int i = 0; i < CH; i++) {
        int idx = base + i;
        if (idx < N_NODES) sum += g_deg[idx] - 1;
    }
    // warp inclusive scan
    int incl = sum;
#pragma unroll
    for (int off = 1; off < 32; off <<= 1) {
        int v = __shfl_up_sync(0xffffffffu, incl, off);
        if (lane >= off) incl += v;
    }
    __shared__ int s_wsum[32];
    if (lane == 31) s_wsum[warp] = incl;
    __syncthreads();
    if (warp == 0) {
        int v = s_wsum[lane];
        int wincl = v;
#pragma unroll
        for (int off = 1; off < 32; off <<= 1) {
            int u = __shfl_up_sync(0xffffffffu, wincl, off);
            if (lane >= off) wincl += u;
        }
        s_wsum[lane] = wincl - v;            // exclusive warp prefix
    }
    __syncthreads();
    int excl = s_wsum[warp] + incl - sum;    // exclusive thread prefix

    int run = excl;
#pragma unroll 7
    for (int i = 0; i < CH; i++) {
        int idx = base + i;
        if (idx < N_NODES) {
            g_rowptr[idx] = run;
            g_cursor[idx] = run;
            run += g_deg[idx] - 1;
        }
    }
    if (t == 1023) g_rowptr[N_NODES] = run;
}

__global__ void k_fill(const int* __restrict__ src, const int* __restrict__ dst) {
    int e = blockIdx.x * blockDim.x + threadIdx.x;
    if (e < N_EDGES) {
        int s = src[e], d = dst[e];
        int pos = atomicAdd(&g_cursor[d], 1);
        g_col[pos] = s;
        g_w[pos]   = g_dinv[s] * g_dinv[d];
    }
}

// ---------------- tf32 tensor-core GEMM: C[M,N] = A[M,K] @ B[K,N] (+bias,+relu) ----
// BM=128, BN=128, BK=32; 256 threads = 8 warps, warp tile 64x32 (4x4 m16n8k8 mmas).
// Requires K % 32 == 0. M, N arbitrary (guarded).
#define SMEM_PAD 8
#define SROW (128 + SMEM_PAD)   // 136: (8k+g) mod 32 distinct -> conflict-free frags

template <bool BIAS, bool RELU>
__global__ void __launch_bounds__(256) gemm_tf32_kernel(
    const float* __restrict__ A, const float* __restrict__ B,
    const float* __restrict__ bias, float* __restrict__ C,
    int M, int N, int K)
{
    __shared__ float As[32][SROW];   // [k][m], tf32 bit patterns
    __shared__ float Bs[32][SROW];   // [k][n]

    const int tid   = threadIdx.x;
    const int lane  = tid & 31;
    const int warp  = tid >> 5;
    const int wm    = warp >> 2;          // 0..1 -> rows wm*64
    const int wn    = warp & 3;           // 0..3 -> cols wn*32
    const int g     = lane >> 2;          // groupID 0..7
    const int tig   = lane & 3;           // thread-in-group 0..3
    const int brow  = blockIdx.x, bcol = blockIdx.y;

    float acc[4][4][4];                   // [im][in][c0..c3]
#pragma unroll
    for (int im = 0; im < 4; im++)
#pragma unroll
        for (int in = 0; in < 4; in++)
#pragma unroll
            for (int c = 0; c < 4; c++) acc[im][in][c] = 0.f;

    for (int k0 = 0; k0 < K; k0 += 32) {
        // --- load A tile 128x32 (1024 float4), transpose to As[k][m], cvt tf32 ---
#pragma unroll
        for (int it = 0; it < 4; it++) {
            int f   = tid + it * 256;
            int r   = f >> 3;                 // 0..127
            int kc4 = (f & 7) << 2;           // 0,4,...,28
            int grow = brow * 128 + r;
            float4 v = f4_zero();
            if (grow < M) v = *(const float4*)(A + (size_t)grow * K + k0 + kc4);
            As[kc4 + 0][r] = __uint_as_float(f2tf32(v.x));
            As[kc4 + 1][r] = __uint_as_float(f2tf32(v.y));
            As[kc4 + 2][r] = __uint_as_float(f2tf32(v.z));
            As[kc4 + 3][r] = __uint_as_float(f2tf32(v.w));
        }
        // --- load B tile 32x128 (1024 float4) to Bs[k][n], cvt tf32 ---
#pragma unroll
        for (int it = 0; it < 4; it++) {
            int f  = tid + it * 256;
            int kr = f >> 5;                  // 0..31
            int c4 = (f & 31) << 2;           // 0..124
            int gcol = bcol * 128 + c4;
            float4 v = f4_zero();
            if (gcol + 3 < N) v = *(const float4*)(B + (size_t)(k0 + kr) * N + gcol);
            else if (gcol < N) {
                v.x = B[(size_t)(k0 + kr) * N + gcol];
                if (gcol + 1 < N) v.y = B[(size_t)(k0 + kr) * N + gcol + 1];
                if (gcol + 2 < N) v.z = B[(size_t)(k0 + kr) * N + gcol + 2];
            }
            float4 w;
            w.x = __uint_as_float(f2tf32(v.x));
            w.y = __uint_as_float(f2tf32(v.y));
            w.z = __uint_as_float(f2tf32(v.z));
            w.w = __uint_as_float(f2tf32(v.w));
            *(float4*)&Bs[kr][c4] = w;
        }
        __syncthreads();

#pragma unroll
        for (int ks = 0; ks < 4; ks++) {
            const int kk = ks * 8;
            uint32_t af[4][4], bf[4][2];
#pragma unroll
            for (int im = 0; im < 4; im++) {
                int m0 = wm * 64 + im * 16;
                af[im][0] = __float_as_uint(As[kk + tig    ][m0 + g    ]);
                af[im][1] = __float_as_uint(As[kk + tig    ][m0 + g + 8]);
                af[im][2] = __float_as_uint(As[kk + tig + 4][m0 + g    ]);
                af[im][3] = __float_as_uint(As[kk + tig + 4][m0 + g + 8]);
            }
#pragma unroll
            for (int in = 0; in < 4; in++) {
                int n0 = wn * 32 + in * 8;
                bf[in][0] = __float_as_uint(Bs[kk + tig    ][n0 + g]);
                bf[in][1] = __float_as_uint(Bs[kk + tig + 4][n0 + g]);
            }
#pragma unroll
            for (int im = 0; im < 4; im++)
#pragma unroll
                for (int in = 0; in < 4; in++) {
                    asm volatile(
                        "mma.sync.aligned.m16n8k8.row.col.f32.tf32.tf32.f32 "
                        "{%0,%1,%2,%3}, {%4,%5,%6,%7}, {%8,%9}, {%0,%1,%2,%3};\n"
                        : "+f"(acc[im][in][0]), "+f"(acc[im][in][1]),
                          "+f"(acc[im][in][2]), "+f"(acc[im][in][3])
                        : "r"(af[im][0]), "r"(af[im][1]), "r"(af[im][2]), "r"(af[im][3]),
                          "r"(bf[in][0]), "r"(bf[in][1]));
                }
        }
        __syncthreads();
    }

    // --- epilogue ---
#pragma unroll
    for (int im = 0; im < 4; im++) {
        int r0 = brow * 128 + wm * 64 + im * 16 + g;
#pragma unroll
        for (int in = 0; in < 4; in++) {
            int c0 = bcol * 128 + wn * 32 + in * 8 + tig * 2;
            if (c0 >= N) continue;
            float b0v = 0.f, b1v = 0.f;
            if (BIAS) { b0v = bias[c0]; if (c0 + 1 < N) b1v = bias[c0 + 1]; }
            if (r0 < M) {
                float v0 = acc[im][in][0] + b0v;
                float v1 = acc[im][in][1] + b1v;
                if (RELU) { v0 = fmaxf(v0, 0.f); v1 = fmaxf(v1, 0.f); }
                C[(size_t)r0 * N + c0] = v0;
                if (c0 + 1 < N) C[(size_t)r0 * N + c0 + 1] = v1;
            }
            if (r0 + 8 < M) {
                float v2 = acc[im][in][2] + b0v;
                float v3 = acc[im][in][3] + b1v;
                if (RELU) { v2 = fmaxf(v2, 0.f); v3 = fmaxf(v3, 0.f); }
                C[(size_t)(r0 + 8) * N + c0] = v2;
                if (c0 + 1 < N) C[(size_t)(r0 + 8) * N + c0 + 1] = v3;
            }
        }
    }
}

// ---------------- aggregation: out[i] = relu(b + dinv[i]^2*t[i] + sum_e w_e*t[col_e]) ----
__global__ void __launch_bounds__(256) agg_relu_kernel(
    const float* __restrict__ t, float* __restrict__ out, const float* __restrict__ bias)
{
    int warp = (blockIdx.x * blockDim.x + threadIdx.x) >> 5;
    int lane = threadIdx.x & 31;
    if (warp >= N_NODES) return;
    const int i = warp;

    const float4* rowi = (const float4*)(t + (size_t)i * HID);
    float di = g_dinv[i];
    float ws = di * di;
    float4 acc0 = f4_zero(), acc1 = f4_zero();
    {
        float4 v0 = rowi[lane], v1 = rowi[lane + 32];
        f4_fma(ws, v0, acc0);
        f4_fma(ws, v1, acc1);
    }
    int e0 = g_rowptr[i], e1 = g_rowptr[i + 1];
    for (int e = e0; e < e1; e++) {
        int   c  = g_col[e];
        float we = g_w[e];
        const float4* rowc = (const float4*)(t + (size_t)c * HID);
        float4 u0 = rowc[lane], u1 = rowc[lane + 32];
        f4_fma(we, u0, acc0);
        f4_fma(we, u1, acc1);
    }
    float4 b0 = ((const float4*)bias)[lane];
    float4 b1 = ((const float4*)bias)[lane + 32];
    acc0.x = fmaxf(acc0.x + b0.x, 0.f); acc0.y = fmaxf(acc0.y + b0.y, 0.f);
    acc0.z = fmaxf(acc0.z + b0.z, 0.f); acc0.w = fmaxf(acc0.w + b0.w, 0.f);
    acc1.x = fmaxf(acc1.x + b1.x, 0.f); acc1.y = fmaxf(acc1.y + b1.y, 0.f);
    acc1.z = fmaxf(acc1.z + b1.z, 0.f); acc1.w = fmaxf(acc1.w + b1.w, 0.f);
    float4* dstp = (float4*)(out + (size_t)i * HID);
    dstp[lane]      = acc0;
    dstp[lane + 32] = acc1;
}

// ---------------- mean pool per graph (batch is sorted, int32) ----------------
__device__ __forceinline__ int lower_bound_i(const int* a, int n, int key) {
    int lo = 0, hi = n;
    while (lo < hi) {
        int mid = (lo + hi) >> 1;
        if (a[mid] < key) lo = mid + 1; else hi = mid;
    }
    return lo;
}

__global__ void __launch_bounds__(256) pool_kernel(
    const float* __restrict__ h, const int* __restrict__ batch)
{
    int g = blockIdx.x;
    int lo = lower_bound_i(batch, N_NODES, g);
    int hi = lower_bound_i(batch, N_NODES, g + 1);
    int cnt = hi - lo;
    int f = threadIdx.x;              // 0..255
    float acc = 0.f;
    for (int i = lo; i < hi; i++)
        acc += h[(size_t)i * HID + f];
    g_pool[(size_t)g * HID + f] = acc / fmaxf((float)cnt, 1.0f);
}

// ---------------- launch ----------------
extern "C" void kernel_launch(void* const* d_in, const int* in_sizes, int n_in,
                              void* d_out, int out_size)
{
    const float* x    = (const float*)d_in[0];
    const int*   ei   = (const int*)d_in[1];     // int32 (JAX x64 disabled)
    const int*   batc = (const int*)d_in[2];     // int32
    const float *W1 = (const float*)d_in[3],  *b1 = (const float*)d_in[4];
    const float *W2 = (const float*)d_in[5],  *b2 = (const float*)d_in[6];
    const float *W3 = (const float*)d_in[7],  *b3 = (const float*)d_in[8];
    const float *Wf1 = (const float*)d_in[9], *bf1 = (const float*)d_in[10];
    const float *Wf2 = (const float*)d_in[11], *bf2 = (const float*)d_in[12];
    float* out = (float*)d_out;

    const int* src = ei;               // row 0 of (2, E)
    const int* dst = ei + N_EDGES;     // row 1

    float *t_buf, *h_buf, *pool_buf, *fc1_buf;
    cudaGetSymbolAddress((void**)&t_buf, g_t);
    cudaGetSymbolAddress((void**)&h_buf, g_h);
    cudaGetSymbolAddress((void**)&pool_buf, g_pool);
    cudaGetSymbolAddress((void**)&fc1_buf, g_fc1);

    // --- graph preprocessing ---
    k_init_deg<<<(N_NODES + 255) / 256, 256>>>();
    k_count<<<(N_EDGES + 255) / 256, 256>>>(dst);
    k_dinv<<<(N_NODES + 255) / 256, 256>>>();
    k_scan_fast<<<1, 1024>>>();
    k_fill<<<(N_EDGES + 255) / 256, 256>>>(src, dst);

    const int aggBlocks = (N_NODES * 32 + 255) / 256;
    dim3 gridN((N_NODES + 127) / 128, (HID + 127) / 128);   // (391, 2)

    // --- layer 1 ---
    gemm_tf32_kernel<false, false><<<gridN, 256>>>(x, W1, nullptr, t_buf, N_NODES, HID, 128);
    agg_relu_kernel<<<aggBlocks, 256>>>(t_buf, h_buf, b1);
    // --- layer 2 ---
    gemm_tf32_kernel<false, false><<<gridN, 256>>>(h_buf, W2, nullptr, t_buf, N_NODES, HID, HID);
    agg_relu_kernel<<<aggBlocks, 256>>>(t_buf, h_buf, b2);
    // --- layer 3 ---
    gemm_tf32_kernel<false, false><<<gridN, 256>>>(h_buf, W3, nullptr, t_buf, N_NODES, HID, HID);
    agg_relu_kernel<<<aggBlocks, 256>>>(t_buf, h_buf, b3);

    // --- mean pool ---
    pool_kernel<<<N_GRAPHS, 256>>>(h_buf, batc);

    // --- MLP head ---
    dim3 gridM((N_GRAPHS + 127) / 128, 1);
    gemm_tf32_kernel<true, true ><<<gridM, 256>>>(pool_buf, Wf1, bf1, fc1_buf, N_GRAPHS, 128, HID);
    gemm_tf32_kernel<true, false><<<gridM, 256>>>(fc1_buf, Wf2, bf2, out, N_GRAPHS, 32, 128);
}

// round 4
// speedup vs baseline: 2.0140x; 1.2631x over previous
#include <cuda_runtime.h>
#include <cuda_bf16.h>
#include <math.h>
#include <stdint.h>

#define N_NODES 50000
#define N_EDGES 300000
#define N_GRAPHS 2048
#define HID 256

// ---------------- scratch (static __device__, no allocation) ----------------
__device__ int   g_deg[N_NODES];
__device__ float g_dinv[N_NODES];
__device__ int   g_rowptr[N_NODES + 1];
__device__ int   g_cursor[N_NODES];
__device__ int   g_col[N_EDGES];
__device__ float g_w[N_EDGES];
__device__ float g_t[(size_t)N_NODES * HID];     // GEMM output (pre-aggregation)
__device__ float g_h[(size_t)N_NODES * HID];     // post-aggregation activations
__device__ float g_pool[(size_t)N_GRAPHS * HID];
__device__ float g_fc1[(size_t)N_GRAPHS * 128];

// ---------------- small helpers ----------------
__device__ __forceinline__ float4 f4_zero() { return make_float4(0.f, 0.f, 0.f, 0.f); }
__device__ __forceinline__ void f4_fma(float s, const float4& a, float4& acc) {
    acc.x = fmaf(s, a.x, acc.x); acc.y = fmaf(s, a.y, acc.y);
    acc.z = fmaf(s, a.z, acc.z); acc.w = fmaf(s, a.w, acc.w);
}
__device__ __forceinline__ uint32_t f2tf32(float f) {
    uint32_t r;
    asm("cvt.rna.tf32.f32 %0, %1;" : "=r"(r) : "f"(f));
    return r;
}

// ---------------- graph preprocessing ----------------
__global__ void k_init_deg() {
    int i = blockIdx.x * blockDim.x + threadIdx.x;
    if (i < N_NODES) g_deg[i] = 1;   // self loop
}

__global__ void k_count(const int* __restrict__ dst) {
    int e = blockIdx.x * blockDim.x + threadIdx.x;
    if (e < N_EDGES) atomicAdd(&g_deg[dst[e]], 1);
}

__global__ void k_dinv() {
    int i = blockIdx.x * blockDim.x + threadIdx.x;
    if (i < N_NODES) g_dinv[i] = rsqrtf((float)g_deg[i]);
}

// Coalesced smem-staged single-block scan.
// All gmem traffic coalesced; the serial per-thread chunk walk happens in smem
// (chunk stride 49 ints -> bank 17*l mod 32, bijective -> conflict-free).
#define SCAN_CH 49
#define SCAN_TOT (1024 * SCAN_CH)   // 50176
#define SCAN_SMEM_BYTES (SCAN_TOT * 4)

__global__ void __launch_bounds__(1024) k_scan_fast() {
    extern __shared__ int s[];       // SCAN_TOT ints
    __shared__ int s_wsum[32];
    const int t = threadIdx.x;
    const int lane = t & 31, warp = t >> 5;

    // Phase 1: coalesced load of (deg - 1)
#pragma unroll
    for (int v = 0; v < SCAN_CH; v++) {
        int idx = v * 1024 + t;
        s[idx] = (idx < N_NODES) ? (g_deg[idx] - 1) : 0;
    }
    __syncthreads();

    // Phase 2: per-thread chunk sum (smem, conflict-free)
    const int base = t * SCAN_CH;
    int sum = 0;
#pragma unroll
    for (int i = 0; i < SCAN_CH; i++) sum += s[base + i];

    // warp inclusive scan
    int incl = sum;
#pragma unroll
    for (int off = 1; off < 32; off <<= 1) {
        int v = __shfl_up_sync(0xffffffffu, incl, off);
        if (lane >= off) incl += v;
    }
    if (lane == 31) s_wsum[warp] = incl;
    __syncthreads();
    if (warp == 0) {
        int v = s_wsum[lane];
        int wincl = v;
#pragma unroll
        for (int off = 1; off < 32; off <<= 1) {
            int u = __shfl_up_sync(0xffffffffu, wincl, off);
            if (lane >= off) wincl += u;
        }
        s_wsum[lane] = wincl - v;    // exclusive warp prefix
    }
    __syncthreads();

    // Phase 3: in-place exclusive prefix within chunk
    int run = s_wsum[warp] + incl - sum;
#pragma unroll
    for (int i = 0; i < SCAN_CH; i++) {
        int vdeg = s[base + i];
        s[base + i] = run;
        run += vdeg;
    }
    if (t == 1023) g_rowptr[N_NODES] = run;   // grand total
    __syncthreads();

    // Phase 4: coalesced write-out
#pragma unroll
    for (int v = 0; v < SCAN_CH; v++) {
        int idx = v * 1024 + t;
        if (idx < N_NODES) {
            int p = s[idx];
            g_rowptr[idx] = p;
            g_cursor[idx] = p;
        }
    }
}

__global__ void k_fill(const int* __restrict__ src, const int* __restrict__ dst) {
    int e = blockIdx.x * blockDim.x + threadIdx.x;
    if (e < N_EDGES) {
        int s = src[e], d = dst[e];
        int pos = atomicAdd(&g_cursor[d], 1);
        g_col[pos] = s;
        g_w[pos]   = g_dinv[s] * g_dinv[d];
    }
}

// ---------------- tf32 tensor-core GEMM (double-buffered) ----------------
// C[M,N] = A[M,K] @ B[K,N] (+bias,+relu). BM=BN=128, BK=32; 256 thr = 8 warps,
// warp tile 64x32 (4x4 m16n8k8). Requires K % 32 == 0.
#define SMEM_PAD 8
#define SROW (128 + SMEM_PAD)             // 136
#define GEMM_TILE_FLOATS (32 * SROW)      // one 32xSROW plane
#define GEMM_SMEM_BYTES (4 * GEMM_TILE_FLOATS * 4)   // 2 bufs x (A+B) = 69632 B

template <bool BIAS, bool RELU>
__global__ void __launch_bounds__(256) gemm_tf32_kernel(
    const float* __restrict__ A, const float* __restrict__ B,
    const float* __restrict__ bias, float* __restrict__ C,
    int M, int N, int K)
{
    extern __shared__ float smem[];
    // As buffer b: smem + b*GEMM_TILE_FLOATS ; Bs buffer b: smem + (2+b)*GEMM_TILE_FLOATS

    const int tid   = threadIdx.x;
    const int lane  = tid & 31;
    const int warp  = tid >> 5;
    const int wm    = warp >> 2;          // 0..1 -> rows wm*64
    const int wn    = warp & 3;           // 0..3 -> cols wn*32
    const int g     = lane >> 2;          // groupID 0..7
    const int tig   = lane & 3;           // thread-in-group 0..3
    const int brow  = blockIdx.x, bcol = blockIdx.y;

    float acc[4][4][4];
#pragma unroll
    for (int im = 0; im < 4; im++)
#pragma unroll
        for (int in = 0; in < 4; in++)
#pragma unroll
            for (int c = 0; c < 4; c++) acc[im][in][c] = 0.f;

    float4 va[4], vb[4];   // staging registers

    auto load_tiles = [&](int k0) {
#pragma unroll
        for (int it = 0; it < 4; it++) {
            int f   = tid + it * 256;
            int r   = f >> 3;                 // 0..127
            int kc4 = (f & 7) << 2;           // 0..28
            int grow = brow * 128 + r;
            va[it] = f4_zero();
            if (grow < M) va[it] = *(const float4*)(A + (size_t)grow * K + k0 + kc4);
        }
#pragma unroll
        for (int it = 0; it < 4; it++) {
            int f  = tid + it * 256;
            int kr = f >> 5;                  // 0..31
            int c4 = (f & 31) << 2;           // 0..124
            int gcol = bcol * 128 + c4;
            vb[it] = f4_zero();
            if (gcol + 3 < N) vb[it] = *(const float4*)(B + (size_t)(k0 + kr) * N + gcol);
            else if (gcol < N) {
                vb[it].x = B[(size_t)(k0 + kr) * N + gcol];
                if (gcol + 1 < N) vb[it].y = B[(size_t)(k0 + kr) * N + gcol + 1];
                if (gcol + 2 < N) vb[it].z = B[(size_t)(k0 + kr) * N + gcol + 2];
            }
        }
    };

    auto store_tiles = [&](int b) {
        float* Asb = smem + b * GEMM_TILE_FLOATS;
        float* Bsb = smem + (2 + b) * GEMM_TILE_FLOATS;
#pragma unroll
        for (int it = 0; it < 4; it++) {
            int f   = tid + it * 256;
            int r   = f >> 3;
            int kc4 = (f & 7) << 2;
            Asb[(kc4 + 0) * SROW + r] = __uint_as_float(f2tf32(va[it].x));
            Asb[(kc4 + 1) * SROW + r] = __uint_as_float(f2tf32(va[it].y));
            Asb[(kc4 + 2) * SROW + r] = __uint_as_float(f2tf32(va[it].z));
            Asb[(kc4 + 3) * SROW + r] = __uint_as_float(f2tf32(va[it].w));
        }
#pragma unroll
        for (int it = 0; it < 4; it++) {
            int f  = tid + it * 256;
            int kr = f >> 5;
            int c4 = (f & 31) << 2;
            float4 w;
            w.x = __uint_as_float(f2tf32(vb[it].x));
            w.y = __uint_as_float(f2tf32(vb[it].y));
            w.z = __uint_as_float(f2tf32(vb[it].z));
            w.w = __uint_as_float(f2tf32(vb[it].w));
            *(float4*)&Bsb[kr * SROW + c4] = w;
        }
    };

    const int nk = K >> 5;
    load_tiles(0);
    store_tiles(0);
    __syncthreads();

    for (int tk = 0; tk < nk; tk++) {
        const int cur = tk & 1;
        if (tk + 1 < nk) load_tiles((tk + 1) << 5);   // LDGs in flight during compute

        const float* Asb = smem + cur * GEMM_TILE_FLOATS;
        const float* Bsb = smem + (2 + cur) * GEMM_TILE_FLOATS;
#pragma unroll
        for (int ks = 0; ks < 4; ks++) {
            const int kk = ks * 8;
            uint32_t af[4][4], bf[4][2];
#pragma unroll
            for (int im = 0; im < 4; im++) {
                int m0 = wm * 64 + im * 16;
                af[im][0] = __float_as_uint(Asb[(kk + tig    ) * SROW + m0 + g    ]);
                af[im][1] = __float_as_uint(Asb[(kk + tig    ) * SROW + m0 + g + 8]);
                af[im][2] = __float_as_uint(Asb[(kk + tig + 4) * SROW + m0 + g    ]);
                af[im][3] = __float_as_uint(Asb[(kk + tig + 4) * SROW + m0 + g + 8]);
            }
#pragma unroll
            for (int in = 0; in < 4; in++) {
                int n0 = wn * 32 + in * 8;
                bf[in][0] = __float_as_uint(Bsb[(kk + tig    ) * SROW + n0 + g]);
                bf[in][1] = __float_as_uint(Bsb[(kk + tig + 4) * SROW + n0 + g]);
            }
#pragma unroll
            for (int im = 0; im < 4; im++)
#pragma unroll
                for (int in = 0; in < 4; in++) {
                    asm volatile(
                        "mma.sync.aligned.m16n8k8.row.col.f32.tf32.tf32.f32 "
                        "{%0,%1,%2,%3}, {%4,%5,%6,%7}, {%8,%9}, {%0,%1,%2,%3};\n"
                        : "+f"(acc[im][in][0]), "+f"(acc[im][in][1]),
                          "+f"(acc[im][in][2]), "+f"(acc[im][in][3])
                        : "r"(af[im][0]), "r"(af[im][1]), "r"(af[im][2]), "r"(af[im][3]),
                          "r"(bf[in][0]), "r"(bf[in][1]));
                }
        }

        if (tk + 1 < nk) store_tiles(1 - cur);   // other buf: last read 2 iters ago
        __syncthreads();
    }

    // --- epilogue ---
#pragma unroll
    for (int im = 0; im < 4; im++) {
        int r0 = brow * 128 + wm * 64 + im * 16 + g;
#pragma unroll
        for (int in = 0; in < 4; in++) {
            int c0 = bcol * 128 + wn * 32 + in * 8 + tig * 2;
            if (c0 >= N) continue;
            float b0v = 0.f, b1v = 0.f;
            if (BIAS) { b0v = bias[c0]; if (c0 + 1 < N) b1v = bias[c0 + 1]; }
            if (r0 < M) {
                float v0 = acc[im][in][0] + b0v;
                float v1 = acc[im][in][1] + b1v;
                if (RELU) { v0 = fmaxf(v0, 0.f); v1 = fmaxf(v1, 0.f); }
                C[(size_t)r0 * N + c0] = v0;
                if (c0 + 1 < N) C[(size_t)r0 * N + c0 + 1] = v1;
            }
            if (r0 + 8 < M) {
                float v2 = acc[im][in][2] + b0v;
                float v3 = acc[im][in][3] + b1v;
                if (RELU) { v2 = fmaxf(v2, 0.f); v3 = fmaxf(v3, 0.f); }
                C[(size_t)(r0 + 8) * N + c0] = v2;
                if (c0 + 1 < N) C[(size_t)(r0 + 8) * N + c0 + 1] = v3;
            }
        }
    }
}

// ---------------- aggregation: out[i] = relu(b + dinv[i]^2*t[i] + sum_e w_e*t[col_e]) ----
__global__ void __launch_bounds__(256) agg_relu_kernel(
    const float* __restrict__ t, float* __restrict__ out, const float* __restrict__ bias)
{
    int warp = (blockIdx.x * blockDim.x + threadIdx.x) >> 5;
    int lane = threadIdx.x & 31;
    if (warp >= N_NODES) return;
    const int i = warp;

    const float4* rowi = (const float4*)(t + (size_t)i * HID);
    float di = g_dinv[i];
    float ws = di * di;
    float4 acc0 = f4_zero(), acc1 = f4_zero();
    {
        float4 v0 = rowi[lane], v1 = rowi[lane + 32];
        f4_fma(ws, v0, acc0);
        f4_fma(ws, v1, acc1);
    }
    int e0 = g_rowptr[i], e1 = g_rowptr[i + 1];
    for (int e = e0; e < e1; e++) {
        int   c  = g_col[e];
        float we = g_w[e];
        const float4* rowc = (const float4*)(t + (size_t)c * HID);
        float4 u0 = rowc[lane], u1 = rowc[lane + 32];
        f4_fma(we, u0, acc0);
        f4_fma(we, u1, acc1);
    }
    float4 b0 = ((const float4*)bias)[lane];
    float4 b1 = ((const float4*)bias)[lane + 32];
    acc0.x = fmaxf(acc0.x + b0.x, 0.f); acc0.y = fmaxf(acc0.y + b0.y, 0.f);
    acc0.z = fmaxf(acc0.z + b0.z, 0.f); acc0.w = fmaxf(acc0.w + b0.w, 0.f);
    acc1.x = fmaxf(acc1.x + b1.x, 0.f); acc1.y = fmaxf(acc1.y + b1.y, 0.f);
    acc1.z = fmaxf(acc1.z + b1.z, 0.f); acc1.w = fmaxf(acc1.w + b1.w, 0.f);
    float4* dstp = (float4*)(out + (size_t)i * HID);
    dstp[lane]      = acc0;
    dstp[lane + 32] = acc1;
}

// ---------------- mean pool per graph (batch is sorted, int32) ----------------
__device__ __forceinline__ int lower_bound_i(const int* a, int n, int key) {
    int lo = 0, hi = n;
    while (lo < hi) {
        int mid = (lo + hi) >> 1;
        if (a[mid] < key) lo = mid + 1; else hi = mid;
    }
    return lo;
}

__global__ void __launch_bounds__(256) pool_kernel(
    const float* __restrict__ h, const int* __restrict__ batch)
{
    int g = blockIdx.x;
    int lo = lower_bound_i(batch, N_NODES, g);
    int hi = lower_bound_i(batch, N_NODES, g + 1);
    int cnt = hi - lo;
    int f = threadIdx.x;              // 0..255
    float acc = 0.f;
    for (int i = lo; i < hi; i++)
        acc += h[(size_t)i * HID + f];
    g_pool[(size_t)g * HID + f] = acc / fmaxf((float)cnt, 1.0f);
}

// ---------------- launch ----------------
extern "C" void kernel_launch(void* const* d_in, const int* in_sizes, int n_in,
                              void* d_out, int out_size)
{
    const float* x    = (const float*)d_in[0];
    const int*   ei   = (const int*)d_in[1];     // int32 (JAX x64 disabled)
    const int*   batc = (const int*)d_in[2];     // int32
    const float *W1 = (const float*)d_in[3],  *b1 = (const float*)d_in[4];
    const float *W2 = (const float*)d_in[5],  *b2 = (const float*)d_in[6];
    const float *W3 = (const float*)d_in[7],  *b3 = (const float*)d_in[8];
    const float *Wf1 = (const float*)d_in[9], *bf1 = (const float*)d_in[10];
    const float *Wf2 = (const float*)d_in[11], *bf2 = (const float*)d_in[12];
    float* out = (float*)d_out;

    const int* src = ei;               // row 0 of (2, E)
    const int* dst = ei + N_EDGES;     // row 1

    float *t_buf, *h_buf, *pool_buf, *fc1_buf;
    cudaGetSymbolAddress((void**)&t_buf, g_t);
    cudaGetSymbolAddress((void**)&h_buf, g_h);
    cudaGetSymbolAddress((void**)&pool_buf, g_pool);
    cudaGetSymbolAddress((void**)&fc1_buf, g_fc1);

    // opt-in large dynamic smem (idempotent host calls; not stream ops)
    cudaFuncSetAttribute(k_scan_fast, cudaFuncAttributeMaxDynamicSharedMemorySize, SCAN_SMEM_BYTES);
    cudaFuncSetAttribute(gemm_tf32_kernel<false, false>, cudaFuncAttributeMaxDynamicSharedMemorySize, GEMM_SMEM_BYTES);
    cudaFuncSetAttribute(gemm_tf32_kernel<true, true>,   cudaFuncAttributeMaxDynamicSharedMemorySize, GEMM_SMEM_BYTES);
    cudaFuncSetAttribute(gemm_tf32_kernel<true, false>,  cudaFuncAttributeMaxDynamicSharedMemorySize, GEMM_SMEM_BYTES);

    // --- graph preprocessing ---
    k_init_deg<<<(N_NODES + 255) / 256, 256>>>();
    k_count<<<(N_EDGES + 255) / 256, 256>>>(dst);
    k_dinv<<<(N_NODES + 255) / 256, 256>>>();
    k_scan_fast<<<1, 1024, SCAN_SMEM_BYTES>>>();
    k_fill<<<(N_EDGES + 255) / 256, 256>>>(src, dst);

    const int aggBlocks = (N_NODES * 32 + 255) / 256;
    dim3 gridN((N_NODES + 127) / 128, (HID + 127) / 128);   // (391, 2)

    // --- layer 1 ---
    gemm_tf32_kernel<false, false><<<gridN, 256, GEMM_SMEM_BYTES>>>(x, W1, nullptr, t_buf, N_NODES, HID, 128);
    agg_relu_kernel<<<aggBlocks, 256>>>(t_buf, h_buf, b1);
    // --- layer 2 ---
    gemm_tf32_kernel<false, false><<<gridN, 256, GEMM_SMEM_BYTES>>>(h_buf, W2, nullptr, t_buf, N_NODES, HID, HID);
    agg_relu_kernel<<<aggBlocks, 256>>>(t_buf, h_buf, b2);
    // --- layer 3 ---
    gemm_tf32_kernel<false, false><<<gridN, 256, GEMM_SMEM_BYTES>>>(h_buf, W3, nullptr, t_buf, N_NODES, HID, HID);
    agg_relu_kernel<<<aggBlocks, 256>>>(t_buf, h_buf, b3);

    // --- mean pool ---
    pool_kernel<<<N_GRAPHS, 256>>>(h_buf, batc);

    // --- MLP head ---
    dim3 gridM((N_GRAPHS + 127) / 128, 1);
    gemm_tf32_kernel<true, true ><<<gridM, 256, GEMM_SMEM_BYTES>>>(pool_buf, Wf1, bf1, fc1_buf, N_GRAPHS, 128, HID);
    gemm_tf32_kernel<true, false><<<gridM, 256, GEMM_SMEM_BYTES>>>(fc1_buf, Wf2, bf2, out, N_GRAPHS, 32, 128);
}

// round 5
// speedup vs baseline: 2.0644x; 1.0251x over previous
#include <cuda_runtime.h>
#include <cuda_bf16.h>
#include <math.h>
#include <stdint.h>

#define N_NODES 50000
#define N_EDGES 300000
#define N_GRAPHS 2048
#define HID 256
#define SCAN_NB ((N_NODES + 255) / 256)   // 196

// ---------------- scratch (static __device__, no allocation) ----------------
__device__ int   g_deg[N_NODES];
__device__ float g_dinv[N_NODES];
__device__ int   g_rowptr[N_NODES + 1];
__device__ int   g_cursor[N_NODES];
__device__ int   g_col[N_EDGES];
__device__ float g_w[N_EDGES];
__device__ int   g_bsum[256];
__device__ int   g_boff[256];
__device__ float g_t[(size_t)N_NODES * HID];     // GEMM output / agg input
__device__ float g_ax[(size_t)N_NODES * 128];    // layer-1 aggregated x
__device__ float g_h[(size_t)N_NODES * HID];     // post-layer activations
__device__ float g_pool[(size_t)N_GRAPHS * HID];
__device__ float g_fc1[(size_t)N_GRAPHS * 128];

// ---------------- small helpers ----------------
__device__ __forceinline__ float4 f4_zero() { return make_float4(0.f, 0.f, 0.f, 0.f); }
__device__ __forceinline__ void f4_fma(float s, const float4& a, float4& acc) {
    acc.x = fmaf(s, a.x, acc.x); acc.y = fmaf(s, a.y, acc.y);
    acc.z = fmaf(s, a.z, acc.z); acc.w = fmaf(s, a.w, acc.w);
}
__device__ __forceinline__ uint32_t f2tf32(float f) {
    uint32_t r;
    asm("cvt.rna.tf32.f32 %0, %1;" : "=r"(r) : "f"(f));
    return r;
}

// ---------------- graph preprocessing ----------------
__global__ void k_init_deg() {
    int i = blockIdx.x * blockDim.x + threadIdx.x;
    if (i < N_NODES) g_deg[i] = 1;   // self loop
}

__global__ void k_count(const int* __restrict__ dst) {
    int e = blockIdx.x * blockDim.x + threadIdx.x;
    if (e < N_EDGES) atomicAdd(&g_deg[dst[e]], 1);
}

// dinv + per-block sum of (deg-1), fused
__global__ void __launch_bounds__(256) k_dinv_bsum() {
    __shared__ int s_w[8];
    int idx = blockIdx.x * 256 + threadIdx.x;
    int lane = threadIdx.x & 31, warp = threadIdx.x >> 5;
    int v = 0;
    if (idx < N_NODES) {
        int d = g_deg[idx];
        g_dinv[idx] = rsqrtf((float)d);
        v = d - 1;
    }
    int s = v;
#pragma unroll
    for (int off = 16; off > 0; off >>= 1) s += __shfl_down_sync(0xffffffffu, s, off);
    if (lane == 0) s_w[warp] = s;
    __syncthreads();
    if (threadIdx.x == 0) {
        int t = 0;
#pragma unroll
        for (int w = 0; w < 8; w++) t += s_w[w];
        g_bsum[blockIdx.x] = t;
    }
}

// single-block exclusive scan of SCAN_NB block sums
__global__ void __launch_bounds__(256) k_bscan() {
    __shared__ int s_w[8];
    int t = threadIdx.x;
    int lane = t & 31, warp = t >> 5;
    int v = (t < SCAN_NB) ? g_bsum[t] : 0;
    int incl = v;
#pragma unroll
    for (int off = 1; off < 32; off <<= 1) {
        int u = __shfl_up_sync(0xffffffffu, incl, off);
        if (lane >= off) incl += u;
    }
    if (lane == 31) s_w[warp] = incl;
    __syncthreads();
    if (warp == 0 && lane < 8) {
        int u = s_w[lane];
        int wi = u;
#pragma unroll
        for (int off = 1; off < 8; off <<= 1) {
            int z = __shfl_up_sync(0xffu, wi, off);
            if (lane >= off) wi += z;
        }
        s_w[lane] = wi - u;   // exclusive
        if (lane == 7) g_rowptr[N_NODES] = wi;   // grand total
    }
    __syncthreads();
    if (t < SCAN_NB) g_boff[t] = s_w[warp] + incl - v;
}

// per-block scan + scatter of rowptr/cursor
__global__ void __launch_bounds__(256) k_scatter() {
    __shared__ int s_w[8];
    int idx = blockIdx.x * 256 + threadIdx.x;
    int lane = threadIdx.x & 31, warp = threadIdx.x >> 5;
    int v = (idx < N_NODES) ? (g_deg[idx] - 1) : 0;
    int incl = v;
#pragma unroll
    for (int off = 1; off < 32; off <<= 1) {
        int u = __shfl_up_sync(0xffffffffu, incl, off);
        if (lane >= off) incl += u;
    }
    if (lane == 31) s_w[warp] = incl;
    __syncthreads();
    if (warp == 0 && lane < 8) {
        int u = s_w[lane];
        int wi = u;
#pragma unroll
        for (int off = 1; off < 8; off <<= 1) {
            int z = __shfl_up_sync(0xffu, wi, off);
            if (lane >= off) wi += z;
        }
        s_w[lane] = wi - u;
    }
    __syncthreads();
    if (idx < N_NODES) {
        int p = g_boff[blockIdx.x] + s_w[warp] + incl - v;
        g_rowptr[idx] = p;
        g_cursor[idx] = p;
    }
}

__global__ void k_fill(const int* __restrict__ src, const int* __restrict__ dst) {
    int e = blockIdx.x * blockDim.x + threadIdx.x;
    if (e < N_EDGES) {
        int s = src[e], d = dst[e];
        int pos = atomicAdd(&g_cursor[d], 1);
        g_col[pos] = s;
        g_w[pos]   = g_dinv[s] * g_dinv[d];
    }
}

// ---------------- tf32 tensor-core GEMM (double-buffered, swizzled A) -------
// C[M,N] = A[M,K] @ B[K,N] (+bias,+relu). BM=BN=128, BK=32; 256 thr = 8 warps,
// warp tile 64x32 (4x4 m16n8k8). Requires K % 32 == 0.
#define SROW 136
#define GEMM_TILE_FLOATS (32 * SROW)
#define GEMM_SMEM_BYTES (4 * GEMM_TILE_FLOATS * 4)   // 69632 B

// A smem index: row k, logical col m, XOR swizzle kills STS bank conflicts
// while keeping fragment loads conflict-free.
__device__ __forceinline__ int aidx(int k, int m) {
    return k * SROW + (m ^ (((k >> 2) & 7) << 2));
}

template <bool BIAS, bool RELU>
__global__ void __launch_bounds__(256) gemm_tf32_kernel(
    const float* __restrict__ A, const float* __restrict__ B,
    const float* __restrict__ bias, float* __restrict__ C,
    int M, int N, int K)
{
    extern __shared__ float smem[];

    const int tid   = threadIdx.x;
    const int lane  = tid & 31;
    const int warp  = tid >> 5;
    const int wm    = warp >> 2;
    const int wn    = warp & 3;
    const int g     = lane >> 2;
    const int tig   = lane & 3;
    const int brow  = blockIdx.x, bcol = blockIdx.y;

    float acc[4][4][4];
#pragma unroll
    for (int im = 0; im < 4; im++)
#pragma unroll
        for (int in = 0; in < 4; in++)
#pragma unroll
            for (int c = 0; c < 4; c++) acc[im][in][c] = 0.f;

    float4 va[4], vb[4];

    auto load_tiles = [&](int k0) {
#pragma unroll
        for (int it = 0; it < 4; it++) {
            int f   = tid + it * 256;
            int r   = f >> 3;
            int kc4 = (f & 7) << 2;
            int grow = brow * 128 + r;
            va[it] = f4_zero();
            if (grow < M) va[it] = *(const float4*)(A + (size_t)grow * K + k0 + kc4);
        }
#pragma unroll
        for (int it = 0; it < 4; it++) {
            int f  = tid + it * 256;
            int kr = f >> 5;
            int c4 = (f & 31) << 2;
            int gcol = bcol * 128 + c4;
            vb[it] = f4_zero();
            if (gcol + 3 < N) vb[it] = *(const float4*)(B + (size_t)(k0 + kr) * N + gcol);
            else if (gcol < N) {
                vb[it].x = B[(size_t)(k0 + kr) * N + gcol];
                if (gcol + 1 < N) vb[it].y = B[(size_t)(k0 + kr) * N + gcol + 1];
                if (gcol + 2 < N) vb[it].z = B[(size_t)(k0 + kr) * N + gcol + 2];
            }
        }
    };

    auto store_tiles = [&](int b) {
        float* Asb = smem + b * GEMM_TILE_FLOATS;
        float* Bsb = smem + (2 + b) * GEMM_TILE_FLOATS;
#pragma unroll
        for (int it = 0; it < 4; it++) {
            int f   = tid + it * 256;
            int r   = f >> 3;
            int kc4 = (f & 7) << 2;
            Asb[aidx(kc4 + 0, r)] = __uint_as_float(f2tf32(va[it].x));
            Asb[aidx(kc4 + 1, r)] = __uint_as_float(f2tf32(va[it].y));
            Asb[aidx(kc4 + 2, r)] = __uint_as_float(f2tf32(va[it].z));
            Asb[aidx(kc4 + 3, r)] = __uint_as_float(f2tf32(va[it].w));
        }
#pragma unroll
        for (int it = 0; it < 4; it++) {
            int f  = tid + it * 256;
            int kr = f >> 5;
            int c4 = (f & 31) << 2;
            float4 w;
            w.x = __uint_as_float(f2tf32(vb[it].x));
            w.y = __uint_as_float(f2tf32(vb[it].y));
            w.z = __uint_as_float(f2tf32(vb[it].z));
            w.w = __uint_as_float(f2tf32(vb[it].w));
            *(float4*)&Bsb[kr * SROW + c4] = w;
        }
    };

    const int nk = K >> 5;
    load_tiles(0);
    store_tiles(0);
    __syncthreads();

    for (int tk = 0; tk < nk; tk++) {
        const int cur = tk & 1;
        if (tk + 1 < nk) load_tiles((tk + 1) << 5);

        const float* Asb = smem + cur * GEMM_TILE_FLOATS;
        const float* Bsb = smem + (2 + cur) * GEMM_TILE_FLOATS;
#pragma unroll
        for (int ks = 0; ks < 4; ks++) {
            const int kk = ks * 8;
            uint32_t af[4][4], bf[4][2];
#pragma unroll
            for (int im = 0; im < 4; im++) {
                int m0 = wm * 64 + im * 16;
                af[im][0] = __float_as_uint(Asb[aidx(kk + tig,     m0 + g    )]);
                af[im][1] = __float_as_uint(Asb[aidx(kk + tig,     m0 + g + 8)]);
                af[im][2] = __float_as_uint(Asb[aidx(kk + tig + 4, m0 + g    )]);
                af[im][3] = __float_as_uint(Asb[aidx(kk + tig + 4, m0 + g + 8)]);
            }
#pragma unroll
            for (int in = 0; in < 4; in++) {
                int n0 = wn * 32 + in * 8;
                bf[in][0] = __float_as_uint(Bsb[(kk + tig    ) * SROW + n0 + g]);
                bf[in][1] = __float_as_uint(Bsb[(kk + tig + 4) * SROW + n0 + g]);
            }
#pragma unroll
            for (int im = 0; im < 4; im++)
#pragma unroll
                for (int in = 0; in < 4; in++) {
                    asm volatile(
                        "mma.sync.aligned.m16n8k8.row.col.f32.tf32.tf32.f32 "
                        "{%0,%1,%2,%3}, {%4,%5,%6,%7}, {%8,%9}, {%0,%1,%2,%3};\n"
                        : "+f"(acc[im][in][0]), "+f"(acc[im][in][1]),
                          "+f"(acc[im][in][2]), "+f"(acc[im][in][3])
                        : "r"(af[im][0]), "r"(af[im][1]), "r"(af[im][2]), "r"(af[im][3]),
                          "r"(bf[in][0]), "r"(bf[in][1]));
                }
        }

        if (tk + 1 < nk) store_tiles(1 - cur);
        __syncthreads();
    }

    // --- epilogue ---
#pragma unroll
    for (int im = 0; im < 4; im++) {
        int r0 = brow * 128 + wm * 64 + im * 16 + g;
#pragma unroll
        for (int in = 0; in < 4; in++) {
            int c0 = bcol * 128 + wn * 32 + in * 8 + tig * 2;
            if (c0 >= N) continue;
            float b0v = 0.f, b1v = 0.f;
            if (BIAS) { b0v = bias[c0]; if (c0 + 1 < N) b1v = bias[c0 + 1]; }
            if (r0 < M) {
                float v0 = acc[im][in][0] + b0v;
                float v1 = acc[im][in][1] + b1v;
                if (RELU) { v0 = fmaxf(v0, 0.f); v1 = fmaxf(v1, 0.f); }
                C[(size_t)r0 * N + c0] = v0;
                if (c0 + 1 < N) C[(size_t)r0 * N + c0 + 1] = v1;
            }
            if (r0 + 8 < M) {
                float v2 = acc[im][in][2] + b0v;
                float v3 = acc[im][in][3] + b1v;
                if (RELU) { v2 = fmaxf(v2, 0.f); v3 = fmaxf(v3, 0.f); }
                C[(size_t)(r0 + 8) * N + c0] = v2;
                if (c0 + 1 < N) C[(size_t)(r0 + 8) * N + c0 + 1] = v3;
            }
        }
    }
}

// ---------------- aggregation (warp per node), templated width -------------
// out[i] = (opt relu/bias)( b + dinv[i]^2 * t[i] + sum_e w_e * t[col_e] )
template <int VEC, bool BIASRELU>   // VEC = WIDTH/128 (float4 per lane)
__global__ void __launch_bounds__(256) agg_kernel(
    const float* __restrict__ t, float* __restrict__ out, const float* __restrict__ bias)
{
    const int WIDTH = VEC * 128;
    int wrp = (blockIdx.x * blockDim.x + threadIdx.x) >> 5;
    int lane = threadIdx.x & 31;
    if (wrp >= N_NODES) return;
    const int i = wrp;

    const float4* rowi = (const float4*)(t + (size_t)i * WIDTH);
    float di = g_dinv[i];
    float ws = di * di;
    float4 acc[VEC];
#pragma unroll
    for (int v = 0; v < VEC; v++) {
        acc[v] = f4_zero();
        f4_fma(ws, rowi[lane + 32 * v], acc[v]);
    }
    int e0 = g_rowptr[i], e1 = g_rowptr[i + 1];
    for (int e = e0; e < e1; e++) {
        int   c  = g_col[e];
        float we = g_w[e];
        const float4* rowc = (const float4*)(t + (size_t)c * WIDTH);
#pragma unroll
        for (int v = 0; v < VEC; v++)
            f4_fma(we, rowc[lane + 32 * v], acc[v]);
    }
    float4* dstp = (float4*)(out + (size_t)i * WIDTH);
#pragma unroll
    for (int v = 0; v < VEC; v++) {
        if (BIASRELU) {
            float4 b = ((const float4*)bias)[lane + 32 * v];
            acc[v].x = fmaxf(acc[v].x + b.x, 0.f);
            acc[v].y = fmaxf(acc[v].y + b.y, 0.f);
            acc[v].z = fmaxf(acc[v].z + b.z, 0.f);
            acc[v].w = fmaxf(acc[v].w + b.w, 0.f);
        }
        dstp[lane + 32 * v] = acc[v];
    }
}

// ---------------- mean pool per graph (batch is sorted, int32) ----------------
__device__ __forceinline__ int lower_bound_i(const int* a, int n, int key) {
    int lo = 0, hi = n;
    while (lo < hi) {
        int mid = (lo + hi) >> 1;
        if (a[mid] < key) lo = mid + 1; else hi = mid;
    }
    return lo;
}

__global__ void __launch_bounds__(256) pool_kernel(
    const float* __restrict__ h, const int* __restrict__ batch)
{
    int g = blockIdx.x;
    int lo = lower_bound_i(batch, N_NODES, g);
    int hi = lower_bound_i(batch, N_NODES, g + 1);
    int cnt = hi - lo;
    int f = threadIdx.x;
    float acc = 0.f;
    for (int i = lo; i < hi; i++)
        acc += h[(size_t)i * HID + f];
    g_pool[(size_t)g * HID + f] = acc / fmaxf((float)cnt, 1.0f);
}

// ---------------- launch ----------------
extern "C" void kernel_launch(void* const* d_in, const int* in_sizes, int n_in,
                              void* d_out, int out_size)
{
    const float* x    = (const float*)d_in[0];
    const int*   ei   = (const int*)d_in[1];     // int32 (JAX x64 disabled)
    const int*   batc = (const int*)d_in[2];     // int32
    const float *W1 = (const float*)d_in[3],  *b1 = (const float*)d_in[4];
    const float *W2 = (const float*)d_in[5],  *b2 = (const float*)d_in[6];
    const float *W3 = (const float*)d_in[7],  *b3 = (const float*)d_in[8];
    const float *Wf1 = (const float*)d_in[9], *bf1 = (const float*)d_in[10];
    const float *Wf2 = (const float*)d_in[11], *bf2 = (const float*)d_in[12];
    float* out = (float*)d_out;

    const int* src = ei;
    const int* dst = ei + N_EDGES;

    float *t_buf, *h_buf, *ax_buf, *pool_buf, *fc1_buf;
    cudaGetSymbolAddress((void**)&t_buf, g_t);
    cudaGetSymbolAddress((void**)&h_buf, g_h);
    cudaGetSymbolAddress((void**)&ax_buf, g_ax);
    cudaGetSymbolAddress((void**)&pool_buf, g_pool);
    cudaGetSymbolAddress((void**)&fc1_buf, g_fc1);

    cudaFuncSetAttribute(gemm_tf32_kernel<false, false>, cudaFuncAttributeMaxDynamicSharedMemorySize, GEMM_SMEM_BYTES);
    cudaFuncSetAttribute(gemm_tf32_kernel<true, true>,   cudaFuncAttributeMaxDynamicSharedMemorySize, GEMM_SMEM_BYTES);
    cudaFuncSetAttribute(gemm_tf32_kernel<true, false>,  cudaFuncAttributeMaxDynamicSharedMemorySize, GEMM_SMEM_BYTES);

    // --- graph preprocessing ---
    k_init_deg<<<(N_NODES + 255) / 256, 256>>>();
    k_count<<<(N_EDGES + 255) / 256, 256>>>(dst);
    k_dinv_bsum<<<SCAN_NB, 256>>>();
    k_bscan<<<1, 256>>>();
    k_scatter<<<SCAN_NB, 256>>>();
    k_fill<<<(N_EDGES + 255) / 256, 256>>>(src, dst);

    const int aggBlocks = (N_NODES * 32 + 255) / 256;
    dim3 gridN((N_NODES + 127) / 128, 2);

    // --- layer 1: ax = A_norm @ x (width 128), h = relu(ax @ W1 + b1) ---
    agg_kernel<1, false><<<aggBlocks, 256>>>(x, ax_buf, nullptr);
    gemm_tf32_kernel<true, true><<<gridN, 256, GEMM_SMEM_BYTES>>>(ax_buf, W1, b1, h_buf, N_NODES, HID, 128);
    // --- layer 2: t = h @ W2 ; h = relu(A_norm @ t + b2) ---
    gemm_tf32_kernel<false, false><<<gridN, 256, GEMM_SMEM_BYTES>>>(h_buf, W2, nullptr, t_buf, N_NODES, HID, HID);
    agg_kernel<2, true><<<aggBlocks, 256>>>(t_buf, h_buf, b2);
    // --- layer 3 ---
    gemm_tf32_kernel<false, false><<<gridN, 256, GEMM_SMEM_BYTES>>>(h_buf, W3, nullptr, t_buf, N_NODES, HID, HID);
    agg_kernel<2, true><<<aggBlocks, 256>>>(t_buf, h_buf, b3);

    // --- mean pool ---
    pool_kernel<<<N_GRAPHS, 256>>>(h_buf, batc);

    // --- MLP head ---
    dim3 gridM((N_GRAPHS + 127) / 128, 1);
    gemm_tf32_kernel<true, true ><<<gridM, 256, GEMM_SMEM_BYTES>>>(pool_buf, Wf1, bf1, fc1_buf, N_GRAPHS, 128, HID);
    gemm_tf32_kernel<true, false><<<gridM, 256, GEMM_SMEM_BYTES>>>(fc1_buf, Wf2, bf2, out, N_GRAPHS, 32, 128);
}

// round 8
// speedup vs baseline: 2.5029x; 1.2124x over previous
#include <cuda_runtime.h>
#include <cuda_bf16.h>
#include <math.h>
#include <stdint.h>

#define N_NODES 50000
#define N_EDGES 300000
#define N_GRAPHS 2048
#define HID 256
#define SCAN_NB ((N_NODES + 255) / 256)   // 196

// ---------------- scratch (static __device__, no allocation) ----------------
__device__ int   g_deg[N_NODES];
__device__ float g_dinv[N_NODES];
__device__ int   g_rowptr[N_NODES + 1];
__device__ int   g_cursor[N_NODES];
__device__ int   g_col[N_EDGES];
__device__ float g_w[N_EDGES];
__device__ int   g_bsum[256];
__device__ int   g_boff[256];
__device__ float g_t[(size_t)N_NODES * HID];
__device__ float g_h[(size_t)N_NODES * HID];
__device__ float g_xc[(size_t)N_NODES * 128];   // tf32-rounded copy of x
__device__ float g_pool[(size_t)N_GRAPHS * HID];
__device__ float g_fc1[(size_t)N_GRAPHS * 128];
__device__ float g_w1t[256 * 128];   // W1^T [n][k], tf32-rounded
__device__ float g_w2t[256 * 256];
__device__ float g_w3t[256 * 256];

// ---------------- small helpers ----------------
__device__ __forceinline__ float4 f4_zero() { return make_float4(0.f, 0.f, 0.f, 0.f); }
__device__ __forceinline__ void f4_fma(float s, const float4& a, float4& acc) {
    acc.x = fmaf(s, a.x, acc.x); acc.y = fmaf(s, a.y, acc.y);
    acc.z = fmaf(s, a.z, acc.z); acc.w = fmaf(s, a.w, acc.w);
}
__device__ __forceinline__ uint32_t f2tf32(float f) {
    uint32_t r;
    asm("cvt.rna.tf32.f32 %0, %1;" : "=r"(r) : "f"(f));
    return r;
}
__device__ __forceinline__ float tf32f(float f) { return __uint_as_float(f2tf32(f)); }
__device__ __forceinline__ uint32_t smem_u32(const void* p) {
    uint32_t a;
    asm("{ .reg .u64 t; cvta.to.shared.u64 t, %1; cvt.u32.u64 %0, t; }" : "=r"(a) : "l"(p));
    return a;
}
__device__ __forceinline__ void cp16(uint32_t dst, const void* src, bool pred) {
    uint32_t sz = pred ? 16u : 0u;
    asm volatile("cp.async.cg.shared.global [%0], [%1], 16, %2;" :: "r"(dst), "l"(src), "r"(sz) : "memory");
}
#define CP_COMMIT() asm volatile("cp.async.commit_group;" ::: "memory")
#define CP_WAIT1()  asm volatile("cp.async.wait_group 1;" ::: "memory")

// ---------------- graph preprocessing ----------------
__global__ void k_init_deg() {
    int i = blockIdx.x * blockDim.x + threadIdx.x;
    if (i < N_NODES) g_deg[i] = 1;
}
__global__ void k_count(const int* __restrict__ dst) {
    int e = blockIdx.x * blockDim.x + threadIdx.x;
    if (e < N_EDGES) atomicAdd(&g_deg[dst[e]], 1);
}
__global__ void __launch_bounds__(256) k_dinv_bsum() {
    __shared__ int s_w[8];
    int idx = blockIdx.x * 256 + threadIdx.x;
    int lane = threadIdx.x & 31, warp = threadIdx.x >> 5;
    int v = 0;
    if (idx < N_NODES) {
        int d = g_deg[idx];
        g_dinv[idx] = rsqrtf((float)d);
        v = d - 1;
    }
    int s = v;
#pragma unroll
    for (int off = 16; off > 0; off >>= 1) s += __shfl_down_sync(0xffffffffu, s, off);
    if (lane == 0) s_w[warp] = s;
    __syncthreads();
    if (threadIdx.x == 0) {
        int t = 0;
#pragma unroll
        for (int w = 0; w < 8; w++) t += s_w[w];
        g_bsum[blockIdx.x] = t;
    }
}
__global__ void __launch_bounds__(256) k_bscan() {
    __shared__ int s_w[8];
    int t = threadIdx.x;
    int lane = t & 31, warp = t >> 5;
    int v = (t < SCAN_NB) ? g_bsum[t] : 0;
    int incl = v;
#pragma unroll
    for (int off = 1; off < 32; off <<= 1) {
        int u = __shfl_up_sync(0xffffffffu, incl, off);
        if (lane >= off) incl += u;
    }
    if (lane == 31) s_w[warp] = incl;
    __syncthreads();
    if (warp == 0 && lane < 8) {
        int u = s_w[lane];
        int wi = u;
#pragma unroll
        for (int off = 1; off < 8; off <<= 1) {
            int z = __shfl_up_sync(0xffu, wi, off);
            if (lane >= off) wi += z;
        }
        s_w[lane] = wi - u;
        if (lane == 7) g_rowptr[N_NODES] = wi;
    }
    __syncthreads();
    if (t < SCAN_NB) g_boff[t] = s_w[warp] + incl - v;
}
__global__ void __launch_bounds__(256) k_scatter() {
    __shared__ int s_w[8];
    int idx = blockIdx.x * 256 + threadIdx.x;
    int lane = threadIdx.x & 31, warp = threadIdx.x >> 5;
    int v = (idx < N_NODES) ? (g_deg[idx] - 1) : 0;
    int incl = v;
#pragma unroll
    for (int off = 1; off < 32; off <<= 1) {
        int u = __shfl_up_sync(0xffffffffu, incl, off);
        if (lane >= off) incl += u;
    }
    if (lane == 31) s_w[warp] = incl;
    __syncthreads();
    if (warp == 0 && lane < 8) {
        int u = s_w[lane];
        int wi = u;
#pragma unroll
        for (int off = 1; off < 8; off <<= 1) {
            int z = __shfl_up_sync(0xffu, wi, off);
            if (lane >= off) wi += z;
        }
        s_w[lane] = wi - u;
    }
    __syncthreads();
    if (idx < N_NODES) {
        int p = g_boff[blockIdx.x] + s_w[warp] + incl - v;
        g_rowptr[idx] = p;
        g_cursor[idx] = p;
    }
}
__global__ void k_fill(const int* __restrict__ src, const int* __restrict__ dst) {
    int e = blockIdx.x * blockDim.x + threadIdx.x;
    if (e < N_EDGES) {
        int s = src[e], d = dst[e];
        int pos = atomicAdd(&g_cursor[d], 1);
        g_col[pos] = s;
        g_w[pos]   = g_dinv[s] * g_dinv[d];
    }
}

// ---------------- tf32-rounded copy of x ----------------
__global__ void k_cvtx(const float* __restrict__ x, float* __restrict__ xc) {
    int i = blockIdx.x * blockDim.x + threadIdx.x;
    const int n4 = N_NODES * 128 / 4;
    if (i < n4) {
        float4 v = ((const float4*)x)[i];
        float4 w;
        w.x = tf32f(v.x); w.y = tf32f(v.y); w.z = tf32f(v.z); w.w = tf32f(v.w);
        ((float4*)xc)[i] = w;
    }
}

// ---------------- weight transpose + cvt: Wt[n][k] = tf32(W[k][n]) ---------
__global__ void k_transpose(const float* __restrict__ W, float* __restrict__ Wt, int K, int N) {
    __shared__ float t[32][33];
    int kb = blockIdx.x * 32, nb = blockIdx.y * 32;
    int tx = threadIdx.x, ty = threadIdx.y;   // 32 x 8
#pragma unroll
    for (int j = 0; j < 32; j += 8) {
        int k = kb + ty + j, n = nb + tx;
        if (k < K && n < N) t[ty + j][tx] = W[(size_t)k * N + n];
    }
    __syncthreads();
#pragma unroll
    for (int j = 0; j < 32; j += 8) {
        int n = nb + ty + j, k = kb + tx;
        if (n < N && k < K) Wt[(size_t)n * K + k] = tf32f(t[tx][ty + j]);
    }
}

// ---------------- cp.async pipelined mma.sync tf32 GEMM --------------------
// C[M,256] = A[M,K] @ Bt^T   (A [m][k], Bt [n][k], both pre-tf32-rounded)
// BM=128, BN=256, BK=32, 512 threads = 16 warps, warp tile 64x32.
// Smem rows stride 36 floats -> all fragment LDS.32 conflict-free.
#define PROW 36
#define PSTAGE_A_FLOATS (128 * PROW)            // 4608
#define PSTAGE_B_FLOATS (256 * PROW)            // 9216
#define PSTAGE_FLOATS   (PSTAGE_A_FLOATS + PSTAGE_B_FLOATS)
#define PIPE_SMEM_BYTES (3 * PSTAGE_FLOATS * 4) // 165888

__global__ void __launch_bounds__(512, 1) gemm_pipe(
    const float* __restrict__ A, const float* __restrict__ Bt,
    float* __restrict__ C, int M, int K)
{
    extern __shared__ float ps[];
    const int tid  = threadIdx.x;
    const int lane = tid & 31;
    const int warp = tid >> 5;
    const int wm   = warp >> 3;          // 0..1 -> m = wm*64
    const int wn   = warp & 7;           // 0..7 -> n = wn*32
    const int g    = lane >> 2;
    const int tig  = lane & 3;
    const int mbase = blockIdx.x * 128;
    const uint32_t sbase = smem_u32(ps);

    float acc[4][4][4];
#pragma unroll
    for (int im = 0; im < 4; im++)
#pragma unroll
        for (int in = 0; in < 4; in++)
#pragma unroll
            for (int c = 0; c < 4; c++) acc[im][in][c] = 0.f;

    auto prefetch = [&](int tk, int s) {
        const int k0 = tk << 5;
        const uint32_t abuf = sbase + (uint32_t)s * PSTAGE_FLOATS * 4;
        const uint32_t bbuf = abuf + PSTAGE_A_FLOATS * 4;
#pragma unroll
        for (int it = 0; it < 2; it++) {     // A: 1024 16B chunks
            int c = tid + it * 512;
            int r = c >> 3, kc = (c & 7) << 2;
            int grow = mbase + r;
            cp16(abuf + (uint32_t)(r * PROW + kc) * 4,
                 A + (size_t)grow * K + k0 + kc, grow < M);
        }
#pragma unroll
        for (int it = 0; it < 4; it++) {     // B: 2048 16B chunks
            int c = tid + it * 512;
            int r = c >> 3, kc = (c & 7) << 2;
            cp16(bbuf + (uint32_t)(r * PROW + kc) * 4,
                 Bt + (size_t)r * K + k0 + kc, true);
        }
    };

    const int nk = K >> 5;
    prefetch(0, 0); CP_COMMIT();
    if (nk > 1) prefetch(1, 1);
    CP_COMMIT();

    for (int tk = 0; tk < nk; tk++) {
        CP_WAIT1();
        __syncthreads();
        const int s = tk % 3;
        if (tk + 2 < nk) prefetch(tk + 2, (tk + 2) % 3);
        CP_COMMIT();

        const float* Ab = ps + (size_t)s * PSTAGE_FLOATS;
        const float* Bb = Ab + PSTAGE_A_FLOATS;
#pragma unroll
        for (int ks = 0; ks < 4; ks++) {
            const int kk = ks * 8;
            uint32_t af[4][4], bf[4][2];
#pragma unroll
            for (int im = 0; im < 4; im++) {
                const float* ra = Ab + (wm * 64 + im * 16 + g) * PROW;
                const float* rb = ra + 8 * PROW;
                af[im][0] = __float_as_uint(ra[kk + tig]);
                af[im][1] = __float_as_uint(rb[kk + tig]);
                af[im][2] = __float_as_uint(ra[kk + tig + 4]);
                af[im][3] = __float_as_uint(rb[kk + tig + 4]);
            }
#pragma unroll
            for (int in = 0; in < 4; in++) {
                const float* rn = Bb + (wn * 32 + in * 8 + g) * PROW;
                bf[in][0] = __float_as_uint(rn[kk + tig]);
                bf[in][1] = __float_as_uint(rn[kk + tig + 4]);
            }
#pragma unroll
            for (int im = 0; im < 4; im++)
#pragma unroll
                for (int in = 0; in < 4; in++) {
                    asm volatile(
                        "mma.sync.aligned.m16n8k8.row.col.f32.tf32.tf32.f32 "
                        "{%0,%1,%2,%3}, {%4,%5,%6,%7}, {%8,%9}, {%0,%1,%2,%3};\n"
                        : "+f"(acc[im][in][0]), "+f"(acc[im][in][1]),
                          "+f"(acc[im][in][2]), "+f"(acc[im][in][3])
                        : "r"(af[im][0]), "r"(af[im][1]), "r"(af[im][2]), "r"(af[im][3]),
                          "r"(bf[in][0]), "r"(bf[in][1]));
                }
        }
    }

    // epilogue: raw fp32 (consumer does bias/relu/cvt)
#pragma unroll
    for (int im = 0; im < 4; im++) {
        int r0 = mbase + wm * 64 + im * 16 + g;
#pragma unroll
        for (int in = 0; in < 4; in++) {
            int c0 = wn * 32 + in * 8 + tig * 2;
            if (r0 < M)
                *(float2*)(C + (size_t)r0 * 256 + c0) = make_float2(acc[im][in][0], acc[im][in][1]);
            if (r0 + 8 < M)
                *(float2*)(C + (size_t)(r0 + 8) * 256 + c0) = make_float2(acc[im][in][2], acc[im][in][3]);
        }
    }
}

// ---------------- aggregation (warp per node): bias+relu+cvt ---------------
__global__ void __launch_bounds__(256) agg_kernel(
    const float* __restrict__ t, float* __restrict__ out, const float* __restrict__ bias)
{
    int wrp = (blockIdx.x * blockDim.x + threadIdx.x) >> 5;
    int lane = threadIdx.x & 31;
    if (wrp >= N_NODES) return;
    const int i = wrp;

    const float4* rowi = (const float4*)(t + (size_t)i * 256);
    float di = g_dinv[i];
    float ws = di * di;
    float4 acc0 = f4_zero(), acc1 = f4_zero();
    f4_fma(ws, rowi[lane], acc0);
    f4_fma(ws, rowi[lane + 32], acc1);
    int e0 = g_rowptr[i], e1 = g_rowptr[i + 1];
    for (int e = e0; e < e1; e++) {
        int   c  = g_col[e];
        float we = g_w[e];
        const float4* rowc = (const float4*)(t + (size_t)c * 256);
        f4_fma(we, rowc[lane], acc0);
        f4_fma(we, rowc[lane + 32], acc1);
    }
    float4 b0 = ((const float4*)bias)[lane];
    float4 b1 = ((const float4*)bias)[lane + 32];
    float4 o0, o1;
    o0.x = tf32f(fmaxf(acc0.x + b0.x, 0.f)); o0.y = tf32f(fmaxf(acc0.y + b0.y, 0.f));
    o0.z = tf32f(fmaxf(acc0.z + b0.z, 0.f)); o0.w = tf32f(fmaxf(acc0.w + b0.w, 0.f));
    o1.x = tf32f(fmaxf(acc1.x + b1.x, 0.f)); o1.y = tf32f(fmaxf(acc1.y + b1.y, 0.f));
    o1.z = tf32f(fmaxf(acc1.z + b1.z, 0.f)); o1.w = tf32f(fmaxf(acc1.w + b1.w, 0.f));
    float4* dstp = (float4*)(out + (size_t)i * 256);
    dstp[lane]      = o0;
    dstp[lane + 32] = o1;
}

// ---------------- mean pool ----------------
__device__ __forceinline__ int lower_bound_i(const int* a, int n, int key) {
    int lo = 0, hi = n;
    while (lo < hi) {
        int mid = (lo + hi) >> 1;
        if (a[mid] < key) lo = mid + 1; else hi = mid;
    }
    return lo;
}
__global__ void __launch_bounds__(256) pool_kernel(
    const float* __restrict__ h, const int* __restrict__ batch)
{
    int g = blockIdx.x;
    int lo = lower_bound_i(batch, N_NODES, g);
    int hi = lower_bound_i(batch, N_NODES, g + 1);
    int cnt = hi - lo;
    int f = threadIdx.x;
    float acc = 0.f;
    for (int i = lo; i < hi; i++)
        acc += h[(size_t)i * HID + f];
    g_pool[(size_t)g * HID + f] = acc / fmaxf((float)cnt, 1.0f);
}

// ---------------- mma.sync tf32 GEMM (MLP head) ----------------------------
#define SROW 136
#define GEMM_TILE_FLOATS (32 * SROW)
#define GEMM_SMEM_BYTES (4 * GEMM_TILE_FLOATS * 4)

__device__ __forceinline__ int aidx(int k, int m) {
    return k * SROW + (m ^ (((k >> 2) & 7) << 2));
}

template <bool BIAS, bool RELU>
__global__ void __launch_bounds__(256) gemm_tf32_kernel(
    const float* __restrict__ A, const float* __restrict__ B,
    const float* __restrict__ bias, float* __restrict__ C,
    int M, int N, int K)
{
    extern __shared__ float smem[];
    const int tid = threadIdx.x;
    const int lane = tid & 31;
    const int warp = tid >> 5;
    const int wm = warp >> 2, wn = warp & 3;
    const int g = lane >> 2, tig = lane & 3;
    const int brow = blockIdx.x, bcol = blockIdx.y;

    float acc[4][4][4];
#pragma unroll
    for (int im = 0; im < 4; im++)
#pragma unroll
        for (int in = 0; in < 4; in++)
#pragma unroll
            for (int c = 0; c < 4; c++) acc[im][in][c] = 0.f;

    float4 va[4], vb[4];
    auto load_tiles = [&](int k0) {
#pragma unroll
        for (int it = 0; it < 4; it++) {
            int f = tid + it * 256;
            int r = f >> 3, kc4 = (f & 7) << 2;
            int grow = brow * 128 + r;
            va[it] = f4_zero();
            if (grow < M) va[it] = *(const float4*)(A + (size_t)grow * K + k0 + kc4);
        }
#pragma unroll
        for (int it = 0; it < 4; it++) {
            int f = tid + it * 256;
            int kr = f >> 5, c4 = (f & 31) << 2;
            int gcol = bcol * 128 + c4;
            vb[it] = f4_zero();
            if (gcol + 3 < N) vb[it] = *(const float4*)(B + (size_t)(k0 + kr) * N + gcol);
            else if (gcol < N) {
                vb[it].x = B[(size_t)(k0 + kr) * N + gcol];
                if (gcol + 1 < N) vb[it].y = B[(size_t)(k0 + kr) * N + gcol + 1];
                if (gcol + 2 < N) vb[it].z = B[(size_t)(k0 + kr) * N + gcol + 2];
            }
        }
    };
    auto store_tiles = [&](int b) {
        float* Asb = smem + b * GEMM_TILE_FLOATS;
        float* Bsb = smem + (2 + b) * GEMM_TILE_FLOATS;
#pragma unroll
        for (int it = 0; it < 4; it++) {
            int f = tid + it * 256;
            int r = f >> 3, kc4 = (f & 7) << 2;
            Asb[aidx(kc4 + 0, r)] = tf32f(va[it].x);
            Asb[aidx(kc4 + 1, r)] = tf32f(va[it].y);
            Asb[aidx(kc4 + 2, r)] = tf32f(va[it].z);
            Asb[aidx(kc4 + 3, r)] = tf32f(va[it].w);
        }
#pragma unroll
        for (int it = 0; it < 4; it++) {
            int f = tid + it * 256;
            int kr = f >> 5, c4 = (f & 31) << 2;
            float4 w;
            w.x = tf32f(vb[it].x); w.y = tf32f(vb[it].y);
            w.z = tf32f(vb[it].z); w.w = tf32f(vb[it].w);
            *(float4*)&Bsb[kr * SROW + c4] = w;
        }
    };

    const int nk = K >> 5;
    load_tiles(0);
    store_tiles(0);
    __syncthreads();

    for (int tk = 0; tk < nk; tk++) {
        const int cur = tk & 1;
        if (tk + 1 < nk) load_tiles((tk + 1) << 5);
        const float* Asb = smem + cur * GEMM_TILE_FLOATS;
        const float* Bsb = smem + (2 + cur) * GEMM_TILE_FLOATS;
#pragma unroll
        for (int ks = 0; ks < 4; ks++) {
            const int kk = ks * 8;
            uint32_t af[4][4], bf[4][2];
#pragma unroll
            for (int im = 0; im < 4; im++) {
                int m0 = wm * 64 + im * 16;
                af[im][0] = __float_as_uint(Asb[aidx(kk + tig,     m0 + g    )]);
                af[im][1] = __float_as_uint(Asb[aidx(kk + tig,     m0 + g + 8)]);
                af[im][2] = __float_as_uint(Asb[aidx(kk + tig + 4, m0 + g    )]);
                af[im][3] = __float_as_uint(Asb[aidx(kk + tig + 4, m0 + g + 8)]);
            }
#pragma unroll
            for (int in = 0; in < 4; in++) {
                int n0 = wn * 32 + in * 8;
                bf[in][0] = __float_as_uint(Bsb[(kk + tig    ) * SROW + n0 + g]);
                bf[in][1] = __float_as_uint(Bsb[(kk + tig + 4) * SROW + n0 + g]);
            }
#pragma unroll
            for (int im = 0; im < 4; im++)
#pragma unroll
                for (int in = 0; in < 4; in++) {
                    asm volatile(
                        "mma.sync.aligned.m16n8k8.row.col.f32.tf32.tf32.f32 "
                        "{%0,%1,%2,%3}, {%4,%5,%6,%7}, {%8,%9}, {%0,%1,%2,%3};\n"
                        : "+f"(acc[im][in][0]), "+f"(acc[im][in][1]),
                          "+f"(acc[im][in][2]), "+f"(acc[im][in][3])
                        : "r"(af[im][0]), "r"(af[im][1]), "r"(af[im][2]), "r"(af[im][3]),
                          "r"(bf[in][0]), "r"(bf[in][1]));
                }
        }
        if (tk + 1 < nk) store_tiles(1 - cur);
        __syncthreads();
    }

#pragma unroll
    for (int im = 0; im < 4; im++) {
        int r0 = brow * 128 + wm * 64 + im * 16 + g;
#pragma unroll
        for (int in = 0; in < 4; in++) {
            int c0 = bcol * 128 + wn * 32 + in * 8 + tig * 2;
            if (c0 >= N) continue;
            float b0v = 0.f, b1v = 0.f;
            if (BIAS) { b0v = bias[c0]; if (c0 + 1 < N) b1v = bias[c0 + 1]; }
            if (r0 < M) {
                float v0 = acc[im][in][0] + b0v;
                float v1 = acc[im][in][1] + b1v;
                if (RELU) { v0 = fmaxf(v0, 0.f); v1 = fmaxf(v1, 0.f); }
                C[(size_t)r0 * N + c0] = v0;
                if (c0 + 1 < N) C[(size_t)r0 * N + c0 + 1] = v1;
            }
            if (r0 + 8 < M) {
                float v2 = acc[im][in][2] + b0v;
                float v3 = acc[im][in][3] + b1v;
                if (RELU) { v2 = fmaxf(v2, 0.f); v3 = fmaxf(v3, 0.f); }
                C[(size_t)(r0 + 8) * N + c0] = v2;
                if (c0 + 1 < N) C[(size_t)(r0 + 8) * N + c0 + 1] = v3;
            }
        }
    }
}

// ---------------- launch ----------------
extern "C" void kernel_launch(void* const* d_in, const int* in_sizes, int n_in,
                              void* d_out, int out_size)
{
    const float* x    = (const float*)d_in[0];
    const int*   ei   = (const int*)d_in[1];
    const int*   batc = (const int*)d_in[2];
    const float *W1 = (const float*)d_in[3],  *b1 = (const float*)d_in[4];
    const float *W2 = (const float*)d_in[5],  *b2 = (const float*)d_in[6];
    const float *W3 = (const float*)d_in[7],  *b3 = (const float*)d_in[8];
    const float *Wf1 = (const float*)d_in[9], *bf1 = (const float*)d_in[10];
    const float *Wf2 = (const float*)d_in[11], *bf2 = (const float*)d_in[12];
    float* out = (float*)d_out;

    const int* src = ei;
    const int* dst = ei + N_EDGES;

    float *t_buf, *h_buf, *xc_buf, *pool_buf, *fc1_buf, *w1t, *w2t, *w3t;
    cudaGetSymbolAddress((void**)&t_buf, g_t);
    cudaGetSymbolAddress((void**)&h_buf, g_h);
    cudaGetSymbolAddress((void**)&xc_buf, g_xc);
    cudaGetSymbolAddress((void**)&pool_buf, g_pool);
    cudaGetSymbolAddress((void**)&fc1_buf, g_fc1);
    cudaGetSymbolAddress((void**)&w1t, g_w1t);
    cudaGetSymbolAddress((void**)&w2t, g_w2t);
    cudaGetSymbolAddress((void**)&w3t, g_w3t);

    cudaFuncSetAttribute(gemm_pipe, cudaFuncAttributeMaxDynamicSharedMemorySize, PIPE_SMEM_BYTES);
    cudaFuncSetAttribute(gemm_tf32_kernel<true, true>,  cudaFuncAttributeMaxDynamicSharedMemorySize, GEMM_SMEM_BYTES);
    cudaFuncSetAttribute(gemm_tf32_kernel<true, false>, cudaFuncAttributeMaxDynamicSharedMemorySize, GEMM_SMEM_BYTES);

    const int aggBlocks = (N_NODES * 32 + 255) / 256;
    const int tcGrid = (N_NODES + 127) / 128;   // 391

    // slots 1-3: prerequisites of the big GEMM; slot 4: gemm_pipe (ncu target)
    k_cvtx<<<(N_NODES * 128 / 4 + 255) / 256, 256>>>(x, xc_buf);               // 1
    k_transpose<<<dim3(4, 8), dim3(32, 8)>>>(W1, w1t, 128, 256);               // 2
    k_init_deg<<<(N_NODES + 255) / 256, 256>>>();                              // 3
    gemm_pipe<<<tcGrid, 512, PIPE_SMEM_BYTES>>>(xc_buf, w1t, t_buf, N_NODES, 128); // 4

    // rest of preprocessing
    k_count<<<(N_EDGES + 255) / 256, 256>>>(dst);                              // 5
    k_dinv_bsum<<<SCAN_NB, 256>>>();                                           // 6
    k_bscan<<<1, 256>>>();                                                     // 7
    k_scatter<<<SCAN_NB, 256>>>();                                             // 8
    k_fill<<<(N_EDGES + 255) / 256, 256>>>(src, dst);                          // 9
    k_transpose<<<dim3(8, 8), dim3(32, 8)>>>(W2, w2t, 256, 256);               // 10
    k_transpose<<<dim3(8, 8), dim3(32, 8)>>>(W3, w3t, 256, 256);               // 11

    // layer 1 finish: h = cvt(relu(agg(t) + b1))
    agg_kernel<<<aggBlocks, 256>>>(t_buf, h_buf, b1);                          // 12
    // layer 2
    gemm_pipe<<<tcGrid, 512, PIPE_SMEM_BYTES>>>(h_buf, w2t, t_buf, N_NODES, 256); // 13
    agg_kernel<<<aggBlocks, 256>>>(t_buf, h_buf, b2);                          // 14
    // layer 3
    gemm_pipe<<<tcGrid, 512, PIPE_SMEM_BYTES>>>(h_buf, w3t, t_buf, N_NODES, 256); // 15
    agg_kernel<<<aggBlocks, 256>>>(t_buf, h_buf, b3);                          // 16

    // mean pool
    pool_kernel<<<N_GRAPHS, 256>>>(h_buf, batc);                               // 17

    // MLP head
    dim3 gridM((N_GRAPHS + 127) / 128, 1);
    gemm_tf32_kernel<true, true ><<<gridM, 256, GEMM_SMEM_BYTES>>>(pool_buf, Wf1, bf1, fc1_buf, N_GRAPHS, 128, HID);
    gemm_tf32_kernel<true, false><<<gridM, 256, GEMM_SMEM_BYTES>>>(fc1_buf, Wf2, bf2, out, N_GRAPHS, 32, 128);
}

// round 9
// speedup vs baseline: 2.6656x; 1.0650x over previous
#include <cuda_runtime.h>
#include <cuda_bf16.h>
#include <math.h>
#include <stdint.h>

#define N_NODES 50000
#define N_EDGES 300000
#define N_GRAPHS 2048
#define HID 256
#define SCAN_NB ((N_NODES + 255) / 256)   // 196

// ---------------- scratch (static __device__, no allocation) ----------------
__device__ int   g_deg[N_NODES];
__device__ float g_dinv[N_NODES];
__device__ int   g_rowptr[N_NODES + 1];
__device__ int   g_cursor[N_NODES];
__device__ int   g_col[N_EDGES];
__device__ float g_w[N_EDGES];
__device__ int   g_bsum[256];
__device__ int   g_boff[256];
__device__ float g_t[(size_t)N_NODES * HID];
__device__ float g_h[(size_t)N_NODES * HID];
__device__ float g_ax[(size_t)N_NODES * 128];   // layer-1 aggregated x (tf32-rounded)
__device__ float g_pool[(size_t)N_GRAPHS * HID];
__device__ float g_fc1[(size_t)N_GRAPHS * 128];
__device__ float g_w1t[256 * 128];   // W1^T [n][k], tf32-rounded
__device__ float g_w2t[256 * 256];
__device__ float g_w3t[256 * 256];

// ---------------- small helpers ----------------
__device__ __forceinline__ float4 f4_zero() { return make_float4(0.f, 0.f, 0.f, 0.f); }
__device__ __forceinline__ void f4_fma(float s, const float4& a, float4& acc) {
    acc.x = fmaf(s, a.x, acc.x); acc.y = fmaf(s, a.y, acc.y);
    acc.z = fmaf(s, a.z, acc.z); acc.w = fmaf(s, a.w, acc.w);
}
__device__ __forceinline__ uint32_t f2tf32(float f) {
    uint32_t r;
    asm("cvt.rna.tf32.f32 %0, %1;" : "=r"(r) : "f"(f));
    return r;
}
__device__ __forceinline__ float tf32f(float f) { return __uint_as_float(f2tf32(f)); }
__device__ __forceinline__ uint32_t smem_u32(const void* p) {
    uint32_t a;
    asm("{ .reg .u64 t; cvta.to.shared.u64 t, %1; cvt.u32.u64 %0, t; }" : "=r"(a) : "l"(p));
    return a;
}
__device__ __forceinline__ void cp16(uint32_t dst, const void* src, bool pred) {
    uint32_t sz = pred ? 16u : 0u;
    asm volatile("cp.async.cg.shared.global [%0], [%1], 16, %2;" :: "r"(dst), "l"(src), "r"(sz) : "memory");
}
#define CP_COMMIT() asm volatile("cp.async.commit_group;" ::: "memory")
#define CP_WAIT1()  asm volatile("cp.async.wait_group 1;" ::: "memory")

// ---------------- graph preprocessing ----------------
__global__ void k_init_deg() {
    int i = blockIdx.x * blockDim.x + threadIdx.x;
    if (i < N_NODES) g_deg[i] = 1;
}
__global__ void k_count(const int* __restrict__ dst) {
    int e = blockIdx.x * blockDim.x + threadIdx.x;
    if (e < N_EDGES) atomicAdd(&g_deg[dst[e]], 1);
}
__global__ void __launch_bounds__(256) k_dinv_bsum() {
    __shared__ int s_w[8];
    int idx = blockIdx.x * 256 + threadIdx.x;
    int lane = threadIdx.x & 31, warp = threadIdx.x >> 5;
    int v = 0;
    if (idx < N_NODES) {
        int d = g_deg[idx];
        g_dinv[idx] = rsqrtf((float)d);
        v = d - 1;
    }
    int s = v;
#pragma unroll
    for (int off = 16; off > 0; off >>= 1) s += __shfl_down_sync(0xffffffffu, s, off);
    if (lane == 0) s_w[warp] = s;
    __syncthreads();
    if (threadIdx.x == 0) {
        int t = 0;
#pragma unroll
        for (int w = 0; w < 8; w++) t += s_w[w];
        g_bsum[blockIdx.x] = t;
    }
}
__global__ void __launch_bounds__(256) k_bscan() {
    __shared__ int s_w[8];
    int t = threadIdx.x;
    int lane = t & 31, warp = t >> 5;
    int v = (t < SCAN_NB) ? g_bsum[t] : 0;
    int incl = v;
#pragma unroll
    for (int off = 1; off < 32; off <<= 1) {
        int u = __shfl_up_sync(0xffffffffu, incl, off);
        if (lane >= off) incl += u;
    }
    if (lane == 31) s_w[warp] = incl;
    __syncthreads();
    if (warp == 0 && lane < 8) {
        int u = s_w[lane];
        int wi = u;
#pragma unroll
        for (int off = 1; off < 8; off <<= 1) {
            int z = __shfl_up_sync(0xffu, wi, off);
            if (lane >= off) wi += z;
        }
        s_w[lane] = wi - u;
        if (lane == 7) g_rowptr[N_NODES] = wi;
    }
    __syncthreads();
    if (t < SCAN_NB) g_boff[t] = s_w[warp] + incl - v;
}
__global__ void __launch_bounds__(256) k_scatter() {
    __shared__ int s_w[8];
    int idx = blockIdx.x * 256 + threadIdx.x;
    int lane = threadIdx.x & 31, warp = threadIdx.x >> 5;
    int v = (idx < N_NODES) ? (g_deg[idx] - 1) : 0;
    int incl = v;
#pragma unroll
    for (int off = 1; off < 32; off <<= 1) {
        int u = __shfl_up_sync(0xffffffffu, incl, off);
        if (lane >= off) incl += u;
    }
    if (lane == 31) s_w[warp] = incl;
    __syncthreads();
    if (warp == 0 && lane < 8) {
        int u = s_w[lane];
        int wi = u;
#pragma unroll
        for (int off = 1; off < 8; off <<= 1) {
            int z = __shfl_up_sync(0xffu, wi, off);
            if (lane >= off) wi += z;
        }
        s_w[lane] = wi - u;
    }
    __syncthreads();
    if (idx < N_NODES) {
        int p = g_boff[blockIdx.x] + s_w[warp] + incl - v;
        g_rowptr[idx] = p;
        g_cursor[idx] = p;
    }
}
__global__ void k_fill(const int* __restrict__ src, const int* __restrict__ dst) {
    int e = blockIdx.x * blockDim.x + threadIdx.x;
    if (e < N_EDGES) {
        int s = src[e], d = dst[e];
        int pos = atomicAdd(&g_cursor[d], 1);
        g_col[pos] = s;
        g_w[pos]   = g_dinv[s] * g_dinv[d];
    }
}

// ---------------- weight transpose + cvt: Wt[n][k] = tf32(W[k][n]) ---------
__global__ void k_transpose(const float* __restrict__ W, float* __restrict__ Wt, int K, int N) {
    __shared__ float t[32][33];
    int kb = blockIdx.x * 32, nb = blockIdx.y * 32;
    int tx = threadIdx.x, ty = threadIdx.y;   // 32 x 8
#pragma unroll
    for (int j = 0; j < 32; j += 8) {
        int k = kb + ty + j, n = nb + tx;
        if (k < K && n < N) t[ty + j][tx] = W[(size_t)k * N + n];
    }
    __syncthreads();
#pragma unroll
    for (int j = 0; j < 32; j += 8) {
        int n = nb + ty + j, k = kb + tx;
        if (n < N && k < K) Wt[(size_t)n * K + k] = tf32f(t[tx][ty + j]);
    }
}

// ---------------- cp.async pipelined mma.sync tf32 GEMM --------------------
// C[M,256] = A[M,K] @ Bt^T (+bias,+relu,+cvt if BR)
// A [m][k], Bt [n][k], both pre-tf32-rounded.
// BM=128, BN=256, BK=32, 256 threads = 8 warps, warp tile 64x64.
// Smem rows stride 36 floats -> all fragment LDS.32 conflict-free.
#define PROW 36
#define PSTAGE_A_FLOATS (128 * PROW)            // 4608
#define PSTAGE_B_FLOATS (256 * PROW)            // 9216
#define PSTAGE_FLOATS   (PSTAGE_A_FLOATS + PSTAGE_B_FLOATS)
#define PIPE_SMEM_BYTES (3 * PSTAGE_FLOATS * 4) // 165888

template <bool BR>   // bias+relu+cvt epilogue
__global__ void __launch_bounds__(256, 1) gemm_pipe(
    const float* __restrict__ A, const float* __restrict__ Bt,
    const float* __restrict__ bias, float* __restrict__ C, int M, int K)
{
    extern __shared__ float ps[];
    const int tid  = threadIdx.x;
    const int lane = tid & 31;
    const int warp = tid >> 5;
    const int wm   = warp >> 2;          // 0..1 -> m = wm*64
    const int wn   = warp & 3;           // 0..3 -> n = wn*64
    const int g    = lane >> 2;
    const int tig  = lane & 3;
    const int mbase = blockIdx.x * 128;
    const uint32_t sbase = smem_u32(ps);

    float acc[4][8][4];
#pragma unroll
    for (int im = 0; im < 4; im++)
#pragma unroll
        for (int in = 0; in < 8; in++)
#pragma unroll
            for (int c = 0; c < 4; c++) acc[im][in][c] = 0.f;

    auto prefetch = [&](int tk, int s) {
        const int k0 = tk << 5;
        const uint32_t abuf = sbase + (uint32_t)s * PSTAGE_FLOATS * 4;
        const uint32_t bbuf = abuf + PSTAGE_A_FLOATS * 4;
#pragma unroll
        for (int it = 0; it < 4; it++) {     // A: 1024 16B chunks
            int c = tid + it * 256;
            int r = c >> 3, kc = (c & 7) << 2;
            int grow = mbase + r;
            cp16(abuf + (uint32_t)(r * PROW + kc) * 4,
                 A + (size_t)grow * K + k0 + kc, grow < M);
        }
#pragma unroll
        for (int it = 0; it < 8; it++) {     // B: 2048 16B chunks
            int c = tid + it * 256;
            int r = c >> 3, kc = (c & 7) << 2;
            cp16(bbuf + (uint32_t)(r * PROW + kc) * 4,
                 Bt + (size_t)r * K + k0 + kc, true);
        }
    };

    const int nk = K >> 5;
    prefetch(0, 0); CP_COMMIT();
    if (nk > 1) prefetch(1, 1);
    CP_COMMIT();

    for (int tk = 0; tk < nk; tk++) {
        CP_WAIT1();
        __syncthreads();
        const int s = tk % 3;
        if (tk + 2 < nk) prefetch(tk + 2, (tk + 2) % 3);
        CP_COMMIT();

        const float* Ab = ps + (size_t)s * PSTAGE_FLOATS;
        const float* Bb = Ab + PSTAGE_A_FLOATS;
#pragma unroll
        for (int ks = 0; ks < 4; ks++) {
            const int kk = ks * 8;
            uint32_t af[4][4], bf[8][2];
#pragma unroll
            for (int im = 0; im < 4; im++) {
                const float* ra = Ab + (wm * 64 + im * 16 + g) * PROW;
                const float* rb = ra + 8 * PROW;
                af[im][0] = __float_as_uint(ra[kk + tig]);
                af[im][1] = __float_as_uint(rb[kk + tig]);
                af[im][2] = __float_as_uint(ra[kk + tig + 4]);
                af[im][3] = __float_as_uint(rb[kk + tig + 4]);
            }
#pragma unroll
            for (int in = 0; in < 8; in++) {
                const float* rn = Bb + (wn * 64 + in * 8 + g) * PROW;
                bf[in][0] = __float_as_uint(rn[kk + tig]);
                bf[in][1] = __float_as_uint(rn[kk + tig + 4]);
            }
#pragma unroll
            for (int im = 0; im < 4; im++)
#pragma unroll
                for (int in = 0; in < 8; in++) {
                    asm volatile(
                        "mma.sync.aligned.m16n8k8.row.col.f32.tf32.tf32.f32 "
                        "{%0,%1,%2,%3}, {%4,%5,%6,%7}, {%8,%9}, {%0,%1,%2,%3};\n"
                        : "+f"(acc[im][in][0]), "+f"(acc[im][in][1]),
                          "+f"(acc[im][in][2]), "+f"(acc[im][in][3])
                        : "r"(af[im][0]), "r"(af[im][1]), "r"(af[im][2]), "r"(af[im][3]),
                          "r"(bf[in][0]), "r"(bf[in][1]));
                }
        }
    }

    // epilogue
#pragma unroll
    for (int im = 0; im < 4; im++) {
        int r0 = mbase + wm * 64 + im * 16 + g;
#pragma unroll
        for (int in = 0; in < 8; in++) {
            int c0 = wn * 64 + in * 8 + tig * 2;
            float v0 = acc[im][in][0], v1 = acc[im][in][1];
            float v2 = acc[im][in][2], v3 = acc[im][in][3];
            if (BR) {
                float b0 = bias[c0], b1 = bias[c0 + 1];
                v0 = tf32f(fmaxf(v0 + b0, 0.f)); v1 = tf32f(fmaxf(v1 + b1, 0.f));
                v2 = tf32f(fmaxf(v2 + b0, 0.f)); v3 = tf32f(fmaxf(v3 + b1, 0.f));
            }
            if (r0 < M)
                *(float2*)(C + (size_t)r0 * 256 + c0) = make_float2(v0, v1);
            if (r0 + 8 < M)
                *(float2*)(C + (size_t)(r0 + 8) * 256 + c0) = make_float2(v2, v3);
        }
    }
}

// ---------------- aggregation (warp per node), templated -------------------
// out[i] = POST( dinv[i]^2 * t[i] + sum_e w_e * t[col_e] )
// BIASRELU: POST = tf32(relu(. + bias)); else POST = tf32(.)
template <int VEC, bool BIASRELU>   // VEC = WIDTH/128
__global__ void __launch_bounds__(256) agg_kernel(
    const float* __restrict__ t, float* __restrict__ out, const float* __restrict__ bias)
{
    const int WIDTH = VEC * 128;
    int wrp = (blockIdx.x * blockDim.x + threadIdx.x) >> 5;
    int lane = threadIdx.x & 31;
    if (wrp >= N_NODES) return;
    const int i = wrp;

    const float4* rowi = (const float4*)(t + (size_t)i * WIDTH);
    float di = g_dinv[i];
    float ws = di * di;
    float4 acc[VEC];
#pragma unroll
    for (int v = 0; v < VEC; v++) {
        acc[v] = f4_zero();
        f4_fma(ws, rowi[lane + 32 * v], acc[v]);
    }
    int e0 = g_rowptr[i], e1 = g_rowptr[i + 1];
    for (int e = e0; e < e1; e++) {
        int   c  = g_col[e];
        float we = g_w[e];
        const float4* rowc = (const float4*)(t + (size_t)c * WIDTH);
#pragma unroll
        for (int v = 0; v < VEC; v++)
            f4_fma(we, rowc[lane + 32 * v], acc[v]);
    }
    float4* dstp = (float4*)(out + (size_t)i * WIDTH);
#pragma unroll
    for (int v = 0; v < VEC; v++) {
        float4 o;
        if (BIASRELU) {
            float4 b = ((const float4*)bias)[lane + 32 * v];
            o.x = tf32f(fmaxf(acc[v].x + b.x, 0.f));
            o.y = tf32f(fmaxf(acc[v].y + b.y, 0.f));
            o.z = tf32f(fmaxf(acc[v].z + b.z, 0.f));
            o.w = tf32f(fmaxf(acc[v].w + b.w, 0.f));
        } else {
            o.x = tf32f(acc[v].x); o.y = tf32f(acc[v].y);
            o.z = tf32f(acc[v].z); o.w = tf32f(acc[v].w);
        }
        dstp[lane + 32 * v] = o;
    }
}

// ---------------- mean pool ----------------
__device__ __forceinline__ int lower_bound_i(const int* a, int n, int key) {
    int lo = 0, hi = n;
    while (lo < hi) {
        int mid = (lo + hi) >> 1;
        if (a[mid] < key) lo = mid + 1; else hi = mid;
    }
    return lo;
}
__global__ void __launch_bounds__(256) pool_kernel(
    const float* __restrict__ h, const int* __restrict__ batch)
{
    int g = blockIdx.x;
    int lo = lower_bound_i(batch, N_NODES, g);
    int hi = lower_bound_i(batch, N_NODES, g + 1);
    int cnt = hi - lo;
    int f = threadIdx.x;
    float acc = 0.f;
    for (int i = lo; i < hi; i++)
        acc += h[(size_t)i * HID + f];
    g_pool[(size_t)g * HID + f] = acc / fmaxf((float)cnt, 1.0f);
}

// ---------------- mma.sync tf32 GEMM (MLP head) ----------------------------
#define SROW 136
#define GEMM_TILE_FLOATS (32 * SROW)
#define GEMM_SMEM_BYTES (4 * GEMM_TILE_FLOATS * 4)

__device__ __forceinline__ int aidx(int k, int m) {
    return k * SROW + (m ^ (((k >> 2) & 7) << 2));
}

template <bool BIAS, bool RELU>
__global__ void __launch_bounds__(256) gemm_tf32_kernel(
    const float* __restrict__ A, const float* __restrict__ B,
    const float* __restrict__ bias, float* __restrict__ C,
    int M, int N, int K)
{
    extern __shared__ float smem[];
    const int tid = threadIdx.x;
    const int lane = tid & 31;
    const int warp = tid >> 5;
    const int wm = warp >> 2, wn = warp & 3;
    const int g = lane >> 2, tig = lane & 3;
    const int brow = blockIdx.x, bcol = blockIdx.y;

    float acc[4][4][4];
#pragma unroll
    for (int im = 0; im < 4; im++)
#pragma unroll
        for (int in = 0; in < 4; in++)
#pragma unroll
            for (int c = 0; c < 4; c++) acc[im][in][c] = 0.f;

    float4 va[4], vb[4];
    auto load_tiles = [&](int k0) {
#pragma unroll
        for (int it = 0; it < 4; it++) {
            int f = tid + it * 256;
            int r = f >> 3, kc4 = (f & 7) << 2;
            int grow = brow * 128 + r;
            va[it] = f4_zero();
            if (grow < M) va[it] = *(const float4*)(A + (size_t)grow * K + k0 + kc4);
        }
#pragma unroll
        for (int it = 0; it < 4; it++) {
            int f = tid + it * 256;
            int kr = f >> 5, c4 = (f & 31) << 2;
            int gcol = bcol * 128 + c4;
            vb[it] = f4_zero();
            if (gcol + 3 < N) vb[it] = *(const float4*)(B + (size_t)(k0 + kr) * N + gcol);
            else if (gcol < N) {
                vb[it].x = B[(size_t)(k0 + kr) * N + gcol];
                if (gcol + 1 < N) vb[it].y = B[(size_t)(k0 + kr) * N + gcol + 1];
                if (gcol + 2 < N) vb[it].z = B[(size_t)(k0 + kr) * N + gcol + 2];
            }
        }
    };
    auto store_tiles = [&](int b) {
        float* Asb = smem + b * GEMM_TILE_FLOATS;
        float* Bsb = smem + (2 + b) * GEMM_TILE_FLOATS;
#pragma unroll
        for (int it = 0; it < 4; it++) {
            int f = tid + it * 256;
            int r = f >> 3, kc4 = (f & 7) << 2;
            Asb[aidx(kc4 + 0, r)] = tf32f(va[it].x);
            Asb[aidx(kc4 + 1, r)] = tf32f(va[it].y);
            Asb[aidx(kc4 + 2, r)] = tf32f(va[it].z);
            Asb[aidx(kc4 + 3, r)] = tf32f(va[it].w);
        }
#pragma unroll
        for (int it = 0; it < 4; it++) {
            int f = tid + it * 256;
            int kr = f >> 5, c4 = (f & 31) << 2;
            float4 w;
            w.x = tf32f(vb[it].x); w.y = tf32f(vb[it].y);
            w.z = tf32f(vb[it].z); w.w = tf32f(vb[it].w);
            *(float4*)&Bsb[kr * SROW + c4] = w;
        }
    };

    const int nk = K >> 5;
    load_tiles(0);
    store_tiles(0);
    __syncthreads();

    for (int tk = 0; tk < nk; tk++) {
        const int cur = tk & 1;
        if (tk + 1 < nk) load_tiles((tk + 1) << 5);
        const float* Asb = smem + cur * GEMM_TILE_FLOATS;
        const float* Bsb = smem + (2 + cur) * GEMM_TILE_FLOATS;
#pragma unroll
        for (int ks = 0; ks < 4; ks++) {
            const int kk = ks * 8;
            uint32_t af[4][4], bf[4][2];
#pragma unroll
            for (int im = 0; im < 4; im++) {
                int m0 = wm * 64 + im * 16;
                af[im][0] = __float_as_uint(Asb[aidx(kk + tig,     m0 + g    )]);
                af[im][1] = __float_as_uint(Asb[aidx(kk + tig,     m0 + g + 8)]);
                af[im][2] = __float_as_uint(Asb[aidx(kk + tig + 4, m0 + g    )]);
                af[im][3] = __float_as_uint(Asb[aidx(kk + tig + 4, m0 + g + 8)]);
            }
#pragma unroll
            for (int in = 0; in < 4; in++) {
                int n0 = wn * 32 + in * 8;
                bf[in][0] = __float_as_uint(Bsb[(kk + tig    ) * SROW + n0 + g]);
                bf[in][1] = __float_as_uint(Bsb[(kk + tig + 4) * SROW + n0 + g]);
            }
#pragma unroll
            for (int im = 0; im < 4; im++)
#pragma unroll
                for (int in = 0; in < 4; in++) {
                    asm volatile(
                        "mma.sync.aligned.m16n8k8.row.col.f32.tf32.tf32.f32 "
                        "{%0,%1,%2,%3}, {%4,%5,%6,%7}, {%8,%9}, {%0,%1,%2,%3};\n"
                        : "+f"(acc[im][in][0]), "+f"(acc[im][in][1]),
                          "+f"(acc[im][in][2]), "+f"(acc[im][in][3])
                        : "r"(af[im][0]), "r"(af[im][1]), "r"(af[im][2]), "r"(af[im][3]),
                          "r"(bf[in][0]), "r"(bf[in][1]));
                }
        }
        if (tk + 1 < nk) store_tiles(1 - cur);
        __syncthreads();
    }

#pragma unroll
    for (int im = 0; im < 4; im++) {
        int r0 = brow * 128 + wm * 64 + im * 16 + g;
#pragma unroll
        for (int in = 0; in < 4; in++) {
            int c0 = bcol * 128 + wn * 32 + in * 8 + tig * 2;
            if (c0 >= N) continue;
            float b0v = 0.f, b1v = 0.f;
            if (BIAS) { b0v = bias[c0]; if (c0 + 1 < N) b1v = bias[c0 + 1]; }
            if (r0 < M) {
                float v0 = acc[im][in][0] + b0v;
                float v1 = acc[im][in][1] + b1v;
                if (RELU) { v0 = fmaxf(v0, 0.f); v1 = fmaxf(v1, 0.f); }
                C[(size_t)r0 * N + c0] = v0;
                if (c0 + 1 < N) C[(size_t)r0 * N + c0 + 1] = v1;
            }
            if (r0 + 8 < M) {
                float v2 = acc[im][in][2] + b0v;
                float v3 = acc[im][in][3] + b1v;
                if (RELU) { v2 = fmaxf(v2, 0.f); v3 = fmaxf(v3, 0.f); }
                C[(size_t)(r0 + 8) * N + c0] = v2;
                if (c0 + 1 < N) C[(size_t)(r0 + 8) * N + c0 + 1] = v3;
            }
        }
    }
}

// ---------------- launch ----------------
extern "C" void kernel_launch(void* const* d_in, const int* in_sizes, int n_in,
                              void* d_out, int out_size)
{
    const float* x    = (const float*)d_in[0];
    const int*   ei   = (const int*)d_in[1];
    const int*   batc = (const int*)d_in[2];
    const float *W1 = (const float*)d_in[3],  *b1 = (const float*)d_in[4];
    const float *W2 = (const float*)d_in[5],  *b2 = (const float*)d_in[6];
    const float *W3 = (const float*)d_in[7],  *b3 = (const float*)d_in[8];
    const float *Wf1 = (const float*)d_in[9], *bf1 = (const float*)d_in[10];
    const float *Wf2 = (const float*)d_in[11], *bf2 = (const float*)d_in[12];
    float* out = (float*)d_out;

    const int* src = ei;
    const int* dst = ei + N_EDGES;

    float *t_buf, *h_buf, *ax_buf, *pool_buf, *fc1_buf, *w1t, *w2t, *w3t;
    cudaGetSymbolAddress((void**)&t_buf, g_t);
    cudaGetSymbolAddress((void**)&h_buf, g_h);
    cudaGetSymbolAddress((void**)&ax_buf, g_ax);
    cudaGetSymbolAddress((void**)&pool_buf, g_pool);
    cudaGetSymbolAddress((void**)&fc1_buf, g_fc1);
    cudaGetSymbolAddress((void**)&w1t, g_w1t);
    cudaGetSymbolAddress((void**)&w2t, g_w2t);
    cudaGetSymbolAddress((void**)&w3t, g_w3t);

    cudaFuncSetAttribute(gemm_pipe<true>,  cudaFuncAttributeMaxDynamicSharedMemorySize, PIPE_SMEM_BYTES);
    cudaFuncSetAttribute(gemm_pipe<false>, cudaFuncAttributeMaxDynamicSharedMemorySize, PIPE_SMEM_BYTES);
    cudaFuncSetAttribute(gemm_tf32_kernel<true, true>,  cudaFuncAttributeMaxDynamicSharedMemorySize, GEMM_SMEM_BYTES);
    cudaFuncSetAttribute(gemm_tf32_kernel<true, false>, cudaFuncAttributeMaxDynamicSharedMemorySize, GEMM_SMEM_BYTES);

    const int aggBlocks = (N_NODES * 32 + 255) / 256;
    const int tcGrid = (N_NODES + 127) / 128;   // 391

    // --- preprocessing + weight transforms ---
    k_init_deg<<<(N_NODES + 255) / 256, 256>>>();
    k_count<<<(N_EDGES + 255) / 256, 256>>>(dst);
    k_dinv_bsum<<<SCAN_NB, 256>>>();
    k_bscan<<<1, 256>>>();
    k_scatter<<<SCAN_NB, 256>>>();
    k_fill<<<(N_EDGES + 255) / 256, 256>>>(src, dst);
    k_transpose<<<dim3(4, 8), dim3(32, 8)>>>(W1, w1t, 128, 256);
    k_transpose<<<dim3(8, 8), dim3(32, 8)>>>(W2, w2t, 256, 256);
    k_transpose<<<dim3(8, 8), dim3(32, 8)>>>(W3, w3t, 256, 256);

    // --- layer 1: ax = tf32(A_norm @ x) ; h = tf32(relu(ax @ W1 + b1)) ---
    agg_kernel<1, false><<<aggBlocks, 256>>>(x, ax_buf, nullptr);
    gemm_pipe<true><<<tcGrid, 256, PIPE_SMEM_BYTES>>>(ax_buf, w1t, b1, h_buf, N_NODES, 128);
    // --- layer 2 ---
    gemm_pipe<false><<<tcGrid, 256, PIPE_SMEM_BYTES>>>(h_buf, w2t, nullptr, t_buf, N_NODES, 256);
    agg_kernel<2, true><<<aggBlocks, 256>>>(t_buf, h_buf, b2);
    // --- layer 3 ---
    gemm_pipe<false><<<tcGrid, 256, PIPE_SMEM_BYTES>>>(h_buf, w3t, nullptr, t_buf, N_NODES, 256);
    agg_kernel<2, true><<<aggBlocks, 256>>>(t_buf, h_buf, b3);

    // --- mean pool ---
    pool_kernel<<<N_GRAPHS, 256>>>(h_buf, batc);

    // --- MLP head ---
    dim3 gridM((N_GRAPHS + 127) / 128, 1);
    gemm_tf32_kernel<true, true ><<<gridM, 256, GEMM_SMEM_BYTES>>>(pool_buf, Wf1, bf1, fc1_buf, N_GRAPHS, 128, HID);
    gemm_tf32_kernel<true, false><<<gridM, 256, GEMM_SMEM_BYTES>>>(fc1_buf, Wf2, bf2, out, N_GRAPHS, 32, 128);
}

// round 12
// speedup vs baseline: 2.6826x; 1.0064x over previous
#include <cuda_runtime.h>
#include <cuda_bf16.h>
#include <math.h>
#include <stdint.h>

#define N_NODES 50000
#define N_EDGES 300000
#define N_GRAPHS 2048
#define HID 256
#define SCAN_NB ((N_NODES + 255) / 256)   // 196

// ---------------- scratch (static __device__, no allocation) ----------------
__device__ int   g_deg[N_NODES];
__device__ float g_dinv[N_NODES];
__device__ int   g_rowptr[N_NODES + 1];
__device__ int   g_cursor[N_NODES];
__device__ int   g_col[N_EDGES];
__device__ float g_w[N_EDGES];
__device__ int   g_bsum[256];
__device__ float g_t[(size_t)N_NODES * HID];
__device__ float g_h[(size_t)N_NODES * HID];
__device__ float g_ax[(size_t)N_NODES * 128];   // layer-1 aggregated x (tf32-rounded)
__device__ float g_pool[(size_t)N_GRAPHS * HID];
__device__ float g_fc1[(size_t)N_GRAPHS * 128];
__device__ float g_w1t[256 * 128];   // W1^T [n][k], tf32-rounded
__device__ float g_w2t[256 * 256];
__device__ float g_w3t[256 * 256];

// ---------------- small helpers ----------------
__device__ __forceinline__ float4 f4_zero() { return make_float4(0.f, 0.f, 0.f, 0.f); }
__device__ __forceinline__ void f4_fma(float s, const float4& a, float4& acc) {
    acc.x = fmaf(s, a.x, acc.x); acc.y = fmaf(s, a.y, acc.y);
    acc.z = fmaf(s, a.z, acc.z); acc.w = fmaf(s, a.w, acc.w);
}
__device__ __forceinline__ uint32_t f2tf32(float f) {
    uint32_t r;
    asm("cvt.rna.tf32.f32 %0, %1;" : "=r"(r) : "f"(f));
    return r;
}
__device__ __forceinline__ float tf32f(float f) { return __uint_as_float(f2tf32(f)); }
__device__ __forceinline__ uint32_t smem_u32(const void* p) {
    uint32_t a;
    asm("{ .reg .u64 t; cvta.to.shared.u64 t, %1; cvt.u32.u64 %0, t; }" : "=r"(a) : "l"(p));
    return a;
}
__device__ __forceinline__ void cp16(uint32_t dst, const void* src, bool pred) {
    uint32_t sz = pred ? 16u : 0u;
    asm volatile("cp.async.cg.shared.global [%0], [%1], 16, %2;" :: "r"(dst), "l"(src), "r"(sz) : "memory");
}
#define CP_COMMIT() asm volatile("cp.async.commit_group;" ::: "memory")
#define CP_WAIT1()  asm volatile("cp.async.wait_group 1;" ::: "memory")

// ---------------- graph preprocessing ----------------
__global__ void k_init_deg() {
    int i = blockIdx.x * blockDim.x + threadIdx.x;
    if (i < N_NODES) g_deg[i] = 1;
}
__global__ void k_count(const int* __restrict__ dst) {
    int e = blockIdx.x * blockDim.x + threadIdx.x;
    if (e < N_EDGES) atomicAdd(&g_deg[dst[e]], 1);
}
__global__ void __launch_bounds__(256) k_dinv_bsum() {
    __shared__ int s_w[8];
    int idx = blockIdx.x * 256 + threadIdx.x;
    int lane = threadIdx.x & 31, warp = threadIdx.x >> 5;
    int v = 0;
    if (idx < N_NODES) {
        int d = g_deg[idx];
        g_dinv[idx] = rsqrtf((float)d);
        v = d - 1;
    }
    int s = v;
#pragma unroll
    for (int off = 16; off > 0; off >>= 1) s += __shfl_down_sync(0xffffffffu, s, off);
    if (lane == 0) s_w[warp] = s;
    __syncthreads();
    if (threadIdx.x == 0) {
        int t = 0;
#pragma unroll
        for (int w = 0; w < 8; w++) t += s_w[w];
        g_bsum[blockIdx.x] = t;
    }
}
// Scatter with FUSED block-sum scan: each block redundantly scans the 196
// block sums (cheap) instead of a separate single-block kernel.
__global__ void __launch_bounds__(256) k_scatter() {
    __shared__ int s_w[8];
    __shared__ int s_boff;
    const int t = threadIdx.x;
    const int lane = t & 31, warp = t >> 5;

    // phase 0: exclusive prefix of g_bsum up to this block
    {
        int v = (t < SCAN_NB) ? g_bsum[t] : 0;
        int incl = v;
#pragma unroll
        for (int off = 1; off < 32; off <<= 1) {
            int u = __shfl_up_sync(0xffffffffu, incl, off);
            if (lane >= off) incl += u;
        }
        if (lane == 31) s_w[warp] = incl;
        __syncthreads();
        if (warp == 0 && lane < 8) {
            int u = s_w[lane];
            int wi = u;
#pragma unroll
            for (int off = 1; off < 8; off <<= 1) {
                int z = __shfl_up_sync(0xffu, wi, off);
                if (lane >= off) wi += z;
            }
            s_w[lane] = wi - u;     // exclusive warp prefix
        }
        __syncthreads();
        int excl = s_w[warp] + incl - v;
        if (t == (int)blockIdx.x) s_boff = excl;
        if (blockIdx.x == 0 && t == SCAN_NB - 1) g_rowptr[N_NODES] = excl + v;
        __syncthreads();
    }

    // phase 1: per-element scan + scatter
    int idx = blockIdx.x * 256 + t;
    int v = (idx < N_NODES) ? (g_deg[idx] - 1) : 0;
    int incl = v;
#pragma unroll
    for (int off = 1; off < 32; off <<= 1) {
        int u = __shfl_up_sync(0xffffffffu, incl, off);
        if (lane >= off) incl += u;
    }
    if (lane == 31) s_w[warp] = incl;
    __syncthreads();
    if (warp == 0 && lane < 8) {
        int u = s_w[lane];
        int wi = u;
#pragma unroll
        for (int off = 1; off < 8; off <<= 1) {
            int z = __shfl_up_sync(0xffu, wi, off);
            if (lane >= off) wi += z;
        }
        s_w[lane] = wi - u;
    }
    __syncthreads();
    if (idx < N_NODES) {
        int p = s_boff + s_w[warp] + incl - v;
        g_rowptr[idx] = p;
        g_cursor[idx] = p;
    }
}
__global__ void k_fill(const int* __restrict__ src, const int* __restrict__ dst) {
    int e = blockIdx.x * blockDim.x + threadIdx.x;
    if (e < N_EDGES) {
        int s = src[e], d = dst[e];
        int pos = atomicAdd(&g_cursor[d], 1);
        g_col[pos] = s;
        g_w[pos]   = g_dinv[s] * g_dinv[d];
    }
}

// ---------------- weight transpose + cvt: Wt[n][k] = tf32(W[k][n]) ---------
__global__ void k_transpose(const float* __restrict__ W, float* __restrict__ Wt, int K, int N) {
    __shared__ float t[32][33];
    int kb = blockIdx.x * 32, nb = blockIdx.y * 32;
    int tx = threadIdx.x, ty = threadIdx.y;   // 32 x 8
#pragma unroll
    for (int j = 0; j < 32; j += 8) {
        int k = kb + ty + j, n = nb + tx;
        if (k < K && n < N) t[ty + j][tx] = W[(size_t)k * N + n];
    }
    __syncthreads();
#pragma unroll
    for (int j = 0; j < 32; j += 8) {
        int n = nb + ty + j, k = kb + tx;
        if (n < N && k < K) Wt[(size_t)n * K + k] = tf32f(t[tx][ty + j]);
    }
}

// ---------------- cp.async pipelined mma.sync tf32 GEMM --------------------
// C[M,256] = A[M,K] @ Bt^T (+bias,+relu,+cvt if BR)
// A [m][k], Bt [n][k], both pre-tf32-rounded.
// BM=128, BN=256, BK=32, 256 threads = 8 warps, warp tile 64x64.
// Fragment register double-buffering overlaps LDS (ks+1) with MMA (ks).
#define PROW 36
#define PSTAGE_A_FLOATS (128 * PROW)            // 4608
#define PSTAGE_B_FLOATS (256 * PROW)            // 9216
#define PSTAGE_FLOATS   (PSTAGE_A_FLOATS + PSTAGE_B_FLOATS)
#define PIPE_SMEM_BYTES (3 * PSTAGE_FLOATS * 4) // 165888

template <bool BR>   // bias+relu+cvt epilogue
__global__ void __launch_bounds__(256, 1) gemm_pipe(
    const float* __restrict__ A, const float* __restrict__ Bt,
    const float* __restrict__ bias, float* __restrict__ C, int M, int K)
{
    extern __shared__ float ps[];
    const int tid  = threadIdx.x;
    const int lane = tid & 31;
    const int warp = tid >> 5;
    const int wm   = warp >> 2;          // 0..1 -> m = wm*64
    const int wn   = warp & 3;           // 0..3 -> n = wn*64
    const int g    = lane >> 2;
    const int tig  = lane & 3;
    const int mbase = blockIdx.x * 128;
    const uint32_t sbase = smem_u32(ps);

    float acc[4][8][4];
#pragma unroll
    for (int im = 0; im < 4; im++)
#pragma unroll
        for (int in = 0; in < 8; in++)
#pragma unroll
            for (int c = 0; c < 4; c++) acc[im][in][c] = 0.f;

    auto prefetch = [&](int tk, int s) {
        const int k0 = tk << 5;
        const uint32_t abuf = sbase + (uint32_t)s * PSTAGE_FLOATS * 4;
        const uint32_t bbuf = abuf + PSTAGE_A_FLOATS * 4;
#pragma unroll
        for (int it = 0; it < 4; it++) {     // A: 1024 16B chunks
            int c = tid + it * 256;
            int r = c >> 3, kc = (c & 7) << 2;
            int grow = mbase + r;
            cp16(abuf + (uint32_t)(r * PROW + kc) * 4,
                 A + (size_t)grow * K + k0 + kc, grow < M);
        }
#pragma unroll
        for (int it = 0; it < 8; it++) {     // B: 2048 16B chunks
            int c = tid + it * 256;
            int r = c >> 3, kc = (c & 7) << 2;
            cp16(bbuf + (uint32_t)(r * PROW + kc) * 4,
                 Bt + (size_t)r * K + k0 + kc, true);
        }
    };

    const int nk = K >> 5;
    prefetch(0, 0); CP_COMMIT();
    if (nk > 1) prefetch(1, 1);
    CP_COMMIT();

    uint32_t af[2][4][4], bf[2][8][2];

    for (int tk = 0; tk < nk; tk++) {
        CP_WAIT1();
        __syncthreads();
        const int s = tk % 3;
        if (tk + 2 < nk) prefetch(tk + 2, (tk + 2) % 3);
        CP_COMMIT();

        const float* Ab = ps + (size_t)s * PSTAGE_FLOATS;
        const float* Bb = Ab + PSTAGE_A_FLOATS;

        // load fragments for ks = 0 into buffer 0
#pragma unroll
        for (int im = 0; im < 4; im++) {
            const float* ra = Ab + (wm * 64 + im * 16 + g) * PROW;
            const float* rb = ra + 8 * PROW;
            af[0][im][0] = __float_as_uint(ra[tig]);
            af[0][im][1] = __float_as_uint(rb[tig]);
            af[0][im][2] = __float_as_uint(ra[tig + 4]);
            af[0][im][3] = __float_as_uint(rb[tig + 4]);
        }
#pragma unroll
        for (int in = 0; in < 8; in++) {
            const float* rn = Bb + (wn * 64 + in * 8 + g) * PROW;
            bf[0][in][0] = __float_as_uint(rn[tig]);
            bf[0][in][1] = __float_as_uint(rn[tig + 4]);
        }

#pragma unroll
        for (int ks = 0; ks < 4; ks++) {
            const int cur = ks & 1;
            if (ks < 3) {    // prefetch ks+1 fragments into other buffer
                const int kk = (ks + 1) * 8;
                const int nxt = cur ^ 1;
#pragma unroll
                for (int im = 0; im < 4; im++) {
                    const float* ra = Ab + (wm * 64 + im * 16 + g) * PROW;
                    const float* rb = ra + 8 * PROW;
                    af[nxt][im][0] = __float_as_uint(ra[kk + tig]);
                    af[nxt][im][1] = __float_as_uint(rb[kk + tig]);
                    af[nxt][im][2] = __float_as_uint(ra[kk + tig + 4]);
                    af[nxt][im][3] = __float_as_uint(rb[kk + tig + 4]);
                }
#pragma unroll
                for (int in = 0; in < 8; in++) {
                    const float* rn = Bb + (wn * 64 + in * 8 + g) * PROW;
                    bf[nxt][in][0] = __float_as_uint(rn[kk + tig]);
                    bf[nxt][in][1] = __float_as_uint(rn[kk + tig + 4]);
                }
            }
#pragma unroll
            for (int im = 0; im < 4; im++)
#pragma unroll
                for (int in = 0; in < 8; in++) {
                    asm volatile(
                        "mma.sync.aligned.m16n8k8.row.col.f32.tf32.tf32.f32 "
                        "{%0,%1,%2,%3}, {%4,%5,%6,%7}, {%8,%9}, {%0,%1,%2,%3};\n"
                        : "+f"(acc[im][in][0]), "+f"(acc[im][in][1]),
                          "+f"(acc[im][in][2]), "+f"(acc[im][in][3])
                        : "r"(af[cur][im][0]), "r"(af[cur][im][1]),
                          "r"(af[cur][im][2]), "r"(af[cur][im][3]),
                          "r"(bf[cur][in][0]), "r"(bf[cur][in][1]));
                }
        }
    }

    // epilogue
#pragma unroll
    for (int im = 0; im < 4; im++) {
        int r0 = mbase + wm * 64 + im * 16 + g;
#pragma unroll
        for (int in = 0; in < 8; in++) {
            int c0 = wn * 64 + in * 8 + tig * 2;
            float v0 = acc[im][in][0], v1 = acc[im][in][1];
            float v2 = acc[im][in][2], v3 = acc[im][in][3];
            if (BR) {
                float b0 = bias[c0], b1 = bias[c0 + 1];
                v0 = tf32f(fmaxf(v0 + b0, 0.f)); v1 = tf32f(fmaxf(v1 + b1, 0.f));
                v2 = tf32f(fmaxf(v2 + b0, 0.f)); v3 = tf32f(fmaxf(v3 + b1, 0.f));
            }
            if (r0 < M)
                *(float2*)(C + (size_t)r0 * 256 + c0) = make_float2(v0, v1);
            if (r0 + 8 < M)
                *(float2*)(C + (size_t)(r0 + 8) * 256 + c0) = make_float2(v2, v3);
        }
    }
}

// ---------------- aggregation (warp per node), 2x unrolled edge loop -------
// out[i] = POST( dinv[i]^2 * t[i] + sum_e w_e * t[col_e] )
template <int VEC, bool BIASRELU>   // VEC = WIDTH/128
__global__ void __launch_bounds__(256) agg_kernel(
    const float* __restrict__ t, float* __restrict__ out, const float* __restrict__ bias)
{
    const int WIDTH = VEC * 128;
    int wrp = (blockIdx.x * blockDim.x + threadIdx.x) >> 5;
    int lane = threadIdx.x & 31;
    if (wrp >= N_NODES) return;
    const int i = wrp;

    const float4* rowi = (const float4*)(t + (size_t)i * WIDTH);
    float di = g_dinv[i];
    float ws = di * di;
    float4 acc[VEC];
#pragma unroll
    for (int v = 0; v < VEC; v++) {
        acc[v] = f4_zero();
        f4_fma(ws, rowi[lane + 32 * v], acc[v]);
    }
    const int e0 = g_rowptr[i], e1 = g_rowptr[i + 1];
    int e = e0;
    for (; e + 2 <= e1; e += 2) {
        int   c0 = g_col[e],     c1 = g_col[e + 1];
        float w0 = g_w[e],       w1 = g_w[e + 1];
        const float4* r0 = (const float4*)(t + (size_t)c0 * WIDTH);
        const float4* r1 = (const float4*)(t + (size_t)c1 * WIDTH);
        float4 u0[VEC], u1[VEC];
#pragma unroll
        for (int v = 0; v < VEC; v++) { u0[v] = r0[lane + 32 * v]; u1[v] = r1[lane + 32 * v]; }
#pragma unroll
        for (int v = 0; v < VEC; v++) { f4_fma(w0, u0[v], acc[v]); f4_fma(w1, u1[v], acc[v]); }
    }
    if (e < e1) {
        int   c  = g_col[e];
        float we = g_w[e];
        const float4* rowc = (const float4*)(t + (size_t)c * WIDTH);
#pragma unroll
        for (int v = 0; v < VEC; v++)
            f4_fma(we, rowc[lane + 32 * v], acc[v]);
    }
    float4* dstp = (float4*)(out + (size_t)i * WIDTH);
#pragma unroll
    for (int v = 0; v < VEC; v++) {
        float4 o;
        if (BIASRELU) {
            float4 b = ((const float4*)bias)[lane + 32 * v];
            o.x = tf32f(fmaxf(acc[v].x + b.x, 0.f));
            o.y = tf32f(fmaxf(acc[v].y + b.y, 0.f));
            o.z = tf32f(fmaxf(acc[v].z + b.z, 0.f));
            o.w = tf32f(fmaxf(acc[v].w + b.w, 0.f));
        } else {
            o.x = tf32f(acc[v].x); o.y = tf32f(acc[v].y);
            o.z = tf32f(acc[v].z); o.w = tf32f(acc[v].w);
        }
        dstp[lane + 32 * v] = o;
    }
}

// ---------------- mean pool ----------------
__device__ __forceinline__ int lower_bound_i(const int* a, int n, int key) {
    int lo = 0, hi = n;
    while (lo < hi) {
        int mid = (lo + hi) >> 1;
        if (a[mid] < key) lo = mid + 1; else hi = mid;
    }
    return lo;
}
__global__ void __launch_bounds__(256) pool_kernel(
    const float* __restrict__ h, const int* __restrict__ batch)
{
    int g = blockIdx.x;
    int lo = lower_bound_i(batch, N_NODES, g);
    int hi = lower_bound_i(batch, N_NODES, g + 1);
    int cnt = hi - lo;
    int f = threadIdx.x;
    float acc = 0.f;
    for (int i = lo; i < hi; i++)
        acc += h[(size_t)i * HID + f];
    g_pool[(size_t)g * HID + f] = acc / fmaxf((float)cnt, 1.0f);
}

// ---------------- mma.sync tf32 GEMM (MLP head) ----------------------------
#define SROW 136
#define GEMM_TILE_FLOATS (32 * SROW)
#define GEMM_SMEM_BYTES (4 * GEMM_TILE_FLOATS * 4)

__device__ __forceinline__ int aidx(int k, int m) {
    return k * SROW + (m ^ (((k >> 2) & 7) << 2));
}

template <bool BIAS, bool RELU>
__global__ void __launch_bounds__(256) gemm_tf32_kernel(
    const float* __restrict__ A, const float* __restrict__ B,
    const float* __restrict__ bias, float* __restrict__ C,
    int M, int N, int K)
{
    extern __shared__ float smem[];
    const int tid = threadIdx.x;
    const int lane = tid & 31;
    const int warp = tid >> 5;
    const int wm = warp >> 2, wn = warp & 3;
    const int g = lane >> 2, tig = lane & 3;
    const int brow = blockIdx.x, bcol = blockIdx.y;

    float acc[4][4][4];
#pragma unroll
    for (int im = 0; im < 4; im++)
#pragma unroll
        for (int in = 0; in < 4; in++)
#pragma unroll
            for (int c = 0; c < 4; c++) acc[im][in][c] = 0.f;

    float4 va[4], vb[4];
    auto load_tiles = [&](int k0) {
#pragma unroll
        for (int it = 0; it < 4; it++) {
            int f = tid + it * 256;
            int r = f >> 3, kc4 = (f & 7) << 2;
            int grow = brow * 128 + r;
            va[it] = f4_zero();
            if (grow < M) va[it] = *(const float4*)(A + (size_t)grow * K + k0 + kc4);
        }
#pragma unroll
        for (int it = 0; it < 4; it++) {
            int f = tid + it * 256;
            int kr = f >> 5, c4 = (f & 31) << 2;
            int gcol = bcol * 128 + c4;
            vb[it] = f4_zero();
            if (gcol + 3 < N) vb[it] = *(const float4*)(B + (size_t)(k0 + kr) * N + gcol);
            else if (gcol < N) {
                vb[it].x = B[(size_t)(k0 + kr) * N + gcol];
                if (gcol + 1 < N) vb[it].y = B[(size_t)(k0 + kr) * N + gcol + 1];
                if (gcol + 2 < N) vb[it].z = B[(size_t)(k0 + kr) * N + gcol + 2];
            }
        }
    };
    auto store_tiles = [&](int b) {
        float* Asb = smem + b * GEMM_TILE_FLOATS;
        float* Bsb = smem + (2 + b) * GEMM_TILE_FLOATS;
#pragma unroll
        for (int it = 0; it < 4; it++) {
            int f = tid + it * 256;
            int r = f >> 3, kc4 = (f & 7) << 2;
            Asb[aidx(kc4 + 0, r)] = tf32f(va[it].x);
            Asb[aidx(kc4 + 1, r)] = tf32f(va[it].y);
            Asb[aidx(kc4 + 2, r)] = tf32f(va[it].z);
            Asb[aidx(kc4 + 3, r)] = tf32f(va[it].w);
        }
#pragma unroll
        for (int it = 0; it < 4; it++) {
            int f = tid + it * 256;
            int kr = f >> 5, c4 = (f & 31) << 2;
            float4 w;
            w.x = tf32f(vb[it].x); w.y = tf32f(vb[it].y);
            w.z = tf32f(vb[it].z); w.w = tf32f(vb[it].w);
            *(float4*)&Bsb[kr * SROW + c4] = w;
        }
    };

    const int nk = K >> 5;
    load_tiles(0);
    store_tiles(0);
    __syncthreads();

    for (int tk = 0; tk < nk; tk++) {
        const int cur = tk & 1;
        if (tk + 1 < nk) load_tiles((tk + 1) << 5);
        const float* Asb = smem + cur * GEMM_TILE_FLOATS;
        const float* Bsb = smem + (2 + cur) * GEMM_TILE_FLOATS;
#pragma unroll
        for (int ks = 0; ks < 4; ks++) {
            const int kk = ks * 8;
            uint32_t af[4][4], bf[4][2];
#pragma unroll
            for (int im = 0; im < 4; im++) {
                int m0 = wm * 64 + im * 16;
                af[im][0] = __float_as_uint(Asb[aidx(kk + tig,     m0 + g    )]);
                af[im][1] = __float_as_uint(Asb[aidx(kk + tig,     m0 + g + 8)]);
                af[im][2] = __float_as_uint(Asb[aidx(kk + tig + 4, m0 + g    )]);
                af[im][3] = __float_as_uint(Asb[aidx(kk + tig + 4, m0 + g + 8)]);
            }
#pragma unroll
            for (int in = 0; in < 4; in++) {
                int n0 = wn * 32 + in * 8;
                bf[in][0] = __float_as_uint(Bsb[(kk + tig    ) * SROW + n0 + g]);
                bf[in][1] = __float_as_uint(Bsb[(kk + tig + 4) * SROW + n0 + g]);
            }
#pragma unroll
            for (int im = 0; im < 4; im++)
#pragma unroll
                for (int in = 0; in < 4; in++) {
                    asm volatile(
                        "mma.sync.aligned.m16n8k8.row.col.f32.tf32.tf32.f32 "
                        "{%0,%1,%2,%3}, {%4,%5,%6,%7}, {%8,%9}, {%0,%1,%2,%3};\n"
                        : "+f"(acc[im][in][0]), "+f"(acc[im][in][1]),
                          "+f"(acc[im][in][2]), "+f"(acc[im][in][3])
                        : "r"(af[im][0]), "r"(af[im][1]), "r"(af[im][2]), "r"(af[im][3]),
                          "r"(bf[in][0]), "r"(bf[in][1]));
                }
        }
        if (tk + 1 < nk) store_tiles(1 - cur);
        __syncthreads();
    }

#pragma unroll
    for (int im = 0; im < 4; im++) {
        int r0 = brow * 128 + wm * 64 + im * 16 + g;
#pragma unroll
        for (int in = 0; in < 4; in++) {
            int c0 = bcol * 128 + wn * 32 + in * 8 + tig * 2;
            if (c0 >= N) continue;
            float b0v = 0.f, b1v = 0.f;
            if (BIAS) { b0v = bias[c0]; if (c0 + 1 < N) b1v = bias[c0 + 1]; }
            if (r0 < M) {
                float v0 = acc[im][in][0] + b0v;
                float v1 = acc[im][in][1] + b1v;
                if (RELU) { v0 = fmaxf(v0, 0.f); v1 = fmaxf(v1, 0.f); }
                C[(size_t)r0 * N + c0] = v0;
                if (c0 + 1 < N) C[(size_t)r0 * N + c0 + 1] = v1;
            }
            if (r0 + 8 < M) {
                float v2 = acc[im][in][2] + b0v;
                float v3 = acc[im][in][3] + b1v;
                if (RELU) { v2 = fmaxf(v2, 0.f); v3 = fmaxf(v3, 0.f); }
                C[(size_t)(r0 + 8) * N + c0] = v2;
                if (c0 + 1 < N) C[(size_t)(r0 + 8) * N + c0 + 1] = v3;
            }
        }
    }
}

// ---------------- launch ----------------
extern "C" void kernel_launch(void* const* d_in, const int* in_sizes, int n_in,
                              void* d_out, int out_size)
{
    const float* x    = (const float*)d_in[0];
    const int*   ei   = (const int*)d_in[1];
    const int*   batc = (const int*)d_in[2];
    const float *W1 = (const float*)d_in[3],  *b1 = (const float*)d_in[4];
    const float *W2 = (const float*)d_in[5],  *b2 = (const float*)d_in[6];
    const float *W3 = (const float*)d_in[7],  *b3 = (const float*)d_in[8];
    const float *Wf1 = (const float*)d_in[9], *bf1 = (const float*)d_in[10];
    const float *Wf2 = (const float*)d_in[11], *bf2 = (const float*)d_in[12];
    float* out = (float*)d_out;

    const int* src = ei;
    const int* dst = ei + N_EDGES;

    float *t_buf, *h_buf, *ax_buf, *pool_buf, *fc1_buf, *w1t, *w2t, *w3t;
    cudaGetSymbolAddress((void**)&t_buf, g_t);
    cudaGetSymbolAddress((void**)&h_buf, g_h);
    cudaGetSymbolAddress((void**)&ax_buf, g_ax);
    cudaGetSymbolAddress((void**)&pool_buf, g_pool);
    cudaGetSymbolAddress((void**)&fc1_buf, g_fc1);
    cudaGetSymbolAddress((void**)&w1t, g_w1t);
    cudaGetSymbolAddress((void**)&w2t, g_w2t);
    cudaGetSymbolAddress((void**)&w3t, g_w3t);

    cudaFuncSetAttribute(gemm_pipe<true>,  cudaFuncAttributeMaxDynamicSharedMemorySize, PIPE_SMEM_BYTES);
    cudaFuncSetAttribute(gemm_pipe<false>, cudaFuncAttributeMaxDynamicSharedMemorySize, PIPE_SMEM_BYTES);
    cudaFuncSetAttribute(gemm_tf32_kernel<true, true>,  cudaFuncAttributeMaxDynamicSharedMemorySize, GEMM_SMEM_BYTES);
    cudaFuncSetAttribute(gemm_tf32_kernel<true, false>, cudaFuncAttributeMaxDynamicSharedMemorySize, GEMM_SMEM_BYTES);

    const int aggBlocks = (N_NODES * 32 + 255) / 256;
    const int tcGrid = (N_NODES + 127) / 128;   // 391

    // --- preprocessing + weight transforms ---
    k_init_deg<<<(N_NODES + 255) / 256, 256>>>();
    k_count<<<(N_EDGES + 255) / 256, 256>>>(dst);
    k_dinv_bsum<<<SCAN_NB, 256>>>();
    k_scatter<<<SCAN_NB, 256>>>();
    k_fill<<<(N_EDGES + 255) / 256, 256>>>(src, dst);
    k_transpose<<<dim3(4, 8), dim3(32, 8)>>>(W1, w1t, 128, 256);
    k_transpose<<<dim3(8, 8), dim3(32, 8)>>>(W2, w2t, 256, 256);
    k_transpose<<<dim3(8, 8), dim3(32, 8)>>>(W3, w3t, 256, 256);

    // --- layer 1: ax = tf32(A_norm @ x) ; h = tf32(relu(ax @ W1 + b1)) ---
    agg_kernel<1, false><<<aggBlocks, 256>>>(x, ax_buf, nullptr);
    gemm_pipe<true><<<tcGrid, 256, PIPE_SMEM_BYTES>>>(ax_buf, w1t, b1, h_buf, N_NODES, 128);
    // --- layer 2 ---
    gemm_pipe<false><<<tcGrid, 256, PIPE_SMEM_BYTES>>>(h_buf, w2t, nullptr, t_buf, N_NODES, 256);
    agg_kernel<2, true><<<aggBlocks, 256>>>(t_buf, h_buf, b2);
    // --- layer 3 ---
    gemm_pipe<false><<<tcGrid, 256, PIPE_SMEM_BYTES>>>(h_buf, w3t, nullptr, t_buf, N_NODES, 256);
    agg_kernel<2, true><<<aggBlocks, 256>>>(t_buf, h_buf, b3);

    // --- mean pool ---
    pool_kernel<<<N_GRAPHS, 256>>>(h_buf, batc);

    // --- MLP head ---
    dim3 gridM((N_GRAPHS + 127) / 128, 1);
    gemm_tf32_kernel<true, true ><<<gridM, 256, GEMM_SMEM_BYTES>>>(pool_buf, Wf1, bf1, fc1_buf, N_GRAPHS, 128, HID);
    gemm_tf32_kernel<true, false><<<gridM, 256, GEMM_SMEM_BYTES>>>(fc1_buf, Wf2, bf2, out, N_GRAPHS, 32, 128);
}

// round 13
// speedup vs baseline: 3.2607x; 1.2155x over previous
#include <cuda_runtime.h>
#include <cuda_fp16.h>
#include <math.h>
#include <stdint.h>

#define N_NODES 50000
#define N_EDGES 300000
#define N_GRAPHS 2048
#define HID 256
#define SCAN_NB ((N_NODES + 255) / 256)   // 196

// ---------------- scratch (static __device__, no allocation) ----------------
__device__ int    g_deg[N_NODES];
__device__ float  g_dinv[N_NODES];
__device__ int    g_rowptr[N_NODES + 1];
__device__ int    g_cursor[N_NODES];
__device__ int    g_col[N_EDGES];
__device__ float  g_w[N_EDGES];
__device__ int    g_bsum[256];
__device__ float  g_t[(size_t)N_NODES * HID];          // GEMM fp32 output
__device__ __half g_h[(size_t)N_NODES * HID];          // activations (fp16)
__device__ __half g_ax[(size_t)N_NODES * 128];         // layer-1 agg(x) (fp16)
__device__ float  g_pool[(size_t)N_GRAPHS * HID];
__device__ float  g_fc1[(size_t)N_GRAPHS * 128];
__device__ __half g_w1t[256 * 128];   // W1^T [n][k] fp16
__device__ __half g_w2t[256 * 256];
__device__ __half g_w3t[256 * 256];

// ---------------- small helpers ----------------
__device__ __forceinline__ float4 f4_zero() { return make_float4(0.f, 0.f, 0.f, 0.f); }
__device__ __forceinline__ void f4_fma(float s, const float4& a, float4& acc) {
    acc.x = fmaf(s, a.x, acc.x); acc.y = fmaf(s, a.y, acc.y);
    acc.z = fmaf(s, a.z, acc.z); acc.w = fmaf(s, a.w, acc.w);
}
__device__ __forceinline__ uint32_t f2tf32(float f) {
    uint32_t r;
    asm("cvt.rna.tf32.f32 %0, %1;" : "=r"(r) : "f"(f));
    return r;
}
__device__ __forceinline__ float tf32f(float f) { return __uint_as_float(f2tf32(f)); }
__device__ __forceinline__ uint32_t smem_u32(const void* p) {
    uint32_t a;
    asm("{ .reg .u64 t; cvta.to.shared.u64 t, %1; cvt.u32.u64 %0, t; }" : "=r"(a) : "l"(p));
    return a;
}
__device__ __forceinline__ void cp16(uint32_t dst, const void* src, bool pred) {
    uint32_t sz = pred ? 16u : 0u;
    asm volatile("cp.async.cg.shared.global [%0], [%1], 16, %2;" :: "r"(dst), "l"(src), "r"(sz) : "memory");
}
#define CP_COMMIT() asm volatile("cp.async.commit_group;" ::: "memory")
#define CP_WAIT1()  asm volatile("cp.async.wait_group 1;" ::: "memory")

__device__ __forceinline__ uint32_t pack_h2(float a, float b) {
    __half2 h = __floats2half2_rn(a, b);
    return *(uint32_t*)&h;
}

// ---------------- graph preprocessing ----------------
__global__ void k_init_deg() {
    int i = blockIdx.x * blockDim.x + threadIdx.x;
    if (i < N_NODES) g_deg[i] = 1;
}
__global__ void k_count(const int* __restrict__ dst) {
    int e = blockIdx.x * blockDim.x + threadIdx.x;
    if (e < N_EDGES) atomicAdd(&g_deg[dst[e]], 1);
}
__global__ void __launch_bounds__(256) k_dinv_bsum() {
    __shared__ int s_w[8];
    int idx = blockIdx.x * 256 + threadIdx.x;
    int lane = threadIdx.x & 31, warp = threadIdx.x >> 5;
    int v = 0;
    if (idx < N_NODES) {
        int d = g_deg[idx];
        g_dinv[idx] = rsqrtf((float)d);
        v = d - 1;
    }
    int s = v;
#pragma unroll
    for (int off = 16; off > 0; off >>= 1) s += __shfl_down_sync(0xffffffffu, s, off);
    if (lane == 0) s_w[warp] = s;
    __syncthreads();
    if (threadIdx.x == 0) {
        int t = 0;
#pragma unroll
        for (int w = 0; w < 8; w++) t += s_w[w];
        g_bsum[blockIdx.x] = t;
    }
}
// Scatter with fused block-sum scan.
__global__ void __launch_bounds__(256) k_scatter() {
    __shared__ int s_w[8];
    __shared__ int s_boff;
    const int t = threadIdx.x;
    const int lane = t & 31, warp = t >> 5;
    {
        int v = (t < SCAN_NB) ? g_bsum[t] : 0;
        int incl = v;
#pragma unroll
        for (int off = 1; off < 32; off <<= 1) {
            int u = __shfl_up_sync(0xffffffffu, incl, off);
            if (lane >= off) incl += u;
        }
        if (lane == 31) s_w[warp] = incl;
        __syncthreads();
        if (warp == 0 && lane < 8) {
            int u = s_w[lane];
            int wi = u;
#pragma unroll
            for (int off = 1; off < 8; off <<= 1) {
                int z = __shfl_up_sync(0xffu, wi, off);
                if (lane >= off) wi += z;
            }
            s_w[lane] = wi - u;
        }
        __syncthreads();
        int excl = s_w[warp] + incl - v;
        if (t == (int)blockIdx.x) s_boff = excl;
        if (blockIdx.x == 0 && t == SCAN_NB - 1) g_rowptr[N_NODES] = excl + v;
        __syncthreads();
    }
    int idx = blockIdx.x * 256 + t;
    int v = (idx < N_NODES) ? (g_deg[idx] - 1) : 0;
    int incl = v;
#pragma unroll
    for (int off = 1; off < 32; off <<= 1) {
        int u = __shfl_up_sync(0xffffffffu, incl, off);
        if (lane >= off) incl += u;
    }
    if (lane == 31) s_w[warp] = incl;
    __syncthreads();
    if (warp == 0 && lane < 8) {
        int u = s_w[lane];
        int wi = u;
#pragma unroll
        for (int off = 1; off < 8; off <<= 1) {
            int z = __shfl_up_sync(0xffu, wi, off);
            if (lane >= off) wi += z;
        }
        s_w[lane] = wi - u;
    }
    __syncthreads();
    if (idx < N_NODES) {
        int p = s_boff + s_w[warp] + incl - v;
        g_rowptr[idx] = p;
        g_cursor[idx] = p;
    }
}
__global__ void k_fill(const int* __restrict__ src, const int* __restrict__ dst) {
    int e = blockIdx.x * blockDim.x + threadIdx.x;
    if (e < N_EDGES) {
        int s = src[e], d = dst[e];
        int pos = atomicAdd(&g_cursor[d], 1);
        g_col[pos] = s;
        g_w[pos]   = g_dinv[s] * g_dinv[d];
    }
}

// ---------------- weight transpose + cvt: Wt[n][k] = fp16(W[k][n]) --------
__global__ void k_transpose(const float* __restrict__ W, __half* __restrict__ Wt, int K, int N) {
    __shared__ float t[32][33];
    int kb = blockIdx.x * 32, nb = blockIdx.y * 32;
    int tx = threadIdx.x, ty = threadIdx.y;   // 32 x 8
#pragma unroll
    for (int j = 0; j < 32; j += 8) {
        int k = kb + ty + j, n = nb + tx;
        if (k < K && n < N) t[ty + j][tx] = W[(size_t)k * N + n];
    }
    __syncthreads();
#pragma unroll
    for (int j = 0; j < 32; j += 8) {
        int n = nb + ty + j, k = kb + tx;
        if (n < N && k < K) Wt[(size_t)n * K + k] = __float2half_rn(t[tx][ty + j]);
    }
}

// ---------------- cp.async pipelined mma.sync fp16 GEMM --------------------
// C = A[M,K] @ Bt^T. A [m][k] fp16, Bt [n][k] fp16. Accumulate fp32.
// BM=128, BN=256, BK=32, 256 threads = 8 warps, warp tile 64x64, m16n8k16.
// Rows stored with 80B pitch (32 halves = 64B + 16B pad): bank = (20g+tig)%32
// covers all 32 banks -> conflict-free fragment loads.
// BR=true: epilogue bias+relu, output fp16 to Ch. BR=false: raw fp32 to Cf.
#define HROWB 80
#define HSTAGE_A (128 * HROWB)             // 10240 B
#define HSTAGE_B (256 * HROWB)             // 20480 B
#define HSTAGE   (HSTAGE_A + HSTAGE_B)     // 30720 B
#define HPIPE_SMEM (3 * HSTAGE)            // 92160 B

template <bool BR>
__global__ void __launch_bounds__(256, 1) gemm_h(
    const __half* __restrict__ A, const __half* __restrict__ Bt,
    const float* __restrict__ bias, float* __restrict__ Cf, __half* __restrict__ Ch,
    int M, int K)
{
    extern __shared__ char ps[];
    const int tid  = threadIdx.x;
    const int lane = tid & 31;
    const int warp = tid >> 5;
    const int wm   = warp >> 2;          // 0..1 -> m = wm*64
    const int wn   = warp & 3;           // 0..3 -> n = wn*64
    const int g    = lane >> 2;
    const int tig  = lane & 3;
    const int mbase = blockIdx.x * 128;
    const uint32_t sbase = smem_u32(ps);

    float acc[4][8][4];
#pragma unroll
    for (int im = 0; im < 4; im++)
#pragma unroll
        for (int in = 0; in < 8; in++)
#pragma unroll
            for (int c = 0; c < 4; c++) acc[im][in][c] = 0.f;

    auto prefetch = [&](int tk, int s) {
        const int k0 = tk << 5;            // in halves
        const uint32_t abuf = sbase + (uint32_t)s * HSTAGE;
        const uint32_t bbuf = abuf + HSTAGE_A;
#pragma unroll
        for (int it = 0; it < 2; it++) {   // A: 512 16B chunks (8 halves each)
            int c = tid + it * 256;
            int r = c >> 2, q = c & 3;
            int grow = mbase + r;
            cp16(abuf + (uint32_t)(r * HROWB + q * 16),
                 A + (size_t)grow * K + k0 + q * 8, grow < M);
        }
#pragma unroll
        for (int it = 0; it < 4; it++) {   // B: 1024 16B chunks
            int c = tid + it * 256;
            int r = c >> 2, q = c & 3;
            cp16(bbuf + (uint32_t)(r * HROWB + q * 16),
                 Bt + (size_t)r * K + k0 + q * 8, true);
        }
    };

    const int nk = K >> 5;
    prefetch(0, 0); CP_COMMIT();
    if (nk > 1) prefetch(1, 1);
    CP_COMMIT();

    for (int tk = 0; tk < nk; tk++) {
        CP_WAIT1();
        __syncthreads();
        const int s = tk % 3;
        if (tk + 2 < nk) prefetch(tk + 2, (tk + 2) % 3);
        CP_COMMIT();

        const char* Ab = ps + (size_t)s * HSTAGE;
        const char* Bb = Ab + HSTAGE_A;
#pragma unroll
        for (int kc = 0; kc < 2; kc++) {   // two k16 chunks per k32 tile
            const int kbyte = kc * 32 + tig * 4;   // 2 halves at khalf = kc*16 + 2*tig
            uint32_t af[4][4], bf[8][2];
#pragma unroll
            for (int im = 0; im < 4; im++) {
                const char* ra = Ab + (wm * 64 + im * 16 + g) * HROWB;
                const char* rb = ra + 8 * HROWB;
                af[im][0] = *(const uint32_t*)(ra + kbyte);        // row g,   k-lo
                af[im][1] = *(const uint32_t*)(rb + kbyte);        // row g+8, k-lo
                af[im][2] = *(const uint32_t*)(ra + kbyte + 16);   // row g,   k-hi
                af[im][3] = *(const uint32_t*)(rb + kbyte + 16);   // row g+8, k-hi
            }
#pragma unroll
            for (int in = 0; in < 8; in++) {
                const char* rn = Bb + (wn * 64 + in * 8 + g) * HROWB;
                bf[in][0] = *(const uint32_t*)(rn + kbyte);
                bf[in][1] = *(const uint32_t*)(rn + kbyte + 16);
            }
#pragma unroll
            for (int im = 0; im < 4; im++)
#pragma unroll
                for (int in = 0; in < 8; in++) {
                    asm volatile(
                        "mma.sync.aligned.m16n8k16.row.col.f32.f16.f16.f32 "
                        "{%0,%1,%2,%3}, {%4,%5,%6,%7}, {%8,%9}, {%0,%1,%2,%3};\n"
                        : "+f"(acc[im][in][0]), "+f"(acc[im][in][1]),
                          "+f"(acc[im][in][2]), "+f"(acc[im][in][3])
                        : "r"(af[im][0]), "r"(af[im][1]), "r"(af[im][2]), "r"(af[im][3]),
                          "r"(bf[in][0]), "r"(bf[in][1]));
                }
        }
    }

    // epilogue
#pragma unroll
    for (int im = 0; im < 4; im++) {
        int r0 = mbase + wm * 64 + im * 16 + g;
#pragma unroll
        for (int in = 0; in < 8; in++) {
            int c0 = wn * 64 + in * 8 + tig * 2;
            float v0 = acc[im][in][0], v1 = acc[im][in][1];
            float v2 = acc[im][in][2], v3 = acc[im][in][3];
            if (BR) {
                float b0 = bias[c0], b1 = bias[c0 + 1];
                v0 = fmaxf(v0 + b0, 0.f); v1 = fmaxf(v1 + b1, 0.f);
                v2 = fmaxf(v2 + b0, 0.f); v3 = fmaxf(v3 + b1, 0.f);
                if (r0 < M)
                    *(uint32_t*)(Ch + (size_t)r0 * 256 + c0) = pack_h2(v0, v1);
                if (r0 + 8 < M)
                    *(uint32_t*)(Ch + (size_t)(r0 + 8) * 256 + c0) = pack_h2(v2, v3);
            } else {
                if (r0 < M)
                    *(float2*)(Cf + (size_t)r0 * 256 + c0) = make_float2(v0, v1);
                if (r0 + 8 < M)
                    *(float2*)(Cf + (size_t)(r0 + 8) * 256 + c0) = make_float2(v2, v3);
            }
        }
    }
}

// ---------------- aggregation (warp per node), fp32 in -> fp16 out ---------
// out[i] = POST( dinv[i]^2 * t[i] + sum_e w_e * t[col_e] )
template <int VEC, bool BIASRELU>   // VEC = WIDTH/128
__global__ void __launch_bounds__(256) agg_kernel(
    const float* __restrict__ t, __half* __restrict__ out, const float* __restrict__ bias)
{
    const int WIDTH = VEC * 128;
    int wrp = (blockIdx.x * blockDim.x + threadIdx.x) >> 5;
    int lane = threadIdx.x & 31;
    if (wrp >= N_NODES) return;
    const int i = wrp;

    const float4* rowi = (const float4*)(t + (size_t)i * WIDTH);
    float di = g_dinv[i];
    float ws = di * di;
    float4 acc[VEC];
#pragma unroll
    for (int v = 0; v < VEC; v++) {
        acc[v] = f4_zero();
        f4_fma(ws, rowi[lane + 32 * v], acc[v]);
    }
    const int e0 = g_rowptr[i], e1 = g_rowptr[i + 1];
    int e = e0;
    for (; e + 2 <= e1; e += 2) {
        int   c0 = g_col[e],     c1 = g_col[e + 1];
        float w0 = g_w[e],       w1 = g_w[e + 1];
        const float4* r0 = (const float4*)(t + (size_t)c0 * WIDTH);
        const float4* r1 = (const float4*)(t + (size_t)c1 * WIDTH);
        float4 u0[VEC], u1[VEC];
#pragma unroll
        for (int v = 0; v < VEC; v++) { u0[v] = r0[lane + 32 * v]; u1[v] = r1[lane + 32 * v]; }
#pragma unroll
        for (int v = 0; v < VEC; v++) { f4_fma(w0, u0[v], acc[v]); f4_fma(w1, u1[v], acc[v]); }
    }
    if (e < e1) {
        int   c  = g_col[e];
        float we = g_w[e];
        const float4* rowc = (const float4*)(t + (size_t)c * WIDTH);
#pragma unroll
        for (int v = 0; v < VEC; v++)
            f4_fma(we, rowc[lane + 32 * v], acc[v]);
    }
#pragma unroll
    for (int v = 0; v < VEC; v++) {
        float4 o = acc[v];
        if (BIASRELU) {
            float4 b = ((const float4*)bias)[lane + 32 * v];
            o.x = fmaxf(o.x + b.x, 0.f); o.y = fmaxf(o.y + b.y, 0.f);
            o.z = fmaxf(o.z + b.z, 0.f); o.w = fmaxf(o.w + b.w, 0.f);
        }
        uint2 p;
        p.x = pack_h2(o.x, o.y);
        p.y = pack_h2(o.z, o.w);
        *(uint2*)(out + (size_t)i * WIDTH + (lane + 32 * v) * 4) = p;
    }
}

// ---------------- mean pool (h fp16 -> pool fp32) ----------------
__device__ __forceinline__ int lower_bound_i(const int* a, int n, int key) {
    int lo = 0, hi = n;
    while (lo < hi) {
        int mid = (lo + hi) >> 1;
        if (a[mid] < key) lo = mid + 1; else hi = mid;
    }
    return lo;
}
__global__ void __launch_bounds__(256) pool_kernel(
    const __half* __restrict__ h, const int* __restrict__ batch)
{
    int g = blockIdx.x;
    int lo = lower_bound_i(batch, N_NODES, g);
    int hi = lower_bound_i(batch, N_NODES, g + 1);
    int cnt = hi - lo;
    int f = threadIdx.x;
    float acc = 0.f;
    for (int i = lo; i < hi; i++)
        acc += __half2float(h[(size_t)i * HID + f]);
    g_pool[(size_t)g * HID + f] = acc / fmaxf((float)cnt, 1.0f);
}

// ---------------- mma.sync tf32 GEMM (MLP head, fp32 in/out) ---------------
#define SROW 136
#define GEMM_TILE_FLOATS (32 * SROW)
#define GEMM_SMEM_BYTES (4 * GEMM_TILE_FLOATS * 4)

__device__ __forceinline__ int aidx(int k, int m) {
    return k * SROW + (m ^ (((k >> 2) & 7) << 2));
}

template <bool BIAS, bool RELU>
__global__ void __launch_bounds__(256) gemm_tf32_kernel(
    const float* __restrict__ A, const float* __restrict__ B,
    const float* __restrict__ bias, float* __restrict__ C,
    int M, int N, int K)
{
    extern __shared__ float smem[];
    const int tid = threadIdx.x;
    const int lane = tid & 31;
    const int warp = tid >> 5;
    const int wm = warp >> 2, wn = warp & 3;
    const int g = lane >> 2, tig = lane & 3;
    const int brow = blockIdx.x, bcol = blockIdx.y;

    float acc[4][4][4];
#pragma unroll
    for (int im = 0; im < 4; im++)
#pragma unroll
        for (int in = 0; in < 4; in++)
#pragma unroll
            for (int c = 0; c < 4; c++) acc[im][in][c] = 0.f;

    float4 va[4], vb[4];
    auto load_tiles = [&](int k0) {
#pragma unroll
        for (int it = 0; it < 4; it++) {
            int f = tid + it * 256;
            int r = f >> 3, kc4 = (f & 7) << 2;
            int grow = brow * 128 + r;
            va[it] = f4_zero();
            if (grow < M) va[it] = *(const float4*)(A + (size_t)grow * K + k0 + kc4);
        }
#pragma unroll
        for (int it = 0; it < 4; it++) {
            int f = tid + it * 256;
            int kr = f >> 5, c4 = (f & 31) << 2;
            int gcol = bcol * 128 + c4;
            vb[it] = f4_zero();
            if (gcol + 3 < N) vb[it] = *(const float4*)(B + (size_t)(k0 + kr) * N + gcol);
            else if (gcol < N) {
                vb[it].x = B[(size_t)(k0 + kr) * N + gcol];
                if (gcol + 1 < N) vb[it].y = B[(size_t)(k0 + kr) * N + gcol + 1];
                if (gcol + 2 < N) vb[it].z = B[(size_t)(k0 + kr) * N + gcol + 2];
            }
        }
    };
    auto store_tiles = [&](int b) {
        float* Asb = smem + b * GEMM_TILE_FLOATS;
        float* Bsb = smem + (2 + b) * GEMM_TILE_FLOATS;
#pragma unroll
        for (int it = 0; it < 4; it++) {
            int f = tid + it * 256;
            int r = f >> 3, kc4 = (f & 7) << 2;
            Asb[aidx(kc4 + 0, r)] = tf32f(va[it].x);
            Asb[aidx(kc4 + 1, r)] = tf32f(va[it].y);
            Asb[aidx(kc4 + 2, r)] = tf32f(va[it].z);
            Asb[aidx(kc4 + 3, r)] = tf32f(va[it].w);
        }
#pragma unroll
        for (int it = 0; it < 4; it++) {
            int f = tid + it * 256;
            int kr = f >> 5, c4 = (f & 31) << 2;
            float4 w;
            w.x = tf32f(vb[it].x); w.y = tf32f(vb[it].y);
            w.z = tf32f(vb[it].z); w.w = tf32f(vb[it].w);
            *(float4*)&Bsb[kr * SROW + c4] = w;
        }
    };

    const int nk = K >> 5;
    load_tiles(0);
    store_tiles(0);
    __syncthreads();

    for (int tk = 0; tk < nk; tk++) {
        const int cur = tk & 1;
        if (tk + 1 < nk) load_tiles((tk + 1) << 5);
        const float* Asb = smem + cur * GEMM_TILE_FLOATS;
        const float* Bsb = smem + (2 + cur) * GEMM_TILE_FLOATS;
#pragma unroll
        for (int ks = 0; ks < 4; ks++) {
            const int kk = ks * 8;
            uint32_t af[4][4], bf[4][2];
#pragma unroll
            for (int im = 0; im < 4; im++) {
                int m0 = wm * 64 + im * 16;
                af[im][0] = __float_as_uint(Asb[aidx(kk + tig,     m0 + g    )]);
                af[im][1] = __float_as_uint(Asb[aidx(kk + tig,     m0 + g + 8)]);
                af[im][2] = __float_as_uint(Asb[aidx(kk + tig + 4, m0 + g    )]);
                af[im][3] = __float_as_uint(Asb[aidx(kk + tig + 4, m0 + g + 8)]);
            }
#pragma unroll
            for (int in = 0; in < 4; in++) {
                int n0 = wn * 32 + in * 8;
                bf[in][0] = __float_as_uint(Bsb[(kk + tig    ) * SROW + n0 + g]);
                bf[in][1] = __float_as_uint(Bsb[(kk + tig + 4) * SROW + n0 + g]);
            }
#pragma unroll
            for (int im = 0; im < 4; im++)
#pragma unroll
                for (int in = 0; in < 4; in++) {
                    asm volatile(
                        "mma.sync.aligned.m16n8k8.row.col.f32.tf32.tf32.f32 "
                        "{%0,%1,%2,%3}, {%4,%5,%6,%7}, {%8,%9}, {%0,%1,%2,%3};\n"
                        : "+f"(acc[im][in][0]), "+f"(acc[im][in][1]),
                          "+f"(acc[im][in][2]), "+f"(acc[im][in][3])
                        : "r"(af[im][0]), "r"(af[im][1]), "r"(af[im][2]), "r"(af[im][3]),
                          "r"(bf[in][0]), "r"(bf[in][1]));
                }
        }
        if (tk + 1 < nk) store_tiles(1 - cur);
        __syncthreads();
    }

#pragma unroll
    for (int im = 0; im < 4; im++) {
        int r0 = brow * 128 + wm * 64 + im * 16 + g;
#pragma unroll
        for (int in = 0; in < 4; in++) {
            int c0 = bcol * 128 + wn * 32 + in * 8 + tig * 2;
            if (c0 >= N) continue;
            float b0v = 0.f, b1v = 0.f;
            if (BIAS) { b0v = bias[c0]; if (c0 + 1 < N) b1v = bias[c0 + 1]; }
            if (r0 < M) {
                float v0 = acc[im][in][0] + b0v;
                float v1 = acc[im][in][1] + b1v;
                if (RELU) { v0 = fmaxf(v0, 0.f); v1 = fmaxf(v1, 0.f); }
                C[(size_t)r0 * N + c0] = v0;
                if (c0 + 1 < N) C[(size_t)r0 * N + c0 + 1] = v1;
            }
            if (r0 + 8 < M) {
                float v2 = acc[im][in][2] + b0v;
                float v3 = acc[im][in][3] + b1v;
                if (RELU) { v2 = fmaxf(v2, 0.f); v3 = fmaxf(v3, 0.f); }
                C[(size_t)(r0 + 8) * N + c0] = v2;
                if (c0 + 1 < N) C[(size_t)(r0 + 8) * N + c0 + 1] = v3;
            }
        }
    }
}

// ---------------- launch ----------------
extern "C" void kernel_launch(void* const* d_in, const int* in_sizes, int n_in,
                              void* d_out, int out_size)
{
    const float* x    = (const float*)d_in[0];
    const int*   ei   = (const int*)d_in[1];
    const int*   batc = (const int*)d_in[2];
    const float *W1 = (const float*)d_in[3],  *b1 = (const float*)d_in[4];
    const float *W2 = (const float*)d_in[5],  *b2 = (const float*)d_in[6];
    const float *W3 = (const float*)d_in[7],  *b3 = (const float*)d_in[8];
    const float *Wf1 = (const float*)d_in[9], *bf1 = (const float*)d_in[10];
    const float *Wf2 = (const float*)d_in[11], *bf2 = (const float*)d_in[12];
    float* out = (float*)d_out;

    const int* src = ei;
    const int* dst = ei + N_EDGES;

    float *t_buf, *pool_buf, *fc1_buf;
    __half *h_buf, *ax_buf, *w1t, *w2t, *w3t;
    cudaGetSymbolAddress((void**)&t_buf, g_t);
    cudaGetSymbolAddress((void**)&h_buf, g_h);
    cudaGetSymbolAddress((void**)&ax_buf, g_ax);
    cudaGetSymbolAddress((void**)&pool_buf, g_pool);
    cudaGetSymbolAddress((void**)&fc1_buf, g_fc1);
    cudaGetSymbolAddress((void**)&w1t, g_w1t);
    cudaGetSymbolAddress((void**)&w2t, g_w2t);
    cudaGetSymbolAddress((void**)&w3t, g_w3t);

    cudaFuncSetAttribute(gemm_h<true>,  cudaFuncAttributeMaxDynamicSharedMemorySize, HPIPE_SMEM);
    cudaFuncSetAttribute(gemm_h<false>, cudaFuncAttributeMaxDynamicSharedMemorySize, HPIPE_SMEM);
    cudaFuncSetAttribute(gemm_tf32_kernel<true, true>,  cudaFuncAttributeMaxDynamicSharedMemorySize, GEMM_SMEM_BYTES);
    cudaFuncSetAttribute(gemm_tf32_kernel<true, false>, cudaFuncAttributeMaxDynamicSharedMemorySize, GEMM_SMEM_BYTES);

    const int aggBlocks = (N_NODES * 32 + 255) / 256;
    const int tcGrid = (N_NODES + 127) / 128;   // 391

    // --- preprocessing + weight transforms ---
    k_init_deg<<<(N_NODES + 255) / 256, 256>>>();
    k_count<<<(N_EDGES + 255) / 256, 256>>>(dst);
    k_dinv_bsum<<<SCAN_NB, 256>>>();
    k_scatter<<<SCAN_NB, 256>>>();
    k_fill<<<(N_EDGES + 255) / 256, 256>>>(src, dst);
    k_transpose<<<dim3(4, 8), dim3(32, 8)>>>(W1, w1t, 128, 256);
    k_transpose<<<dim3(8, 8), dim3(32, 8)>>>(W2, w2t, 256, 256);
    k_transpose<<<dim3(8, 8), dim3(32, 8)>>>(W3, w3t, 256, 256);

    // --- layer 1: ax = fp16(A_norm @ x) ; h = fp16(relu(ax @ W1 + b1)) ---
    agg_kernel<1, false><<<aggBlocks, 256>>>(x, ax_buf, nullptr);
    gemm_h<true><<<tcGrid, 256, HPIPE_SMEM>>>(ax_buf, w1t, b1, nullptr, h_buf, N_NODES, 128);
    // --- layer 2: t = h @ W2 (fp32) ; h = fp16(relu(A_norm @ t + b2)) ---
    gemm_h<false><<<tcGrid, 256, HPIPE_SMEM>>>(h_buf, w2t, nullptr, t_buf, nullptr, N_NODES, 256);
    agg_kernel<2, true><<<aggBlocks, 256>>>(t_buf, h_buf, b2);
    // --- layer 3 ---
    gemm_h<false><<<tcGrid, 256, HPIPE_SMEM>>>(h_buf, w3t, nullptr, t_buf, nullptr, N_NODES, 256);
    agg_kernel<2, true><<<aggBlocks, 256>>>(t_buf, h_buf, b3);

    // --- mean pool ---
    pool_kernel<<<N_GRAPHS, 256>>>(h_buf, batc);

    // --- MLP head (tf32, fp32 in/out) ---
    dim3 gridM((N_GRAPHS + 127) / 128, 1);
    gemm_tf32_kernel<true, true ><<<gridM, 256, GEMM_SMEM_BYTES>>>(pool_buf, Wf1, bf1, fc1_buf, N_GRAPHS, 128, HID);
    gemm_tf32_kernel<true, false><<<gridM, 256, GEMM_SMEM_BYTES>>>(fc1_buf, Wf2, bf2, out, N_GRAPHS, 32, 128);
}

// round 16
// speedup vs baseline: 3.4654x; 1.0628x over previous
#include <cuda_runtime.h>
#include <cuda_fp16.h>
#include <math.h>
#include <stdint.h>

#define N_NODES 50000
#define N_EDGES 300000
#define N_GRAPHS 2048
#define HID 256
#define SCAN_NB ((N_NODES + 255) / 256)   // 196

// ---------------- scratch (static __device__, no allocation) ----------------
__device__ int    g_deg[N_NODES];
__device__ float  g_dinv[N_NODES];
__device__ int    g_rowptr[N_NODES + 1];
__device__ int    g_cursor[N_NODES];
__device__ int    g_col[N_EDGES];
__device__ float  g_w[N_EDGES];
__device__ int    g_bsum[256];
__device__ __half g_t[(size_t)N_NODES * HID];          // GEMM output (fp16)
__device__ __half g_h[(size_t)N_NODES * HID];          // activations (fp16)
__device__ __half g_ax[(size_t)N_NODES * 128];         // layer-1 agg(x) (fp16)
__device__ float  g_pool[(size_t)N_GRAPHS * HID];
__device__ float  g_fc1[(size_t)N_GRAPHS * 128];
__device__ __half g_w1t[256 * 128];   // W1^T [n][k] fp16
__device__ __half g_w2t[256 * 256];
__device__ __half g_w3t[256 * 256];

// ---------------- small helpers ----------------
__device__ __forceinline__ float4 f4_zero() { return make_float4(0.f, 0.f, 0.f, 0.f); }
__device__ __forceinline__ void f4_fma(float s, const float4& a, float4& acc) {
    acc.x = fmaf(s, a.x, acc.x); acc.y = fmaf(s, a.y, acc.y);
    acc.z = fmaf(s, a.z, acc.z); acc.w = fmaf(s, a.w, acc.w);
}
__device__ __forceinline__ uint32_t f2tf32(float f) {
    uint32_t r;
    asm("cvt.rna.tf32.f32 %0, %1;" : "=r"(r) : "f"(f));
    return r;
}
__device__ __forceinline__ float tf32f(float f) { return __uint_as_float(f2tf32(f)); }
__device__ __forceinline__ uint32_t smem_u32(const void* p) {
    uint32_t a;
    asm("{ .reg .u64 t; cvta.to.shared.u64 t, %1; cvt.u32.u64 %0, t; }" : "=r"(a) : "l"(p));
    return a;
}
__device__ __forceinline__ void cp16(uint32_t dst, const void* src, bool pred) {
    uint32_t sz = pred ? 16u : 0u;
    asm volatile("cp.async.cg.shared.global [%0], [%1], 16, %2;" :: "r"(dst), "l"(src), "r"(sz) : "memory");
}
#define CP_COMMIT() asm volatile("cp.async.commit_group;" ::: "memory")
#define CP_WAIT1()  asm volatile("cp.async.wait_group 1;" ::: "memory")

__device__ __forceinline__ uint32_t pack_h2(float a, float b) {
    __half2 h = __floats2half2_rn(a, b);
    return *(uint32_t*)&h;
}
__device__ __forceinline__ void h8_fma(float w, const uint4& u, float* acc) {
    const __half2* h = (const __half2*)&u;
#pragma unroll
    for (int j = 0; j < 4; j++) {
        float2 f = __half22float2(h[j]);
        acc[2 * j]     = fmaf(w, f.x, acc[2 * j]);
        acc[2 * j + 1] = fmaf(w, f.y, acc[2 * j + 1]);
    }
}

// ---------------- graph preprocessing ----------------
__global__ void k_init_deg() {
    int i = blockIdx.x * blockDim.x + threadIdx.x;
    if (i < N_NODES) g_deg[i] = 1;
}
__global__ void k_count(const int* __restrict__ dst) {
    int e = blockIdx.x * blockDim.x + threadIdx.x;
    if (e < N_EDGES) atomicAdd(&g_deg[dst[e]], 1);
}
__global__ void __launch_bounds__(256) k_dinv_bsum() {
    __shared__ int s_w[8];
    int idx = blockIdx.x * 256 + threadIdx.x;
    int lane = threadIdx.x & 31, warp = threadIdx.x >> 5;
    int v = 0;
    if (idx < N_NODES) {
        int d = g_deg[idx];
        g_dinv[idx] = rsqrtf((float)d);
        v = d - 1;
    }
    int s = v;
#pragma unroll
    for (int off = 16; off > 0; off >>= 1) s += __shfl_down_sync(0xffffffffu, s, off);
    if (lane == 0) s_w[warp] = s;
    __syncthreads();
    if (threadIdx.x == 0) {
        int t = 0;
#pragma unroll
        for (int w = 0; w < 8; w++) t += s_w[w];
        g_bsum[blockIdx.x] = t;
    }
}
// Scatter with fused block-sum scan.
__global__ void __launch_bounds__(256) k_scatter() {
    __shared__ int s_w[8];
    __shared__ int s_boff;
    const int t = threadIdx.x;
    const int lane = t & 31, warp = t >> 5;
    {
        int v = (t < SCAN_NB) ? g_bsum[t] : 0;
        int incl = v;
#pragma unroll
        for (int off = 1; off < 32; off <<= 1) {
            int u = __shfl_up_sync(0xffffffffu, incl, off);
            if (lane >= off) incl += u;
        }
        if (lane == 31) s_w[warp] = incl;
        __syncthreads();
        if (warp == 0 && lane < 8) {
            int u = s_w[lane];
            int wi = u;
#pragma unroll
            for (int off = 1; off < 8; off <<= 1) {
                int z = __shfl_up_sync(0xffu, wi, off);
                if (lane >= off) wi += z;
            }
            s_w[lane] = wi - u;
        }
        __syncthreads();
        int excl = s_w[warp] + incl - v;
        if (t == (int)blockIdx.x) s_boff = excl;
        if (blockIdx.x == 0 && t == SCAN_NB - 1) g_rowptr[N_NODES] = excl + v;
        __syncthreads();
    }
    int idx = blockIdx.x * 256 + t;
    int v = (idx < N_NODES) ? (g_deg[idx] - 1) : 0;
    int incl = v;
#pragma unroll
    for (int off = 1; off < 32; off <<= 1) {
        int u = __shfl_up_sync(0xffffffffu, incl, off);
        if (lane >= off) incl += u;
    }
    if (lane == 31) s_w[warp] = incl;
    __syncthreads();
    if (warp == 0 && lane < 8) {
        int u = s_w[lane];
        int wi = u;
#pragma unroll
        for (int off = 1; off < 8; off <<= 1) {
            int z = __shfl_up_sync(0xffu, wi, off);
            if (lane >= off) wi += z;
        }
        s_w[lane] = wi - u;
    }
    __syncthreads();
    if (idx < N_NODES) {
        int p = s_boff + s_w[warp] + incl - v;
        g_rowptr[idx] = p;
        g_cursor[idx] = p;
    }
}
__global__ void k_fill(const int* __restrict__ src, const int* __restrict__ dst) {
    int e = blockIdx.x * blockDim.x + threadIdx.x;
    if (e < N_EDGES) {
        int s = src[e], d = dst[e];
        int pos = atomicAdd(&g_cursor[d], 1);
        g_col[pos] = s;
        g_w[pos]   = g_dinv[s] * g_dinv[d];
    }
}

// ---------------- weight transpose + cvt: Wt[n][k] = fp16(W[k][n]) --------
__global__ void k_transpose(const float* __restrict__ W, __half* __restrict__ Wt, int K, int N) {
    __shared__ float t[32][33];
    int kb = blockIdx.x * 32, nb = blockIdx.y * 32;
    int tx = threadIdx.x, ty = threadIdx.y;   // 32 x 8
#pragma unroll
    for (int j = 0; j < 32; j += 8) {
        int k = kb + ty + j, n = nb + tx;
        if (k < K && n < N) t[ty + j][tx] = W[(size_t)k * N + n];
    }
    __syncthreads();
#pragma unroll
    for (int j = 0; j < 32; j += 8) {
        int n = nb + ty + j, k = kb + tx;
        if (n < N && k < K) Wt[(size_t)n * K + k] = __float2half_rn(t[tx][ty + j]);
    }
}

// ---------------- cp.async pipelined mma.sync fp16 GEMM --------------------
// C[M,256] = A[M,K] @ Bt^T, fp16 in, fp32 accumulate, fp16 out.
// BM=128, BN=256, BK=32, 256 threads = 8 warps, warp tile 64x64, m16n8k16.
// 80B row pitch: bank = (20g+tig)%32 bijective -> conflict-free.
#define HROWB 80
#define HSTAGE_A (128 * HROWB)
#define HSTAGE_B (256 * HROWB)
#define HSTAGE   (HSTAGE_A + HSTAGE_B)     // 30720 B
#define HPIPE_SMEM (3 * HSTAGE)            // 92160 B

template <bool BR>   // BR: bias + relu in epilogue
__global__ void __launch_bounds__(256, 1) gemm_h(
    const __half* __restrict__ A, const __half* __restrict__ Bt,
    const float* __restrict__ bias, __half* __restrict__ C,
    int M, int K)
{
    extern __shared__ char ps[];
    const int tid  = threadIdx.x;
    const int lane = tid & 31;
    const int warp = tid >> 5;
    const int wm   = warp >> 2;
    const int wn   = warp & 3;
    const int g    = lane >> 2;
    const int tig  = lane & 3;
    const int mbase = blockIdx.x * 128;
    const uint32_t sbase = smem_u32(ps);

    float acc[4][8][4];
#pragma unroll
    for (int im = 0; im < 4; im++)
#pragma unroll
        for (int in = 0; in < 8; in++)
#pragma unroll
            for (int c = 0; c < 4; c++) acc[im][in][c] = 0.f;

    auto prefetch = [&](int tk, int s) {
        const int k0 = tk << 5;            // in halves
        const uint32_t abuf = sbase + (uint32_t)s * HSTAGE;
        const uint32_t bbuf = abuf + HSTAGE_A;
#pragma unroll
        for (int it = 0; it < 2; it++) {   // A: 512 16B chunks
            int c = tid + it * 256;
            int r = c >> 2, q = c & 3;
            int grow = mbase + r;
            cp16(abuf + (uint32_t)(r * HROWB + q * 16),
                 A + (size_t)grow * K + k0 + q * 8, grow < M);
        }
#pragma unroll
        for (int it = 0; it < 4; it++) {   // B: 1024 16B chunks
            int c = tid + it * 256;
            int r = c >> 2, q = c & 3;
            cp16(bbuf + (uint32_t)(r * HROWB + q * 16),
                 Bt + (size_t)r * K + k0 + q * 8, true);
        }
    };

    const int nk = K >> 5;
    prefetch(0, 0); CP_COMMIT();
    if (nk > 1) prefetch(1, 1);
    CP_COMMIT();

    for (int tk = 0; tk < nk; tk++) {
        CP_WAIT1();
        __syncthreads();
        const int s = tk % 3;
        if (tk + 2 < nk) prefetch(tk + 2, (tk + 2) % 3);
        CP_COMMIT();

        const char* Ab = ps + (size_t)s * HSTAGE;
        const char* Bb = Ab + HSTAGE_A;
#pragma unroll
        for (int kc = 0; kc < 2; kc++) {
            const int kbyte = kc * 32 + tig * 4;
            uint32_t af[4][4], bf[8][2];
#pragma unroll
            for (int im = 0; im < 4; im++) {
                const char* ra = Ab + (wm * 64 + im * 16 + g) * HROWB;
                const char* rb = ra + 8 * HROWB;
                af[im][0] = *(const uint32_t*)(ra + kbyte);
                af[im][1] = *(const uint32_t*)(rb + kbyte);
                af[im][2] = *(const uint32_t*)(ra + kbyte + 16);
                af[im][3] = *(const uint32_t*)(rb + kbyte + 16);
            }
#pragma unroll
            for (int in = 0; in < 8; in++) {
                const char* rn = Bb + (wn * 64 + in * 8 + g) * HROWB;
                bf[in][0] = *(const uint32_t*)(rn + kbyte);
                bf[in][1] = *(const uint32_t*)(rn + kbyte + 16);
            }
#pragma unroll
            for (int im = 0; im < 4; im++)
#pragma unroll
                for (int in = 0; in < 8; in++) {
                    asm volatile(
                        "mma.sync.aligned.m16n8k16.row.col.f32.f16.f16.f32 "
                        "{%0,%1,%2,%3}, {%4,%5,%6,%7}, {%8,%9}, {%0,%1,%2,%3};\n"
                        : "+f"(acc[im][in][0]), "+f"(acc[im][in][1]),
                          "+f"(acc[im][in][2]), "+f"(acc[im][in][3])
                        : "r"(af[im][0]), "r"(af[im][1]), "r"(af[im][2]), "r"(af[im][3]),
                          "r"(bf[in][0]), "r"(bf[in][1]));
                }
        }
    }

    // epilogue: fp16 output, optional bias+relu
#pragma unroll
    for (int im = 0; im < 4; im++) {
        int r0 = mbase + wm * 64 + im * 16 + g;
#pragma unroll
        for (int in = 0; in < 8; in++) {
            int c0 = wn * 64 + in * 8 + tig * 2;
            float v0 = acc[im][in][0], v1 = acc[im][in][1];
            float v2 = acc[im][in][2], v3 = acc[im][in][3];
            if (BR) {
                float b0 = bias[c0], b1 = bias[c0 + 1];
                v0 = fmaxf(v0 + b0, 0.f); v1 = fmaxf(v1 + b1, 0.f);
                v2 = fmaxf(v2 + b0, 0.f); v3 = fmaxf(v3 + b1, 0.f);
            }
            if (r0 < M)
                *(uint32_t*)(C + (size_t)r0 * 256 + c0) = pack_h2(v0, v1);
            if (r0 + 8 < M)
                *(uint32_t*)(C + (size_t)(r0 + 8) * 256 + c0) = pack_h2(v2, v3);
        }
    }
}

// ---------------- layer-1 aggregation: fp32 x (width 128) -> fp16 ax -------
__global__ void __launch_bounds__(256) agg_x_kernel(
    const float* __restrict__ t, __half* __restrict__ out)
{
    int wrp = (blockIdx.x * blockDim.x + threadIdx.x) >> 5;
    int lane = threadIdx.x & 31;
    if (wrp >= N_NODES) return;
    const int i = wrp;

    const float4* rowi = (const float4*)(t + (size_t)i * 128);
    float di = g_dinv[i];
    float ws = di * di;
    float4 acc = f4_zero();
    f4_fma(ws, rowi[lane], acc);
    const int e0 = g_rowptr[i], e1 = g_rowptr[i + 1];
    int e = e0;
    for (; e + 2 <= e1; e += 2) {
        int   c0 = g_col[e],     c1 = g_col[e + 1];
        float w0 = g_w[e],       w1 = g_w[e + 1];
        float4 u0 = ((const float4*)(t + (size_t)c0 * 128))[lane];
        float4 u1 = ((const float4*)(t + (size_t)c1 * 128))[lane];
        f4_fma(w0, u0, acc);
        f4_fma(w1, u1, acc);
    }
    if (e < e1) {
        float4 u = ((const float4*)(t + (size_t)g_col[e] * 128))[lane];
        f4_fma(g_w[e], u, acc);
    }
    uint2 p;
    p.x = pack_h2(acc.x, acc.y);
    p.y = pack_h2(acc.z, acc.w);
    *(uint2*)(out + (size_t)i * 128 + lane * 4) = p;
}

// ---------------- fp16 aggregation (width 256): t fp16 -> h fp16 -----------
// out[i] = fp16(relu(bias + dinv^2 * t[i] + sum_e w_e * t[col_e])), fp32 accum
__global__ void __launch_bounds__(256) agg_h_kernel(
    const __half* __restrict__ t, __half* __restrict__ out, const float* __restrict__ bias)
{
    int wrp = (blockIdx.x * blockDim.x + threadIdx.x) >> 5;
    int lane = threadIdx.x & 31;
    if (wrp >= N_NODES) return;
    const int i = wrp;
    const int off = lane * 8;            // 8 halves per lane

    float acc[8];
    float di = g_dinv[i];
    float ws = di * di;
    {
        uint4 u = *(const uint4*)(t + (size_t)i * 256 + off);
#pragma unroll
        for (int j = 0; j < 8; j++) acc[j] = 0.f;
        h8_fma(ws, u, acc);
    }
    const int e0 = g_rowptr[i], e1 = g_rowptr[i + 1];
    int e = e0;
    for (; e + 2 <= e1; e += 2) {
        int   c0 = g_col[e],     c1 = g_col[e + 1];
        float w0 = g_w[e],       w1 = g_w[e + 1];
        uint4 u0 = *(const uint4*)(t + (size_t)c0 * 256 + off);
        uint4 u1 = *(const uint4*)(t + (size_t)c1 * 256 + off);
        h8_fma(w0, u0, acc);
        h8_fma(w1, u1, acc);
    }
    if (e < e1) {
        uint4 u = *(const uint4*)(t + (size_t)g_col[e] * 256 + off);
        h8_fma(g_w[e], u, acc);
    }
    float4 b0 = *(const float4*)(bias + off);
    float4 b1 = *(const float4*)(bias + off + 4);
    float o0 = fmaxf(acc[0] + b0.x, 0.f), o1 = fmaxf(acc[1] + b0.y, 0.f);
    float o2 = fmaxf(acc[2] + b0.z, 0.f), o3 = fmaxf(acc[3] + b0.w, 0.f);
    float o4 = fmaxf(acc[4] + b1.x, 0.f), o5 = fmaxf(acc[5] + b1.y, 0.f);
    float o6 = fmaxf(acc[6] + b1.z, 0.f), o7 = fmaxf(acc[7] + b1.w, 0.f);
    uint4 p;
    p.x = pack_h2(o0, o1); p.y = pack_h2(o2, o3);
    p.z = pack_h2(o4, o5); p.w = pack_h2(o6, o7);
    *(uint4*)(out + (size_t)i * 256 + off) = p;
}

// ---------------- mean pool (h fp16 -> pool fp32) ----------------
__device__ __forceinline__ int lower_bound_i(const int* a, int n, int key) {
    int lo = 0, hi = n;
    while (lo < hi) {
        int mid = (lo + hi) >> 1;
        if (a[mid] < key) lo = mid + 1; else hi = mid;
    }
    return lo;
}
__global__ void __launch_bounds__(256) pool_kernel(
    const __half* __restrict__ h, const int* __restrict__ batch)
{
    int g = blockIdx.x;
    int lo = lower_bound_i(batch, N_NODES, g);
    int hi = lower_bound_i(batch, N_NODES, g + 1);
    int cnt = hi - lo;
    int f = threadIdx.x;
    float acc = 0.f;
    for (int i = lo; i < hi; i++)
        acc += __half2float(h[(size_t)i * HID + f]);
    g_pool[(size_t)g * HID + f] = acc / fmaxf((float)cnt, 1.0f);
}

// ---------------- mma.sync tf32 GEMM (MLP head, fp32 in/out) ---------------
#define SROW 136
#define GEMM_TILE_FLOATS (32 * SROW)
#define GEMM_SMEM_BYTES (4 * GEMM_TILE_FLOATS * 4)

__device__ __forceinline__ int aidx(int k, int m) {
    return k * SROW + (m ^ (((k >> 2) & 7) << 2));
}

template <bool BIAS, bool RELU>
__global__ void __launch_bounds__(256) gemm_tf32_kernel(
    const float* __restrict__ A, const float* __restrict__ B,
    const float* __restrict__ bias, float* __restrict__ C,
    int M, int N, int K)
{
    extern __shared__ float smem[];
    const int tid = threadIdx.x;
    const int lane = tid & 31;
    const int warp = tid >> 5;
    const int wm = warp >> 2, wn = warp & 3;
    const int g = lane >> 2, tig = lane & 3;
    const int brow = blockIdx.x, bcol = blockIdx.y;

    float acc[4][4][4];
#pragma unroll
    for (int im = 0; im < 4; im++)
#pragma unroll
        for (int in = 0; in < 4; in++)
#pragma unroll
            for (int c = 0; c < 4; c++) acc[im][in][c] = 0.f;

    float4 va[4], vb[4];
    auto load_tiles = [&](int k0) {
#pragma unroll
        for (int it = 0; it < 4; it++) {
            int f = tid + it * 256;
            int r = f >> 3, kc4 = (f & 7) << 2;
            int grow = brow * 128 + r;
            va[it] = f4_zero();
            if (grow < M) va[it] = *(const float4*)(A + (size_t)grow * K + k0 + kc4);
        }
#pragma unroll
        for (int it = 0; it < 4; it++) {
            int f = tid + it * 256;
            int kr = f >> 5, c4 = (f & 31) << 2;
            int gcol = bcol * 128 + c4;
            vb[it] = f4_zero();
            if (gcol + 3 < N) vb[it] = *(const float4*)(B + (size_t)(k0 + kr) * N + gcol);
            else if (gcol < N) {
                vb[it].x = B[(size_t)(k0 + kr) * N + gcol];
                if (gcol + 1 < N) vb[it].y = B[(size_t)(k0 + kr) * N + gcol + 1];
                if (gcol + 2 < N) vb[it].z = B[(size_t)(k0 + kr) * N + gcol + 2];
            }
        }
    };
    auto store_tiles = [&](int b) {
        float* Asb = smem + b * GEMM_TILE_FLOATS;
        float* Bsb = smem + (2 + b) * GEMM_TILE_FLOATS;
#pragma unroll
        for (int it = 0; it < 4; it++) {
            int f = tid + it * 256;
            int r = f >> 3, kc4 = (f & 7) << 2;
            Asb[aidx(kc4 + 0, r)] = tf32f(va[it].x);
            Asb[aidx(kc4 + 1, r)] = tf32f(va[it].y);
            Asb[aidx(kc4 + 2, r)] = tf32f(va[it].z);
            Asb[aidx(kc4 + 3, r)] = tf32f(va[it].w);
        }
#pragma unroll
        for (int it = 0; it < 4; it++) {
            int f = tid + it * 256;
            int kr = f >> 5, c4 = (f & 31) << 2;
            float4 w;
            w.x = tf32f(vb[it].x); w.y = tf32f(vb[it].y);
            w.z = tf32f(vb[it].z); w.w = tf32f(vb[it].w);
            *(float4*)&Bsb[kr * SROW + c4] = w;
        }
    };

    const int nk = K >> 5;
    load_tiles(0);
    store_tiles(0);
    __syncthreads();

    for (int tk = 0; tk < nk; tk++) {
        const int cur = tk & 1;
        if (tk + 1 < nk) load_tiles((tk + 1) << 5);
        const float* Asb = smem + cur * GEMM_TILE_FLOATS;
        const float* Bsb = smem + (2 + cur) * GEMM_TILE_FLOATS;
#pragma unroll
        for (int ks = 0; ks < 4; ks++) {
            const int kk = ks * 8;
            uint32_t af[4][4], bf[4][2];
#pragma unroll
            for (int im = 0; im < 4; im++) {
                int m0 = wm * 64 + im * 16;
                af[im][0] = __float_as_uint(Asb[aidx(kk + tig,     m0 + g    )]);
                af[im][1] = __float_as_uint(Asb[aidx(kk + tig,     m0 + g + 8)]);
                af[im][2] = __float_as_uint(Asb[aidx(kk + tig + 4, m0 + g    )]);
                af[im][3] = __float_as_uint(Asb[aidx(kk + tig + 4, m0 + g + 8)]);
            }
#pragma unroll
            for (int in = 0; in < 4; in++) {
                int n0 = wn * 32 + in * 8;
                bf[in][0] = __float_as_uint(Bsb[(kk + tig    ) * SROW + n0 + g]);
                bf[in][1] = __float_as_uint(Bsb[(kk + tig + 4) * SROW + n0 + g]);
            }
#pragma unroll
            for (int im = 0; im < 4; im++)
#pragma unroll
                for (int in = 0; in < 4; in++) {
                    asm volatile(
                        "mma.sync.aligned.m16n8k8.row.col.f32.tf32.tf32.f32 "
                        "{%0,%1,%2,%3}, {%4,%5,%6,%7}, {%8,%9}, {%0,%1,%2,%3};\n"
                        : "+f"(acc[im][in][0]), "+f"(acc[im][in][1]),
                          "+f"(acc[im][in][2]), "+f"(acc[im][in][3])
                        : "r"(af[im][0]), "r"(af[im][1]), "r"(af[im][2]), "r"(af[im][3]),
                          "r"(bf[in][0]), "r"(bf[in][1]));
                }
        }
        if (tk + 1 < nk) store_tiles(1 - cur);
        __syncthreads();
    }

#pragma unroll
    for (int im = 0; im < 4; im++) {
        int r0 = brow * 128 + wm * 64 + im * 16 + g;
#pragma unroll
        for (int in = 0; in < 4; in++) {
            int c0 = bcol * 128 + wn * 32 + in * 8 + tig * 2;
            if (c0 >= N) continue;
            float b0v = 0.f, b1v = 0.f;
            if (BIAS) { b0v = bias[c0]; if (c0 + 1 < N) b1v = bias[c0 + 1]; }
            if (r0 < M) {
                float v0 = acc[im][in][0] + b0v;
                float v1 = acc[im][in][1] + b1v;
                if (RELU) { v0 = fmaxf(v0, 0.f); v1 = fmaxf(v1, 0.f); }
                C[(size_t)r0 * N + c0] = v0;
                if (c0 + 1 < N) C[(size_t)r0 * N + c0 + 1] = v1;
            }
            if (r0 + 8 < M) {
                float v2 = acc[im][in][2] + b0v;
                float v3 = acc[im][in][3] + b1v;
                if (RELU) { v2 = fmaxf(v2, 0.f); v3 = fmaxf(v3, 0.f); }
                C[(size_t)(r0 + 8) * N + c0] = v2;
                if (c0 + 1 < N) C[(size_t)(r0 + 8) * N + c0 + 1] = v3;
            }
        }
    }
}

// ---------------- launch ----------------
extern "C" void kernel_launch(void* const* d_in, const int* in_sizes, int n_in,
                              void* d_out, int out_size)
{
    const float* x    = (const float*)d_in[0];
    const int*   ei   = (const int*)d_in[1];
    const int*   batc = (const int*)d_in[2];
    const float *W1 = (const float*)d_in[3],  *b1 = (const float*)d_in[4];
    const float *W2 = (const float*)d_in[5],  *b2 = (const float*)d_in[6];
    const float *W3 = (const float*)d_in[7],  *b3 = (const float*)d_in[8];
    const float *Wf1 = (const float*)d_in[9], *bf1 = (const float*)d_in[10];
    const float *Wf2 = (const float*)d_in[11], *bf2 = (const float*)d_in[12];
    float* out = (float*)d_out;

    const int* src = ei;
    const int* dst = ei + N_EDGES;

    float *pool_buf, *fc1_buf;
    __half *t_buf, *h_buf, *ax_buf, *w1t, *w2t, *w3t;
    cudaGetSymbolAddress((void**)&t_buf, g_t);
    cudaGetSymbolAddress((void**)&h_buf, g_h);
    cudaGetSymbolAddress((void**)&ax_buf, g_ax);
    cudaGetSymbolAddress((void**)&pool_buf, g_pool);
    cudaGetSymbolAddress((void**)&fc1_buf, g_fc1);
    cudaGetSymbolAddress((void**)&w1t, g_w1t);
    cudaGetSymbolAddress((void**)&w2t, g_w2t);
    cudaGetSymbolAddress((void**)&w3t, g_w3t);

    cudaFuncSetAttribute(gemm_h<true>,  cudaFuncAttributeMaxDynamicSharedMemorySize, HPIPE_SMEM);
    cudaFuncSetAttribute(gemm_h<false>, cudaFuncAttributeMaxDynamicSharedMemorySize, HPIPE_SMEM);
    cudaFuncSetAttribute(gemm_tf32_kernel<true, true>,  cudaFuncAttributeMaxDynamicSharedMemorySize, GEMM_SMEM_BYTES);
    cudaFuncSetAttribute(gemm_tf32_kernel<true, false>, cudaFuncAttributeMaxDynamicSharedMemorySize, GEMM_SMEM_BYTES);

    const int aggBlocks = (N_NODES * 32 + 255) / 256;
    const int tcGrid = (N_NODES + 127) / 128;   // 391

    // --- preprocessing + weight transforms ---
    k_init_deg<<<(N_NODES + 255) / 256, 256>>>();
    k_count<<<(N_EDGES + 255) / 256, 256>>>(dst);
    k_dinv_bsum<<<SCAN_NB, 256>>>();
    k_scatter<<<SCAN_NB, 256>>>();
    k_fill<<<(N_EDGES + 255) / 256, 256>>>(src, dst);
    k_transpose<<<dim3(4, 8), dim3(32, 8)>>>(W1, w1t, 128, 256);
    k_transpose<<<dim3(8, 8), dim3(32, 8)>>>(W2, w2t, 256, 256);
    k_transpose<<<dim3(8, 8), dim3(32, 8)>>>(W3, w3t, 256, 256);

    // --- layer 1: ax = fp16(A_norm @ x) ; h = fp16(relu(ax @ W1 + b1)) ---
    agg_x_kernel<<<aggBlocks, 256>>>(x, ax_buf);
    gemm_h<true><<<tcGrid, 256, HPIPE_SMEM>>>(ax_buf, w1t, b1, h_buf, N_NODES, 128);
    // --- layer 2: t = fp16(h @ W2) ; h = fp16(relu(A_norm @ t + b2)) ---
    gemm_h<false><<<tcGrid, 256, HPIPE_SMEM>>>(h_buf, w2t, nullptr, t_buf, N_NODES, 256);
    agg_h_kernel<<<aggBlocks, 256>>>(t_buf, h_buf, b2);
    // --- layer 3 ---
    gemm_h<false><<<tcGrid, 256, HPIPE_SMEM>>>(h_buf, w3t, nullptr, t_buf, N_NODES, 256);
    agg_h_kernel<<<aggBlocks, 256>>>(t_buf, h_buf, b3);

    // --- mean pool ---
    pool_kernel<<<N_GRAPHS, 256>>>(h_buf, batc);

    // --- MLP head (tf32, fp32 in/out) ---
    dim3 gridM((N_GRAPHS + 127) / 128, 1);
    gemm_tf32_kernel<true, true ><<<gridM, 256, GEMM_SMEM_BYTES>>>(pool_buf, Wf1, bf1, fc1_buf, N_GRAPHS, 128, HID);
    gemm_tf32_kernel<true, false><<<gridM, 256, GEMM_SMEM_BYTES>>>(fc1_buf, Wf2, bf2, out, N_GRAPHS, 32, 128);
}

// round 17
// speedup vs baseline: 3.5543x; 1.0256x over previous
#include <cuda_runtime.h>
#include <cuda_fp16.h>
#include <math.h>
#include <stdint.h>

#define N_NODES 50000
#define N_EDGES 300000
#define N_GRAPHS 2048
#define HID 256
#define SCAN_NB ((N_NODES + 255) / 256)   // 196

// ---------------- scratch (static __device__, no allocation) ----------------
__device__ int    g_deg[N_NODES];
__device__ float  g_dinv[N_NODES];
__device__ int    g_rowptr[N_NODES + 1];
__device__ int    g_cursor[N_NODES];
__device__ int    g_col[N_EDGES];
__device__ float  g_w[N_EDGES];
__device__ int    g_bsum[256];
__device__ __half g_t[(size_t)N_NODES * HID];          // GEMM output (fp16)
__device__ __half g_h[(size_t)N_NODES * HID];          // activations (fp16)
__device__ __half g_ax[(size_t)N_NODES * 128];         // layer-1 agg(x) (fp16)
__device__ float  g_pool[(size_t)N_GRAPHS * HID];
__device__ float  g_fc1[(size_t)N_GRAPHS * 128];
__device__ __half g_w1t[256 * 128];   // W1^T [n][k] fp16
__device__ __half g_w2t[256 * 256];
__device__ __half g_w3t[256 * 256];

// ---------------- small helpers ----------------
__device__ __forceinline__ float4 f4_zero() { return make_float4(0.f, 0.f, 0.f, 0.f); }
__device__ __forceinline__ void f4_fma(float s, const float4& a, float4& acc) {
    acc.x = fmaf(s, a.x, acc.x); acc.y = fmaf(s, a.y, acc.y);
    acc.z = fmaf(s, a.z, acc.z); acc.w = fmaf(s, a.w, acc.w);
}
__device__ __forceinline__ uint32_t f2tf32(float f) {
    uint32_t r;
    asm("cvt.rna.tf32.f32 %0, %1;" : "=r"(r) : "f"(f));
    return r;
}
__device__ __forceinline__ float tf32f(float f) { return __uint_as_float(f2tf32(f)); }
__device__ __forceinline__ uint32_t smem_u32(const void* p) {
    uint32_t a;
    asm("{ .reg .u64 t; cvta.to.shared.u64 t, %1; cvt.u32.u64 %0, t; }" : "=r"(a) : "l"(p));
    return a;
}
__device__ __forceinline__ void cp16(uint32_t dst, const void* src, bool pred) {
    uint32_t sz = pred ? 16u : 0u;
    asm volatile("cp.async.cg.shared.global [%0], [%1], 16, %2;" :: "r"(dst), "l"(src), "r"(sz) : "memory");
}
#define CP_COMMIT() asm volatile("cp.async.commit_group;" ::: "memory")
#define CP_WAIT1()  asm volatile("cp.async.wait_group 1;" ::: "memory")

__device__ __forceinline__ uint32_t pack_h2(float a, float b) {
    __half2 h = __floats2half2_rn(a, b);
    return *(uint32_t*)&h;
}
__device__ __forceinline__ void h8_fma(float w, const uint4& u, float* acc) {
    const __half2* h = (const __half2*)&u;
#pragma unroll
    for (int j = 0; j < 4; j++) {
        float2 f = __half22float2(h[j]);
        acc[2 * j]     = fmaf(w, f.x, acc[2 * j]);
        acc[2 * j + 1] = fmaf(w, f.y, acc[2 * j + 1]);
    }
}

// ---------------- graph preprocessing ----------------
__global__ void k_init_deg() {
    int i = blockIdx.x * blockDim.x + threadIdx.x;
    if (i < N_NODES) g_deg[i] = 1;
}
__global__ void k_count(const int* __restrict__ dst) {
    int e = blockIdx.x * blockDim.x + threadIdx.x;
    if (e < N_EDGES) atomicAdd(&g_deg[dst[e]], 1);
}
__global__ void __launch_bounds__(256) k_dinv_bsum() {
    __shared__ int s_w[8];
    int idx = blockIdx.x * 256 + threadIdx.x;
    int lane = threadIdx.x & 31, warp = threadIdx.x >> 5;
    int v = 0;
    if (idx < N_NODES) {
        int d = g_deg[idx];
        g_dinv[idx] = rsqrtf((float)d);
        v = d - 1;
    }
    int s = v;
#pragma unroll
    for (int off = 16; off > 0; off >>= 1) s += __shfl_down_sync(0xffffffffu, s, off);
    if (lane == 0) s_w[warp] = s;
    __syncthreads();
    if (threadIdx.x == 0) {
        int t = 0;
#pragma unroll
        for (int w = 0; w < 8; w++) t += s_w[w];
        g_bsum[blockIdx.x] = t;
    }
}
// Scatter with fused block-sum scan.
__global__ void __launch_bounds__(256) k_scatter() {
    __shared__ int s_w[8];
    __shared__ int s_boff;
    const int t = threadIdx.x;
    const int lane = t & 31, warp = t >> 5;
    {
        int v = (t < SCAN_NB) ? g_bsum[t] : 0;
        int incl = v;
#pragma unroll
        for (int off = 1; off < 32; off <<= 1) {
            int u = __shfl_up_sync(0xffffffffu, incl, off);
            if (lane >= off) incl += u;
        }
        if (lane == 31) s_w[warp] = incl;
        __syncthreads();
        if (warp == 0 && lane < 8) {
            int u = s_w[lane];
            int wi = u;
#pragma unroll
            for (int off = 1; off < 8; off <<= 1) {
                int z = __shfl_up_sync(0xffu, wi, off);
                if (lane >= off) wi += z;
            }
            s_w[lane] = wi - u;
        }
        __syncthreads();
        int excl = s_w[warp] + incl - v;
        if (t == (int)blockIdx.x) s_boff = excl;
        if (blockIdx.x == 0 && t == SCAN_NB - 1) g_rowptr[N_NODES] = excl + v;
        __syncthreads();
    }
    int idx = blockIdx.x * 256 + t;
    int v = (idx < N_NODES) ? (g_deg[idx] - 1) : 0;
    int incl = v;
#pragma unroll
    for (int off = 1; off < 32; off <<= 1) {
        int u = __shfl_up_sync(0xffffffffu, incl, off);
        if (lane >= off) incl += u;
    }
    if (lane == 31) s_w[warp] = incl;
    __syncthreads();
    if (warp == 0 && lane < 8) {
        int u = s_w[lane];
        int wi = u;
#pragma unroll
        for (int off = 1; off < 8; off <<= 1) {
            int z = __shfl_up_sync(0xffu, wi, off);
            if (lane >= off) wi += z;
        }
        s_w[lane] = wi - u;
    }
    __syncthreads();
    if (idx < N_NODES) {
        int p = s_boff + s_w[warp] + incl - v;
        g_rowptr[idx] = p;
        g_cursor[idx] = p;
    }
}
__global__ void k_fill(const int* __restrict__ src, const int* __restrict__ dst) {
    int e = blockIdx.x * blockDim.x + threadIdx.x;
    if (e < N_EDGES) {
        int s = src[e], d = dst[e];
        int pos = atomicAdd(&g_cursor[d], 1);
        g_col[pos] = s;
        g_w[pos]   = g_dinv[s] * g_dinv[d];
    }
}

// ---------------- weight transpose + cvt: Wt[n][k] = fp16(W[k][n]) --------
__global__ void k_transpose(const float* __restrict__ W, __half* __restrict__ Wt, int K, int N) {
    __shared__ float t[32][33];
    int kb = blockIdx.x * 32, nb = blockIdx.y * 32;
    int tx = threadIdx.x, ty = threadIdx.y;   // 32 x 8
#pragma unroll
    for (int j = 0; j < 32; j += 8) {
        int k = kb + ty + j, n = nb + tx;
        if (k < K && n < N) t[ty + j][tx] = W[(size_t)k * N + n];
    }
    __syncthreads();
#pragma unroll
    for (int j = 0; j < 32; j += 8) {
        int n = nb + ty + j, k = kb + tx;
        if (n < N && k < K) Wt[(size_t)n * K + k] = __float2half_rn(t[tx][ty + j]);
    }
}

// ---------------- cp.async pipelined mma.sync fp16 GEMM --------------------
// C[M,256] = A[M,K] @ Bt^T, fp16 in, fp32 accumulate, fp16 out.
// BM=128, BN=256, BK=32, 256 threads = 8 warps, warp tile 64x64, m16n8k16.
// 80B row pitch: bank = (20g+tig)%32 bijective -> conflict-free.
#define HROWB 80
#define HSTAGE_A (128 * HROWB)
#define HSTAGE_B (256 * HROWB)
#define HSTAGE   (HSTAGE_A + HSTAGE_B)     // 30720 B
#define HPIPE_SMEM (3 * HSTAGE)            // 92160 B

template <bool BR>   // BR: bias + relu in epilogue
__global__ void __launch_bounds__(256, 1) gemm_h(
    const __half* __restrict__ A, const __half* __restrict__ Bt,
    const float* __restrict__ bias, __half* __restrict__ C,
    int M, int K)
{
    extern __shared__ char ps[];
    const int tid  = threadIdx.x;
    const int lane = tid & 31;
    const int warp = tid >> 5;
    const int wm   = warp >> 2;
    const int wn   = warp & 3;
    const int g    = lane >> 2;
    const int tig  = lane & 3;
    const int mbase = blockIdx.x * 128;
    const uint32_t sbase = smem_u32(ps);

    float acc[4][8][4];
#pragma unroll
    for (int im = 0; im < 4; im++)
#pragma unroll
        for (int in = 0; in < 8; in++)
#pragma unroll
            for (int c = 0; c < 4; c++) acc[im][in][c] = 0.f;

    auto prefetch = [&](int tk, int s) {
        const int k0 = tk << 5;            // in halves
        const uint32_t abuf = sbase + (uint32_t)s * HSTAGE;
        const uint32_t bbuf = abuf + HSTAGE_A;
#pragma unroll
        for (int it = 0; it < 2; it++) {   // A: 512 16B chunks
            int c = tid + it * 256;
            int r = c >> 2, q = c & 3;
            int grow = mbase + r;
            cp16(abuf + (uint32_t)(r * HROWB + q * 16),
                 A + (size_t)grow * K + k0 + q * 8, grow < M);
        }
#pragma unroll
        for (int it = 0; it < 4; it++) {   // B: 1024 16B chunks
            int c = tid + it * 256;
            int r = c >> 2, q = c & 3;
            cp16(bbuf + (uint32_t)(r * HROWB + q * 16),
                 Bt + (size_t)r * K + k0 + q * 8, true);
        }
    };

    const int nk = K >> 5;
    prefetch(0, 0); CP_COMMIT();
    if (nk > 1) prefetch(1, 1);
    CP_COMMIT();

    for (int tk = 0; tk < nk; tk++) {
        CP_WAIT1();
        __syncthreads();
        const int s = tk % 3;
        if (tk + 2 < nk) prefetch(tk + 2, (tk + 2) % 3);
        CP_COMMIT();

        const char* Ab = ps + (size_t)s * HSTAGE;
        const char* Bb = Ab + HSTAGE_A;
#pragma unroll
        for (int kc = 0; kc < 2; kc++) {
            const int kbyte = kc * 32 + tig * 4;
            uint32_t af[4][4], bf[8][2];
#pragma unroll
            for (int im = 0; im < 4; im++) {
                const char* ra = Ab + (wm * 64 + im * 16 + g) * HROWB;
                const char* rb = ra + 8 * HROWB;
                af[im][0] = *(const uint32_t*)(ra + kbyte);
                af[im][1] = *(const uint32_t*)(rb + kbyte);
                af[im][2] = *(const uint32_t*)(ra + kbyte + 16);
                af[im][3] = *(const uint32_t*)(rb + kbyte + 16);
            }
#pragma unroll
            for (int in = 0; in < 8; in++) {
                const char* rn = Bb + (wn * 64 + in * 8 + g) * HROWB;
                bf[in][0] = *(const uint32_t*)(rn + kbyte);
                bf[in][1] = *(const uint32_t*)(rn + kbyte + 16);
            }
#pragma unroll
            for (int im = 0; im < 4; im++)
#pragma unroll
                for (int in = 0; in < 8; in++) {
                    asm volatile(
                        "mma.sync.aligned.m16n8k16.row.col.f32.f16.f16.f32 "
                        "{%0,%1,%2,%3}, {%4,%5,%6,%7}, {%8,%9}, {%0,%1,%2,%3};\n"
                        : "+f"(acc[im][in][0]), "+f"(acc[im][in][1]),
                          "+f"(acc[im][in][2]), "+f"(acc[im][in][3])
                        : "r"(af[im][0]), "r"(af[im][1]), "r"(af[im][2]), "r"(af[im][3]),
                          "r"(bf[in][0]), "r"(bf[in][1]));
                }
        }
    }

    // epilogue: fp16 output, optional bias+relu
#pragma unroll
    for (int im = 0; im < 4; im++) {
        int r0 = mbase + wm * 64 + im * 16 + g;
#pragma unroll
        for (int in = 0; in < 8; in++) {
            int c0 = wn * 64 + in * 8 + tig * 2;
            float v0 = acc[im][in][0], v1 = acc[im][in][1];
            float v2 = acc[im][in][2], v3 = acc[im][in][3];
            if (BR) {
                float b0 = bias[c0], b1 = bias[c0 + 1];
                v0 = fmaxf(v0 + b0, 0.f); v1 = fmaxf(v1 + b1, 0.f);
                v2 = fmaxf(v2 + b0, 0.f); v3 = fmaxf(v3 + b1, 0.f);
            }
            if (r0 < M)
                *(uint32_t*)(C + (size_t)r0 * 256 + c0) = pack_h2(v0, v1);
            if (r0 + 8 < M)
                *(uint32_t*)(C + (size_t)(r0 + 8) * 256 + c0) = pack_h2(v2, v3);
        }
    }
}

// ---------------- layer-1 aggregation: fp32 x (width 128) -> fp16 ax -------
// Edge loop unrolled x4 with batched loads (MLP=4).
__global__ void __launch_bounds__(256) agg_x_kernel(
    const float* __restrict__ t, __half* __restrict__ out)
{
    int wrp = (blockIdx.x * blockDim.x + threadIdx.x) >> 5;
    int lane = threadIdx.x & 31;
    if (wrp >= N_NODES) return;
    const int i = wrp;

    const float4* rowi = (const float4*)(t + (size_t)i * 128);
    float di = g_dinv[i];
    float ws = di * di;
    float4 acc = f4_zero();
    f4_fma(ws, rowi[lane], acc);
    const int e0 = g_rowptr[i], e1 = g_rowptr[i + 1];
    int e = e0;
    for (; e + 4 <= e1; e += 4) {
        int c0 = g_col[e], c1 = g_col[e + 1], c2 = g_col[e + 2], c3 = g_col[e + 3];
        float w0 = g_w[e], w1 = g_w[e + 1], w2 = g_w[e + 2], w3 = g_w[e + 3];
        float4 u0 = ((const float4*)(t + (size_t)c0 * 128))[lane];
        float4 u1 = ((const float4*)(t + (size_t)c1 * 128))[lane];
        float4 u2 = ((const float4*)(t + (size_t)c2 * 128))[lane];
        float4 u3 = ((const float4*)(t + (size_t)c3 * 128))[lane];
        f4_fma(w0, u0, acc);
        f4_fma(w1, u1, acc);
        f4_fma(w2, u2, acc);
        f4_fma(w3, u3, acc);
    }
    for (; e < e1; e++) {
        float4 u = ((const float4*)(t + (size_t)g_col[e] * 128))[lane];
        f4_fma(g_w[e], u, acc);
    }
    uint2 p;
    p.x = pack_h2(acc.x, acc.y);
    p.y = pack_h2(acc.z, acc.w);
    *(uint2*)(out + (size_t)i * 128 + lane * 4) = p;
}

// ---------------- fp16 aggregation (width 256): t fp16 -> h fp16 -----------
// out[i] = fp16(relu(bias + dinv^2 * t[i] + sum_e w_e * t[col_e])), fp32 accum
// Edge loop unrolled x4 with batched loads (MLP=4).
__global__ void __launch_bounds__(256) agg_h_kernel(
    const __half* __restrict__ t, __half* __restrict__ out, const float* __restrict__ bias)
{
    int wrp = (blockIdx.x * blockDim.x + threadIdx.x) >> 5;
    int lane = threadIdx.x & 31;
    if (wrp >= N_NODES) return;
    const int i = wrp;
    const int off = lane * 8;            // 8 halves per lane

    float acc[8];
    float di = g_dinv[i];
    float ws = di * di;
    {
        uint4 u = *(const uint4*)(t + (size_t)i * 256 + off);
#pragma unroll
        for (int j = 0; j < 8; j++) acc[j] = 0.f;
        h8_fma(ws, u, acc);
    }
    const int e0 = g_rowptr[i], e1 = g_rowptr[i + 1];
    int e = e0;
    for (; e + 4 <= e1; e += 4) {
        int c0 = g_col[e], c1 = g_col[e + 1], c2 = g_col[e + 2], c3 = g_col[e + 3];
        float w0 = g_w[e], w1 = g_w[e + 1], w2 = g_w[e + 2], w3 = g_w[e + 3];
        uint4 u0 = *(const uint4*)(t + (size_t)c0 * 256 + off);
        uint4 u1 = *(const uint4*)(t + (size_t)c1 * 256 + off);
        uint4 u2 = *(const uint4*)(t + (size_t)c2 * 256 + off);
        uint4 u3 = *(const uint4*)(t + (size_t)c3 * 256 + off);
        h8_fma(w0, u0, acc);
        h8_fma(w1, u1, acc);
        h8_fma(w2, u2, acc);
        h8_fma(w3, u3, acc);
    }
    for (; e < e1; e++) {
        uint4 u = *(const uint4*)(t + (size_t)g_col[e] * 256 + off);
        h8_fma(g_w[e], u, acc);
    }
    float4 b0 = *(const float4*)(bias + off);
    float4 b1 = *(const float4*)(bias + off + 4);
    float o0 = fmaxf(acc[0] + b0.x, 0.f), o1 = fmaxf(acc[1] + b0.y, 0.f);
    float o2 = fmaxf(acc[2] + b0.z, 0.f), o3 = fmaxf(acc[3] + b0.w, 0.f);
    float o4 = fmaxf(acc[4] + b1.x, 0.f), o5 = fmaxf(acc[5] + b1.y, 0.f);
    float o6 = fmaxf(acc[6] + b1.z, 0.f), o7 = fmaxf(acc[7] + b1.w, 0.f);
    uint4 p;
    p.x = pack_h2(o0, o1); p.y = pack_h2(o2, o3);
    p.z = pack_h2(o4, o5); p.w = pack_h2(o6, o7);
    *(uint4*)(out + (size_t)i * 256 + off) = p;
}

// ---------------- mean pool (h fp16 -> pool fp32) ----------------
__device__ __forceinline__ int lower_bound_i(const int* a, int n, int key) {
    int lo = 0, hi = n;
    while (lo < hi) {
        int mid = (lo + hi) >> 1;
        if (a[mid] < key) lo = mid + 1; else hi = mid;
    }
    return lo;
}
__global__ void __launch_bounds__(256) pool_kernel(
    const __half* __restrict__ h, const int* __restrict__ batch)
{
    int g = blockIdx.x;
    int lo = lower_bound_i(batch, N_NODES, g);
    int hi = lower_bound_i(batch, N_NODES, g + 1);
    int cnt = hi - lo;
    int f = threadIdx.x;
    float acc = 0.f;
    for (int i = lo; i < hi; i++)
        acc += __half2float(h[(size_t)i * HID + f]);
    g_pool[(size_t)g * HID + f] = acc / fmaxf((float)cnt, 1.0f);
}

// ---------------- mma.sync tf32 GEMM (MLP head, fp32 in/out) ---------------
#define SROW 136
#define GEMM_TILE_FLOATS (32 * SROW)
#define GEMM_SMEM_BYTES (4 * GEMM_TILE_FLOATS * 4)

__device__ __forceinline__ int aidx(int k, int m) {
    return k * SROW + (m ^ (((k >> 2) & 7) << 2));
}

template <bool BIAS, bool RELU>
__global__ void __launch_bounds__(256) gemm_tf32_kernel(
    const float* __restrict__ A, const float* __restrict__ B,
    const float* __restrict__ bias, float* __restrict__ C,
    int M, int N, int K)
{
    extern __shared__ float smem[];
    const int tid = threadIdx.x;
    const int lane = tid & 31;
    const int warp = tid >> 5;
    const int wm = warp >> 2, wn = warp & 3;
    const int g = lane >> 2, tig = lane & 3;
    const int brow = blockIdx.x, bcol = blockIdx.y;

    float acc[4][4][4];
#pragma unroll
    for (int im = 0; im < 4; im++)
#pragma unroll
        for (int in = 0; in < 4; in++)
#pragma unroll
            for (int c = 0; c < 4; c++) acc[im][in][c] = 0.f;

    float4 va[4], vb[4];
    auto load_tiles = [&](int k0) {
#pragma unroll
        for (int it = 0; it < 4; it++) {
            int f = tid + it * 256;
            int r = f >> 3, kc4 = (f & 7) << 2;
            int grow = brow * 128 + r;
            va[it] = f4_zero();
            if (grow < M) va[it] = *(const float4*)(A + (size_t)grow * K + k0 + kc4);
        }
#pragma unroll
        for (int it = 0; it < 4; it++) {
            int f = tid + it * 256;
            int kr = f >> 5, c4 = (f & 31) << 2;
            int gcol = bcol * 128 + c4;
            vb[it] = f4_zero();
            if (gcol + 3 < N) vb[it] = *(const float4*)(B + (size_t)(k0 + kr) * N + gcol);
            else if (gcol < N) {
                vb[it].x = B[(size_t)(k0 + kr) * N + gcol];
                if (gcol + 1 < N) vb[it].y = B[(size_t)(k0 + kr) * N + gcol + 1];
                if (gcol + 2 < N) vb[it].z = B[(size_t)(k0 + kr) * N + gcol + 2];
            }
        }
    };
    auto store_tiles = [&](int b) {
        float* Asb = smem + b * GEMM_TILE_FLOATS;
        float* Bsb = smem + (2 + b) * GEMM_TILE_FLOATS;
#pragma unroll
        for (int it = 0; it < 4; it++) {
            int f = tid + it * 256;
            int r = f >> 3, kc4 = (f & 7) << 2;
            Asb[aidx(kc4 + 0, r)] = tf32f(va[it].x);
            Asb[aidx(kc4 + 1, r)] = tf32f(va[it].y);
            Asb[aidx(kc4 + 2, r)] = tf32f(va[it].z);
            Asb[aidx(kc4 + 3, r)] = tf32f(va[it].w);
        }
#pragma unroll
        for (int it = 0; it < 4; it++) {
            int f = tid + it * 256;
            int kr = f >> 5, c4 = (f & 31) << 2;
            float4 w;
            w.x = tf32f(vb[it].x); w.y = tf32f(vb[it].y);
            w.z = tf32f(vb[it].z); w.w = tf32f(vb[it].w);
            *(float4*)&Bsb[kr * SROW + c4] = w;
        }
    };

    const int nk = K >> 5;
    load_tiles(0);
    store_tiles(0);
    __syncthreads();

    for (int tk = 0; tk < nk; tk++) {
        const int cur = tk & 1;
        if (tk + 1 < nk) load_tiles((tk + 1) << 5);
        const float* Asb = smem + cur * GEMM_TILE_FLOATS;
        const float* Bsb = smem + (2 + cur) * GEMM_TILE_FLOATS;
#pragma unroll
        for (int ks = 0; ks < 4; ks++) {
            const int kk = ks * 8;
            uint32_t af[4][4], bf[4][2];
#pragma unroll
            for (int im = 0; im < 4; im++) {
                int m0 = wm * 64 + im * 16;
                af[im][0] = __float_as_uint(Asb[aidx(kk + tig,     m0 + g    )]);
                af[im][1] = __float_as_uint(Asb[aidx(kk + tig,     m0 + g + 8)]);
                af[im][2] = __float_as_uint(Asb[aidx(kk + tig + 4, m0 + g    )]);
                af[im][3] = __float_as_uint(Asb[aidx(kk + tig + 4, m0 + g + 8)]);
            }
#pragma unroll
            for (int in = 0; in < 4; in++) {
                int n0 = wn * 32 + in * 8;
                bf[in][0] = __float_as_uint(Bsb[(kk + tig    ) * SROW + n0 + g]);
                bf[in][1] = __float_as_uint(Bsb[(kk + tig + 4) * SROW + n0 + g]);
            }
#pragma unroll
            for (int im = 0; im < 4; im++)
#pragma unroll
                for (int in = 0; in < 4; in++) {
                    asm volatile(
                        "mma.sync.aligned.m16n8k8.row.col.f32.tf32.tf32.f32 "
                        "{%0,%1,%2,%3}, {%4,%5,%6,%7}, {%8,%9}, {%0,%1,%2,%3};\n"
                        : "+f"(acc[im][in][0]), "+f"(acc[im][in][1]),
                          "+f"(acc[im][in][2]), "+f"(acc[im][in][3])
                        : "r"(af[im][0]), "r"(af[im][1]), "r"(af[im][2]), "r"(af[im][3]),
                          "r"(bf[in][0]), "r"(bf[in][1]));
                }
        }
        if (tk + 1 < nk) store_tiles(1 - cur);
        __syncthreads();
    }

#pragma unroll
    for (int im = 0; im < 4; im++) {
        int r0 = brow * 128 + wm * 64 + im * 16 + g;
#pragma unroll
        for (int in = 0; in < 4; in++) {
            int c0 = bcol * 128 + wn * 32 + in * 8 + tig * 2;
            if (c0 >= N) continue;
            float b0v = 0.f, b1v = 0.f;
            if (BIAS) { b0v = bias[c0]; if (c0 + 1 < N) b1v = bias[c0 + 1]; }
            if (r0 < M) {
                float v0 = acc[im][in][0] + b0v;
                float v1 = acc[im][in][1] + b1v;
                if (RELU) { v0 = fmaxf(v0, 0.f); v1 = fmaxf(v1, 0.f); }
                C[(size_t)r0 * N + c0] = v0;
                if (c0 + 1 < N) C[(size_t)r0 * N + c0 + 1] = v1;
            }
            if (r0 + 8 < M) {
                float v2 = acc[im][in][2] + b0v;
                float v3 = acc[im][in][3] + b1v;
                if (RELU) { v2 = fmaxf(v2, 0.f); v3 = fmaxf(v3, 0.f); }
                C[(size_t)(r0 + 8) * N + c0] = v2;
                if (c0 + 1 < N) C[(size_t)(r0 + 8) * N + c0 + 1] = v3;
            }
        }
    }
}

// ---------------- launch ----------------
extern "C" void kernel_launch(void* const* d_in, const int* in_sizes, int n_in,
                              void* d_out, int out_size)
{
    const float* x    = (const float*)d_in[0];
    const int*   ei   = (const int*)d_in[1];
    const int*   batc = (const int*)d_in[2];
    const float *W1 = (const float*)d_in[3],  *b1 = (const float*)d_in[4];
    const float *W2 = (const float*)d_in[5],  *b2 = (const float*)d_in[6];
    const float *W3 = (const float*)d_in[7],  *b3 = (const float*)d_in[8];
    const float *Wf1 = (const float*)d_in[9], *bf1 = (const float*)d_in[10];
    const float *Wf2 = (const float*)d_in[11], *bf2 = (const float*)d_in[12];
    float* out = (float*)d_out;

    const int* src = ei;
    const int* dst = ei + N_EDGES;

    float *pool_buf, *fc1_buf;
    __half *t_buf, *h_buf, *ax_buf, *w1t, *w2t, *w3t;
    cudaGetSymbolAddress((void**)&t_buf, g_t);
    cudaGetSymbolAddress((void**)&h_buf, g_h);
    cudaGetSymbolAddress((void**)&ax_buf, g_ax);
    cudaGetSymbolAddress((void**)&pool_buf, g_pool);
    cudaGetSymbolAddress((void**)&fc1_buf, g_fc1);
    cudaGetSymbolAddress((void**)&w1t, g_w1t);
    cudaGetSymbolAddress((void**)&w2t, g_w2t);
    cudaGetSymbolAddress((void**)&w3t, g_w3t);

    cudaFuncSetAttribute(gemm_h<true>,  cudaFuncAttributeMaxDynamicSharedMemorySize, HPIPE_SMEM);
    cudaFuncSetAttribute(gemm_h<false>, cudaFuncAttributeMaxDynamicSharedMemorySize, HPIPE_SMEM);
    cudaFuncSetAttribute(gemm_tf32_kernel<true, true>,  cudaFuncAttributeMaxDynamicSharedMemorySize, GEMM_SMEM_BYTES);
    cudaFuncSetAttribute(gemm_tf32_kernel<true, false>, cudaFuncAttributeMaxDynamicSharedMemorySize, GEMM_SMEM_BYTES);

    const int aggBlocks = (N_NODES * 32 + 255) / 256;
    const int tcGrid = (N_NODES + 127) / 128;   // 391

    // --- preprocessing + weight transforms ---
    k_init_deg<<<(N_NODES + 255) / 256, 256>>>();
    k_count<<<(N_EDGES + 255) / 256, 256>>>(dst);
    k_dinv_bsum<<<SCAN_NB, 256>>>();
    k_scatter<<<SCAN_NB, 256>>>();
    k_fill<<<(N_EDGES + 255) / 256, 256>>>(src, dst);
    k_transpose<<<dim3(4, 8), dim3(32, 8)>>>(W1, w1t, 128, 256);
    k_transpose<<<dim3(8, 8), dim3(32, 8)>>>(W2, w2t, 256, 256);
    k_transpose<<<dim3(8, 8), dim3(32, 8)>>>(W3, w3t, 256, 256);

    // --- layer 1: ax = fp16(A_norm @ x) ; h = fp16(relu(ax @ W1 + b1)) ---
    agg_x_kernel<<<aggBlocks, 256>>>(x, ax_buf);
    gemm_h<true><<<tcGrid, 256, HPIPE_SMEM>>>(ax_buf, w1t, b1, h_buf, N_NODES, 128);
    // --- layer 2: t = fp16(h @ W2) ; h = fp16(relu(A_norm @ t + b2)) ---
    gemm_h<false><<<tcGrid, 256, HPIPE_SMEM>>>(h_buf, w2t, nullptr, t_buf, N_NODES, 256);
    agg_h_kernel<<<aggBlocks, 256>>>(t_buf, h_buf, b2);
    // --- layer 3 ---
    gemm_h<false><<<tcGrid, 256, HPIPE_SMEM>>>(h_buf, w3t, nullptr, t_buf, N_NODES, 256);
    agg_h_kernel<<<aggBlocks, 256>>>(t_buf, h_buf, b3);

    // --- mean pool ---
    pool_kernel<<<N_GRAPHS, 256>>>(h_buf, batc);

    // --- MLP head (tf32, fp32 in/out) ---
    dim3 gridM((N_GRAPHS + 127) / 128, 1);
    gemm_tf32_kernel<true, true ><<<gridM, 256, GEMM_SMEM_BYTES>>>(pool_buf, Wf1, bf1, fc1_buf, N_GRAPHS, 128, HID);
    gemm_tf32_kernel<true, false><<<gridM, 256, GEMM_SMEM_BYTES>>>(fc1_buf, Wf2, bf2, out, N_GRAPHS, 32, 128);
}